// round 4
// baseline (speedup 1.0000x reference)
#include <cuda_runtime.h>
#include <math.h>

#define BODYD 10
#define FEATD 15
#define NOBJ  8
#define TB    8          // elements per block in k_main
#define PAIRS 64         // TB * NOBJ
#define XP    53         // x_sh pitch (pad for bank spread)
#define HP    261        // h_sh pitch (odd -> conflict-light)
#define WA1P  416        // padded N for a1 (400 -> 416, even 26-wide thread slices)
#define KC    8          // K-chunk for W_a1 streaming
#define UNION_FL 13056   // union region floats (Wa0 12800 + ba0 256)

#define EP  64           // elements per block in k_head
#define AP  404          // ip tile pitch
#define PPITCH 260       // p tile pitch

typedef unsigned long long ull;

// 104.9 MB scratch for input_pi (B x 400 fp32)
__device__ float g_ip[65536 * 400];

__device__ __forceinline__ ull packdup(float v) {
    ull r; asm("mov.b64 %0, {%1,%1};" : "=l"(r) : "f"(v)); return r;
}
__device__ __forceinline__ void unpack2(ull v, float& lo, float& hi) {
    asm("mov.b64 {%0,%1}, %2;" : "=f"(lo), "=f"(hi) : "l"(v));
}
#define FMA2(d, a, b) asm("fma.rn.f32x2 %0, %1, %2, %0;" : "+l"(d) : "l"(a), "l"(b))

// ---------------------------------------------------------------------------
// Kernel 1: attention + gather + a0 + a1 + object-sum -> g_ip (B x 400)
// Block = 8 elements = 64 (elem, obj) pairs, 256 threads.
// ---------------------------------------------------------------------------
__global__ __launch_bounds__(256, 1) void k_main(
    const float* __restrict__ o,   const float* __restrict__ g,
    const float* __restrict__ Wc,  const float* __restrict__ bc,
    const float* __restrict__ Wa0, const float* __restrict__ ba0,
    const float* __restrict__ Wa1, const float* __restrict__ ba1)
{
    extern __shared__ float sm[];
    float* x_sh = sm;                    // 64 x 53   = 3392
    float* h_sh = sm + PAIRS * XP;       // 64 x 261  = 16704
    float* u    = h_sh + PAIRS * HP;     // union     = 13056

    const int tid = threadIdx.x;
    const int e0  = blockIdx.x * TB;

    // ---------------- phase 0: attention + build scaled x ----------------
    {
        float* Wc_sh = u;            // 100 x 50 = 5000
        float* g_sh  = u + 5000;     // 8 x 100  = 800
        float* att   = u + 5800;     // 8 x 52   = 416
        for (int i = tid; i < 5000; i += 256) Wc_sh[i] = Wc[i];
        for (int i = tid; i < TB * 100; i += 256) g_sh[i] = g[(size_t)e0 * 100 + i];
        __syncthreads();

        for (int idx = tid; idx < TB * 50; idx += 256) {
            int e = idx / 50, j = idx % 50;
            float acc = bc[j];
            #pragma unroll 4
            for (int k = 0; k < 100; k++)
                acc = fmaf(g_sh[e * 100 + k], Wc_sh[k * 50 + j], acc);
            att[e * 52 + j] = 1.0f / (1.0f + expf(-acc));
        }
        __syncthreads();

        // x[e][n][d], d<20: body (o[0:10] ++ o[130:140]); d>=20: object slices
        for (int idx = tid; idx < TB * NOBJ * 50; idx += 256) {
            int e = idx / 400, r = idx % 400, n = r / 50, d = r % 50;
            int gi;
            if (d < 10)       gi = d;
            else if (d < 20)  gi = 120 + d;                 // 130 + (d-10)
            else if (d < 35)  gi = 15 * n + d - 10;         // 10 + 15n + (d-20)
            else              gi = 15 * n + d + 105;        // 140 + 15n + (d-35)
            x_sh[(e * NOBJ + n) * XP + d] =
                o[(size_t)(e0 + e) * 260 + gi] * att[e * 52 + d];
        }
        __syncthreads();
    }

    // ---------------- phase 1: h = relu(x @ Wa0 + ba0) ----------------
    {
        float* Wa0_sh = u;            // 50 x 256 = 12800
        float* ba0_sh = u + 12800;    // 256
        for (int i = tid; i < 12800; i += 256) Wa0_sh[i] = Wa0[i];
        if (tid < 256) ba0_sh[tid] = ba0[tid];
        __syncthreads();

        const int tx = tid & 15;   // pair group: pairs tx*4 .. tx*4+3
        const int ty = tid >> 4;   // j group:    j = ty*16 + 2i (+1)
        ull acc[4][8];
        #pragma unroll
        for (int p = 0; p < 4; p++)
            #pragma unroll
            for (int i = 0; i < 8; i++) acc[p][i] = 0ULL;

        for (int k = 0; k < 50; k++) {
            ull a[4];
            #pragma unroll
            for (int p = 0; p < 4; p++)
                a[p] = packdup(x_sh[(tx * 4 + p) * XP + k]);
            #pragma unroll
            for (int i = 0; i < 8; i++) {
                ull b = *(const ull*)&Wa0_sh[k * 256 + ty * 16 + 2 * i];
                FMA2(acc[0][i], a[0], b);
                FMA2(acc[1][i], a[1], b);
                FMA2(acc[2][i], a[2], b);
                FMA2(acc[3][i], a[3], b);
            }
        }
        #pragma unroll
        for (int p = 0; p < 4; p++)
            #pragma unroll
            for (int i = 0; i < 8; i++) {
                int j = ty * 16 + 2 * i;
                float lo, hi; unpack2(acc[p][i], lo, hi);
                h_sh[(tx * 4 + p) * HP + j]     = fmaxf(lo + ba0_sh[j],     0.f);
                h_sh[(tx * 4 + p) * HP + j + 1] = fmaxf(hi + ba0_sh[j + 1], 0.f);
            }
        __syncthreads();
    }

    // ------- phase 2: input_pi = sum_n relu(h @ Wa1 + ba1) -> g_ip -------
    {
        float* wbuf   = u;                    // KC x 416 = 3328
        float* ba1_sh = u + KC * WA1P;        // 416
        float* part   = ba1_sh + WA1P;        // 16 x 416 = 6656
        for (int i = tid; i < WA1P; i += 256) ba1_sh[i] = (i < 400) ? ba1[i] : 0.f;

        const int tx = tid & 15;   // j slice: j = tx*26 + 2i (+1)
        const int ty = tid >> 4;   // pair group: pairs ty*4 .. ty*4+3 (one e)
        ull acc[4][13];
        #pragma unroll
        for (int p = 0; p < 4; p++)
            #pragma unroll
            for (int i = 0; i < 13; i++) acc[p][i] = 0ULL;

        for (int k0 = 0; k0 < 256; k0 += KC) {
            for (int i = tid; i < KC * 400; i += 256)
                wbuf[(i / 400) * WA1P + (i % 400)] = Wa1[(size_t)k0 * 400 + i];
            for (int i = tid; i < KC * 16; i += 256)
                wbuf[(i / 16) * WA1P + 400 + (i % 16)] = 0.f;
            __syncthreads();
            #pragma unroll
            for (int kk = 0; kk < KC; kk++) {
                ull a[4];
                #pragma unroll
                for (int p = 0; p < 4; p++)
                    a[p] = packdup(h_sh[(ty * 4 + p) * HP + k0 + kk]);
                #pragma unroll
                for (int i = 0; i < 13; i++) {
                    ull b = *(const ull*)&wbuf[kk * WA1P + tx * 26 + 2 * i];
                    FMA2(acc[0][i], a[0], b);
                    FMA2(acc[1][i], a[1], b);
                    FMA2(acc[2][i], a[2], b);
                    FMA2(acc[3][i], a[3], b);
                }
            }
            __syncthreads();
        }

        // relu + partial sum over this thread's 4 objects (all same element)
        #pragma unroll
        for (int i = 0; i < 13; i++) {
            int j = tx * 26 + 2 * i;
            if (j < 400) {
                float s0 = 0.f, s1 = 0.f;
                #pragma unroll
                for (int p = 0; p < 4; p++) {
                    float lo, hi; unpack2(acc[p][i], lo, hi);
                    s0 += fmaxf(lo + ba1_sh[j],     0.f);
                    s1 += fmaxf(hi + ba1_sh[j + 1], 0.f);
                }
                part[ty * WA1P + j]     = s0;
                part[ty * WA1P + j + 1] = s1;
            }
        }
        __syncthreads();
        for (int idx = tid; idx < TB * 400; idx += 256) {
            int e = idx / 400, j = idx % 400;
            g_ip[(size_t)(e0 + e) * 400 + j] =
                part[(2 * e) * WA1P + j] + part[(2 * e + 1) * WA1P + j];
        }
    }
}

// ---------------------------------------------------------------------------
// Kernel 2: policy head  p0(relu) -> p1(relu) -> p2(tanh) -> out (B x 8)
// Block = 64 elements, 256 threads.
// ---------------------------------------------------------------------------
__global__ __launch_bounds__(256, 1) void k_head(
    const float* __restrict__ Wp0, const float* __restrict__ bp0,
    const float* __restrict__ Wp1, const float* __restrict__ bp1,
    const float* __restrict__ Wp2, const float* __restrict__ bp2,
    float* __restrict__ out)
{
    extern __shared__ float sm[];
    float* a_sh = sm;                      // 64 x 404 = 25856 (ip tile, later q)
    float* p_sh = a_sh + EP * AP;          // 64 x 260 = 16640
    float* wbuf = p_sh + EP * PPITCH;      // 16 x 256 = 4096
    float* w2   = wbuf + 16 * 256;         // 256 x 8  = 2048

    const int tid = threadIdx.x;
    const int e0  = blockIdx.x * EP;
    for (int i = tid; i < EP * 400; i += 256)
        a_sh[(i / 400) * AP + (i % 400)] = g_ip[(size_t)e0 * 400 + i];
    for (int i = tid; i < 2048; i += 256) w2[i] = Wp2[i];
    __syncthreads();

    const int tx = tid & 15;   // j pairs at tx*2 + 32i
    const int ty = tid >> 4;   // elements ty*4 .. ty*4+3

    // GEMM1: p = relu(ip @ Wp0 + bp0), K=400, N=256
    {
        ull acc[4][8];
        #pragma unroll
        for (int p = 0; p < 4; p++)
            #pragma unroll
            for (int i = 0; i < 8; i++) acc[p][i] = 0ULL;
        for (int k0 = 0; k0 < 400; k0 += 16) {
            for (int i = tid; i < 16 * 256; i += 256)
                wbuf[i] = Wp0[(size_t)k0 * 256 + i];
            __syncthreads();
            #pragma unroll
            for (int kk = 0; kk < 16; kk++) {
                ull a[4];
                #pragma unroll
                for (int p = 0; p < 4; p++)
                    a[p] = packdup(a_sh[(ty * 4 + p) * AP + k0 + kk]);
                #pragma unroll
                for (int i = 0; i < 8; i++) {
                    ull b = *(const ull*)&wbuf[kk * 256 + tx * 2 + 32 * i];
                    FMA2(acc[0][i], a[0], b);
                    FMA2(acc[1][i], a[1], b);
                    FMA2(acc[2][i], a[2], b);
                    FMA2(acc[3][i], a[3], b);
                }
            }
            __syncthreads();
        }
        #pragma unroll
        for (int p = 0; p < 4; p++)
            #pragma unroll
            for (int i = 0; i < 8; i++) {
                int j = tx * 2 + 32 * i;
                float lo, hi; unpack2(acc[p][i], lo, hi);
                p_sh[(ty * 4 + p) * PPITCH + j]     = fmaxf(lo + __ldg(bp0 + j),     0.f);
                p_sh[(ty * 4 + p) * PPITCH + j + 1] = fmaxf(hi + __ldg(bp0 + j + 1), 0.f);
            }
        __syncthreads();
    }

    // GEMM2: q = relu(p @ Wp1 + bp1), K=256, N=256 (q overwrites a_sh)
    {
        ull acc[4][8];
        #pragma unroll
        for (int p = 0; p < 4; p++)
            #pragma unroll
            for (int i = 0; i < 8; i++) acc[p][i] = 0ULL;
        for (int k0 = 0; k0 < 256; k0 += 16) {
            for (int i = tid; i < 16 * 256; i += 256)
                wbuf[i] = Wp1[(size_t)k0 * 256 + i];
            __syncthreads();
            #pragma unroll
            for (int kk = 0; kk < 16; kk++) {
                ull a[4];
                #pragma unroll
                for (int p = 0; p < 4; p++)
                    a[p] = packdup(p_sh[(ty * 4 + p) * PPITCH + k0 + kk]);
                #pragma unroll
                for (int i = 0; i < 8; i++) {
                    ull b = *(const ull*)&wbuf[kk * 256 + tx * 2 + 32 * i];
                    FMA2(acc[0][i], a[0], b);
                    FMA2(acc[1][i], a[1], b);
                    FMA2(acc[2][i], a[2], b);
                    FMA2(acc[3][i], a[3], b);
                }
            }
            __syncthreads();
        }
        #pragma unroll
        for (int p = 0; p < 4; p++)
            #pragma unroll
            for (int i = 0; i < 8; i++) {
                int j = tx * 2 + 32 * i;
                float lo, hi; unpack2(acc[p][i], lo, hi);
                a_sh[(ty * 4 + p) * PPITCH + j]     = fmaxf(lo + __ldg(bp1 + j),     0.f);
                a_sh[(ty * 4 + p) * PPITCH + j + 1] = fmaxf(hi + __ldg(bp1 + j + 1), 0.f);
            }
        __syncthreads();
    }

    // GEMM3: out = tanh(q @ Wp2 + bp2), N=8
    for (int idx = tid; idx < EP * 8; idx += 256) {
        int e = idx >> 3, jo = idx & 7;
        float acc = __ldg(bp2 + jo);
        #pragma unroll 8
        for (int k = 0; k < 256; k++)
            acc = fmaf(a_sh[e * PPITCH + k], w2[k * 8 + jo], acc);
        out[(size_t)(e0 + e) * 8 + jo] = tanhf(acc);
    }
}

// ---------------------------------------------------------------------------
extern "C" void kernel_launch(void* const* d_in, const int* in_sizes, int n_in,
                              void* d_out, int out_size)
{
    const float* o   = (const float*)d_in[0];
    const float* g   = (const float*)d_in[1];
    const float* Wc  = (const float*)d_in[2];
    const float* bc  = (const float*)d_in[3];
    const float* Wa0 = (const float*)d_in[4];
    const float* ba0 = (const float*)d_in[5];
    const float* Wa1 = (const float*)d_in[6];
    const float* ba1 = (const float*)d_in[7];
    const float* Wp0 = (const float*)d_in[8];
    const float* bp0 = (const float*)d_in[9];
    const float* Wp1 = (const float*)d_in[10];
    const float* bp1 = (const float*)d_in[11];
    const float* Wp2 = (const float*)d_in[12];
    const float* bp2 = (const float*)d_in[13];
    float* out = (float*)d_out;

    int B = in_sizes[0] / 260;

    size_t sm1 = (size_t)(PAIRS * XP + PAIRS * HP + UNION_FL) * sizeof(float);
    size_t sm3 = (size_t)(EP * AP + EP * PPITCH + 16 * 256 + 2048) * sizeof(float);
    cudaFuncSetAttribute(k_main, cudaFuncAttributeMaxDynamicSharedMemorySize, (int)sm1);
    cudaFuncSetAttribute(k_head, cudaFuncAttributeMaxDynamicSharedMemorySize, (int)sm3);

    k_main<<<B / TB, 256, sm1>>>(o, g, Wc, bc, Wa0, ba0, Wa1, ba1);
    k_head<<<B / EP, 256, sm3>>>(Wp0, bp0, Wp1, bp1, Wp2, bp2, out);
}

// round 5
// speedup vs baseline: 1.0002x; 1.0002x over previous
#include <cuda_runtime.h>
#include <math.h>

#define BODYD 10
#define FEATD 15
#define NOBJ  8
#define TB    8          // elements per block in k_main
#define PAIRS 64         // TB * NOBJ
#define XP    53         // x_sh pitch (pad for bank spread)
#define HP    261        // h_sh pitch (odd -> conflict-light)
#define WA1P  416        // padded N for a1 (400 -> 416, even 26-wide thread slices)
#define KC    8          // K-chunk for W_a1 streaming
#define UNION_FL 13056   // union region floats (Wa0 12800 + ba0 256)

#define EP  64           // elements per block in k_head
#define AP  404          // ip tile pitch
#define PPITCH 260       // p tile pitch

typedef unsigned long long ull;

// 104.9 MB scratch for input_pi (B x 400 fp32)
__device__ float g_ip[65536 * 400];

__device__ __forceinline__ ull packdup(float v) {
    ull r; asm("mov.b64 %0, {%1,%1};" : "=l"(r) : "f"(v)); return r;
}
__device__ __forceinline__ void unpack2(ull v, float& lo, float& hi) {
    asm("mov.b64 {%0,%1}, %2;" : "=f"(lo), "=f"(hi) : "l"(v));
}
#define FMA2(d, a, b) asm("fma.rn.f32x2 %0, %1, %2, %0;" : "+l"(d) : "l"(a), "l"(b))

// ---------------------------------------------------------------------------
// Kernel 1: attention + gather + a0 + a1 + object-sum -> g_ip (B x 400)
// Block = 8 elements = 64 (elem, obj) pairs, 256 threads.
// ---------------------------------------------------------------------------
__global__ __launch_bounds__(256, 1) void k_main(
    const float* __restrict__ o,   const float* __restrict__ g,
    const float* __restrict__ Wc,  const float* __restrict__ bc,
    const float* __restrict__ Wa0, const float* __restrict__ ba0,
    const float* __restrict__ Wa1, const float* __restrict__ ba1)
{
    extern __shared__ float sm[];
    float* x_sh = sm;                    // 64 x 53   = 3392
    float* h_sh = sm + PAIRS * XP;       // 64 x 261  = 16704
    float* u    = h_sh + PAIRS * HP;     // union     = 13056

    const int tid = threadIdx.x;
    const int e0  = blockIdx.x * TB;

    // ---------------- phase 0: attention + build scaled x ----------------
    {
        float* Wc_sh = u;            // 100 x 50 = 5000
        float* g_sh  = u + 5000;     // 8 x 100  = 800
        float* att   = u + 5800;     // 8 x 52   = 416
        for (int i = tid; i < 5000; i += 256) Wc_sh[i] = Wc[i];
        for (int i = tid; i < TB * 100; i += 256) g_sh[i] = g[(size_t)e0 * 100 + i];
        __syncthreads();

        for (int idx = tid; idx < TB * 50; idx += 256) {
            int e = idx / 50, j = idx % 50;
            float acc = bc[j];
            #pragma unroll 4
            for (int k = 0; k < 100; k++)
                acc = fmaf(g_sh[e * 100 + k], Wc_sh[k * 50 + j], acc);
            att[e * 52 + j] = 1.0f / (1.0f + expf(-acc));
        }
        __syncthreads();

        // x[e][n][d], d<20: body (o[0:10] ++ o[130:140]); d>=20: object slices
        for (int idx = tid; idx < TB * NOBJ * 50; idx += 256) {
            int e = idx / 400, r = idx % 400, n = r / 50, d = r % 50;
            int gi;
            if (d < 10)       gi = d;
            else if (d < 20)  gi = 120 + d;                 // 130 + (d-10)
            else if (d < 35)  gi = 15 * n + d - 10;         // 10 + 15n + (d-20)
            else              gi = 15 * n + d + 105;        // 140 + 15n + (d-35)
            x_sh[(e * NOBJ + n) * XP + d] =
                o[(size_t)(e0 + e) * 260 + gi] * att[e * 52 + d];
        }
        __syncthreads();
    }

    // ---------------- phase 1: h = relu(x @ Wa0 + ba0) ----------------
    {
        float* Wa0_sh = u;            // 50 x 256 = 12800
        float* ba0_sh = u + 12800;    // 256
        for (int i = tid; i < 12800; i += 256) Wa0_sh[i] = Wa0[i];
        if (tid < 256) ba0_sh[tid] = ba0[tid];
        __syncthreads();

        const int tx = tid & 15;   // pair group: pairs tx*4 .. tx*4+3
        const int ty = tid >> 4;   // j group:    j = ty*16 + 2i (+1)
        ull acc[4][8];
        #pragma unroll
        for (int p = 0; p < 4; p++)
            #pragma unroll
            for (int i = 0; i < 8; i++) acc[p][i] = 0ULL;

        for (int k = 0; k < 50; k++) {
            ull a[4];
            #pragma unroll
            for (int p = 0; p < 4; p++)
                a[p] = packdup(x_sh[(tx * 4 + p) * XP + k]);
            #pragma unroll
            for (int i = 0; i < 8; i++) {
                ull b = *(const ull*)&Wa0_sh[k * 256 + ty * 16 + 2 * i];
                FMA2(acc[0][i], a[0], b);
                FMA2(acc[1][i], a[1], b);
                FMA2(acc[2][i], a[2], b);
                FMA2(acc[3][i], a[3], b);
            }
        }
        #pragma unroll
        for (int p = 0; p < 4; p++)
            #pragma unroll
            for (int i = 0; i < 8; i++) {
                int j = ty * 16 + 2 * i;
                float lo, hi; unpack2(acc[p][i], lo, hi);
                h_sh[(tx * 4 + p) * HP + j]     = fmaxf(lo + ba0_sh[j],     0.f);
                h_sh[(tx * 4 + p) * HP + j + 1] = fmaxf(hi + ba0_sh[j + 1], 0.f);
            }
        __syncthreads();
    }

    // ------- phase 2: input_pi = sum_n relu(h @ Wa1 + ba1) -> g_ip -------
    {
        float* wbuf   = u;                    // KC x 416 = 3328
        float* ba1_sh = u + KC * WA1P;        // 416
        float* part   = ba1_sh + WA1P;        // 16 x 416 = 6656
        for (int i = tid; i < WA1P; i += 256) ba1_sh[i] = (i < 400) ? ba1[i] : 0.f;

        const int tx = tid & 15;   // j slice: j = tx*26 + 2i (+1)
        const int ty = tid >> 4;   // pair group: pairs ty*4 .. ty*4+3 (one e)
        ull acc[4][13];
        #pragma unroll
        for (int p = 0; p < 4; p++)
            #pragma unroll
            for (int i = 0; i < 13; i++) acc[p][i] = 0ULL;

        for (int k0 = 0; k0 < 256; k0 += KC) {
            for (int i = tid; i < KC * 400; i += 256)
                wbuf[(i / 400) * WA1P + (i % 400)] = Wa1[(size_t)k0 * 400 + i];
            for (int i = tid; i < KC * 16; i += 256)
                wbuf[(i / 16) * WA1P + 400 + (i % 16)] = 0.f;
            __syncthreads();
            #pragma unroll
            for (int kk = 0; kk < KC; kk++) {
                ull a[4];
                #pragma unroll
                for (int p = 0; p < 4; p++)
                    a[p] = packdup(h_sh[(ty * 4 + p) * HP + k0 + kk]);
                #pragma unroll
                for (int i = 0; i < 13; i++) {
                    ull b = *(const ull*)&wbuf[kk * WA1P + tx * 26 + 2 * i];
                    FMA2(acc[0][i], a[0], b);
                    FMA2(acc[1][i], a[1], b);
                    FMA2(acc[2][i], a[2], b);
                    FMA2(acc[3][i], a[3], b);
                }
            }
            __syncthreads();
        }

        // relu + partial sum over this thread's 4 objects (all same element)
        #pragma unroll
        for (int i = 0; i < 13; i++) {
            int j = tx * 26 + 2 * i;
            if (j < 400) {
                float s0 = 0.f, s1 = 0.f;
                #pragma unroll
                for (int p = 0; p < 4; p++) {
                    float lo, hi; unpack2(acc[p][i], lo, hi);
                    s0 += fmaxf(lo + ba1_sh[j],     0.f);
                    s1 += fmaxf(hi + ba1_sh[j + 1], 0.f);
                }
                part[ty * WA1P + j]     = s0;
                part[ty * WA1P + j + 1] = s1;
            }
        }
        __syncthreads();
        for (int idx = tid; idx < TB * 400; idx += 256) {
            int e = idx / 400, j = idx % 400;
            g_ip[(size_t)(e0 + e) * 400 + j] =
                part[(2 * e) * WA1P + j] + part[(2 * e + 1) * WA1P + j];
        }
    }
}

// ---------------------------------------------------------------------------
// Kernel 2: policy head  p0(relu) -> p1(relu) -> p2(tanh) -> out (B x 8)
// Block = 64 elements, 256 threads.
// ---------------------------------------------------------------------------
__global__ __launch_bounds__(256, 1) void k_head(
    const float* __restrict__ Wp0, const float* __restrict__ bp0,
    const float* __restrict__ Wp1, const float* __restrict__ bp1,
    const float* __restrict__ Wp2, const float* __restrict__ bp2,
    float* __restrict__ out)
{
    extern __shared__ float sm[];
    float* a_sh = sm;                      // 64 x 404 = 25856 (ip tile, later q)
    float* p_sh = a_sh + EP * AP;          // 64 x 260 = 16640
    float* wbuf = p_sh + EP * PPITCH;      // 16 x 256 = 4096
    float* w2   = wbuf + 16 * 256;         // 256 x 8  = 2048

    const int tid = threadIdx.x;
    const int e0  = blockIdx.x * EP;
    for (int i = tid; i < EP * 400; i += 256)
        a_sh[(i / 400) * AP + (i % 400)] = g_ip[(size_t)e0 * 400 + i];
    for (int i = tid; i < 2048; i += 256) w2[i] = Wp2[i];
    __syncthreads();

    const int tx = tid & 15;   // j pairs at tx*2 + 32i
    const int ty = tid >> 4;   // elements ty*4 .. ty*4+3

    // GEMM1: p = relu(ip @ Wp0 + bp0), K=400, N=256
    {
        ull acc[4][8];
        #pragma unroll
        for (int p = 0; p < 4; p++)
            #pragma unroll
            for (int i = 0; i < 8; i++) acc[p][i] = 0ULL;
        for (int k0 = 0; k0 < 400; k0 += 16) {
            for (int i = tid; i < 16 * 256; i += 256)
                wbuf[i] = Wp0[(size_t)k0 * 256 + i];
            __syncthreads();
            #pragma unroll
            for (int kk = 0; kk < 16; kk++) {
                ull a[4];
                #pragma unroll
                for (int p = 0; p < 4; p++)
                    a[p] = packdup(a_sh[(ty * 4 + p) * AP + k0 + kk]);
                #pragma unroll
                for (int i = 0; i < 8; i++) {
                    ull b = *(const ull*)&wbuf[kk * 256 + tx * 2 + 32 * i];
                    FMA2(acc[0][i], a[0], b);
                    FMA2(acc[1][i], a[1], b);
                    FMA2(acc[2][i], a[2], b);
                    FMA2(acc[3][i], a[3], b);
                }
            }
            __syncthreads();
        }
        #pragma unroll
        for (int p = 0; p < 4; p++)
            #pragma unroll
            for (int i = 0; i < 8; i++) {
                int j = tx * 2 + 32 * i;
                float lo, hi; unpack2(acc[p][i], lo, hi);
                p_sh[(ty * 4 + p) * PPITCH + j]     = fmaxf(lo + __ldg(bp0 + j),     0.f);
                p_sh[(ty * 4 + p) * PPITCH + j + 1] = fmaxf(hi + __ldg(bp0 + j + 1), 0.f);
            }
        __syncthreads();
    }

    // GEMM2: q = relu(p @ Wp1 + bp1), K=256, N=256 (q overwrites a_sh)
    {
        ull acc[4][8];
        #pragma unroll
        for (int p = 0; p < 4; p++)
            #pragma unroll
            for (int i = 0; i < 8; i++) acc[p][i] = 0ULL;
        for (int k0 = 0; k0 < 256; k0 += 16) {
            for (int i = tid; i < 16 * 256; i += 256)
                wbuf[i] = Wp1[(size_t)k0 * 256 + i];
            __syncthreads();
            #pragma unroll
            for (int kk = 0; kk < 16; kk++) {
                ull a[4];
                #pragma unroll
                for (int p = 0; p < 4; p++)
                    a[p] = packdup(p_sh[(ty * 4 + p) * PPITCH + k0 + kk]);
                #pragma unroll
                for (int i = 0; i < 8; i++) {
                    ull b = *(const ull*)&wbuf[kk * 256 + tx * 2 + 32 * i];
                    FMA2(acc[0][i], a[0], b);
                    FMA2(acc[1][i], a[1], b);
                    FMA2(acc[2][i], a[2], b);
                    FMA2(acc[3][i], a[3], b);
                }
            }
            __syncthreads();
        }
        #pragma unroll
        for (int p = 0; p < 4; p++)
            #pragma unroll
            for (int i = 0; i < 8; i++) {
                int j = tx * 2 + 32 * i;
                float lo, hi; unpack2(acc[p][i], lo, hi);
                a_sh[(ty * 4 + p) * PPITCH + j]     = fmaxf(lo + __ldg(bp1 + j),     0.f);
                a_sh[(ty * 4 + p) * PPITCH + j + 1] = fmaxf(hi + __ldg(bp1 + j + 1), 0.f);
            }
        __syncthreads();
    }

    // GEMM3: out = tanh(q @ Wp2 + bp2), N=8
    for (int idx = tid; idx < EP * 8; idx += 256) {
        int e = idx >> 3, jo = idx & 7;
        float acc = __ldg(bp2 + jo);
        #pragma unroll 8
        for (int k = 0; k < 256; k++)
            acc = fmaf(a_sh[e * PPITCH + k], w2[k * 8 + jo], acc);
        out[(size_t)(e0 + e) * 8 + jo] = tanhf(acc);
    }
}

// ---------------------------------------------------------------------------
extern "C" void kernel_launch(void* const* d_in, const int* in_sizes, int n_in,
                              void* d_out, int out_size)
{
    const float* o   = (const float*)d_in[0];
    const float* g   = (const float*)d_in[1];
    const float* Wc  = (const float*)d_in[2];
    const float* bc  = (const float*)d_in[3];
    const float* Wa0 = (const float*)d_in[4];
    const float* ba0 = (const float*)d_in[5];
    const float* Wa1 = (const float*)d_in[6];
    const float* ba1 = (const float*)d_in[7];
    const float* Wp0 = (const float*)d_in[8];
    const float* bp0 = (const float*)d_in[9];
    const float* Wp1 = (const float*)d_in[10];
    const float* bp1 = (const float*)d_in[11];
    const float* Wp2 = (const float*)d_in[12];
    const float* bp2 = (const float*)d_in[13];
    float* out = (float*)d_out;

    int B = in_sizes[0] / 260;

    size_t sm1 = (size_t)(PAIRS * XP + PAIRS * HP + UNION_FL) * sizeof(float);
    size_t sm3 = (size_t)(EP * AP + EP * PPITCH + 16 * 256 + 2048) * sizeof(float);
    cudaFuncSetAttribute(k_main, cudaFuncAttributeMaxDynamicSharedMemorySize, (int)sm1);
    cudaFuncSetAttribute(k_head, cudaFuncAttributeMaxDynamicSharedMemorySize, (int)sm3);

    k_main<<<B / TB, 256, sm1>>>(o, g, Wc, bc, Wa0, ba0, Wa1, ba1);
    k_head<<<B / EP, 256, sm3>>>(Wp0, bp0, Wp1, bp1, Wp2, bp2, out);
}

// round 6
// speedup vs baseline: 1.3384x; 1.3381x over previous
#include <cuda_runtime.h>
#include <math.h>

#define NOBJ  8
#define TB    8            // elements per block in k_main
#define PAIRS 64           // TB * NOBJ
#define XP    53           // x_sh pitch
#define HP    258          // h_sh pitch (even for 8B-aligned stores)
#define WAP   448          // padded a1 N (400 -> 448 = 32 lanes * 14)
#define KC    16           // K-chunk for W_a1 streaming
#define NCH   16           // 256 / KC
#define WBUF_FL (2*KC*WAP) // 14336 double-buffered weight chunks
#define U_FL  (WBUF_FL + WAP) // + padded ba1

#define EP  64             // elements per block in k_head
#define AP  400            // ip tile pitch
#define PP  256            // p/q tile pitch

typedef unsigned long long ull;

// 104.9 MB scratch for input_pi (B x 400 fp32)
__device__ float g_ip[65536 * 400];

__device__ __forceinline__ ull packdup(float v) {
    ull r; asm("mov.b64 %0, {%1,%1};" : "=l"(r) : "f"(v)); return r;
}
__device__ __forceinline__ void unpack2(ull v, float& lo, float& hi) {
    asm("mov.b64 {%0,%1}, %2;" : "=f"(lo), "=f"(hi) : "l"(v));
}
#define FMA2(d, a, b) asm("fma.rn.f32x2 %0, %1, %2, %0;" : "+l"(d) : "l"(a), "l"(b))

__device__ __forceinline__ unsigned smem_u32(const void* p) {
    unsigned a;
    asm("{ .reg .u64 t; cvta.to.shared.u64 t, %1; cvt.u32.u64 %0, t; }"
        : "=r"(a) : "l"(p));
    return a;
}
#define CP16(dst_u32, src_ptr) \
    asm volatile("cp.async.cg.shared.global [%0], [%1], 16;" \
                 :: "r"(dst_u32), "l"(src_ptr))
#define CP_COMMIT() asm volatile("cp.async.commit_group;")
#define CP_WAIT1()  asm volatile("cp.async.wait_group 1;")
#define CP_WAIT0()  asm volatile("cp.async.wait_group 0;")

// ---------------------------------------------------------------------------
// Kernel 1: attention + gather + a0 + a1 + object-sum -> g_ip (B x 400)
// Block = 8 elements = 64 (elem, obj) pairs, 256 threads.
// Thread tile: ty (0..7) = element (owns all 8 object rows), tx (0..31) =
// column slice j = tx*2 + 64*i. 8 FMA2 per weight load; weights via cp.async.
// ---------------------------------------------------------------------------
__global__ __launch_bounds__(256, 1) void k_main(
    const float* __restrict__ o,   const float* __restrict__ g,
    const float* __restrict__ Wc,  const float* __restrict__ bc,
    const float* __restrict__ Wa0, const float* __restrict__ ba0,
    const float* __restrict__ Wa1, const float* __restrict__ ba1)
{
    extern __shared__ float sm[];
    float* x_sh = sm;                    // 64 x 53  = 3392
    float* h_sh = sm + PAIRS * XP;       // 64 x 258 = 16512
    float* u    = h_sh + PAIRS * HP;     // union    = 14784

    const int tid = threadIdx.x;
    const int e0  = blockIdx.x * TB;

    // ---------------- phase 0: attention + build scaled x ----------------
    {
        float* Wc_sh = u;            // 100 x 50 = 5000
        float* g_sh  = u + 5000;     // 8 x 100  = 800
        float* att   = u + 5800;     // 8 x 52   = 416
        for (int i = tid; i < 5000; i += 256) Wc_sh[i] = Wc[i];
        for (int i = tid; i < TB * 100; i += 256) g_sh[i] = g[(size_t)e0 * 100 + i];
        __syncthreads();

        for (int idx = tid; idx < TB * 50; idx += 256) {
            int e = idx / 50, j = idx % 50;
            float acc = bc[j];
            #pragma unroll 4
            for (int k = 0; k < 100; k++)
                acc = fmaf(g_sh[e * 100 + k], Wc_sh[k * 50 + j], acc);
            att[e * 52 + j] = 1.0f / (1.0f + expf(-acc));
        }
        __syncthreads();

        // x[e][n][d], d<20: body (o[0:10] ++ o[130:140]); d>=20: object slices
        for (int idx = tid; idx < TB * NOBJ * 50; idx += 256) {
            int e = idx / 400, r = idx % 400, n = r / 50, d = r % 50;
            int gi;
            if (d < 10)       gi = d;
            else if (d < 20)  gi = 120 + d;                 // 130 + (d-10)
            else if (d < 35)  gi = 15 * n + d - 10;         // 10 + 15n + (d-20)
            else              gi = 15 * n + d + 105;        // 140 + 15n + (d-35)
            x_sh[(e * NOBJ + n) * XP + d] =
                o[(size_t)(e0 + e) * 260 + gi] * att[e * 52 + d];
        }
        __syncthreads();
    }

    const int tx = tid & 31;
    const int ty = tid >> 5;

    // ---------------- phase 1: h = relu(x @ Wa0 + ba0) ----------------
    {
        float* Wa0_sh = u;            // 50 x 256 = 12800
        float* ba0_sh = u + 12800;    // 256
        for (int i = tid; i < 12800; i += 256) Wa0_sh[i] = Wa0[i];
        if (tid < 256) ba0_sh[tid] = ba0[tid];
        __syncthreads();

        ull acc[8][4];
        #pragma unroll
        for (int p = 0; p < 8; p++)
            #pragma unroll
            for (int i = 0; i < 4; i++) acc[p][i] = 0ULL;

        for (int k = 0; k < 50; k++) {
            ull a[8];
            #pragma unroll
            for (int p = 0; p < 8; p++)
                a[p] = packdup(x_sh[(ty * 8 + p) * XP + k]);   // warp-broadcast
            #pragma unroll
            for (int i = 0; i < 4; i++) {
                ull b = *(const ull*)&Wa0_sh[k * 256 + tx * 2 + 64 * i]; // lane-consecutive
                #pragma unroll
                for (int p = 0; p < 8; p++) FMA2(acc[p][i], a[p], b);
            }
        }
        #pragma unroll
        for (int p = 0; p < 8; p++)
            #pragma unroll
            for (int i = 0; i < 4; i++) {
                int j = tx * 2 + 64 * i;
                float lo, hi; unpack2(acc[p][i], lo, hi);
                float2 v = make_float2(fmaxf(lo + ba0_sh[j],     0.f),
                                       fmaxf(hi + ba0_sh[j + 1], 0.f));
                *(float2*)&h_sh[(ty * 8 + p) * HP + j] = v;
            }
        __syncthreads();
    }

    // ------- phase 2: input_pi = sum_n relu(h @ Wa1 + ba1) -> g_ip -------
    {
        float* wbuf   = u;                 // 2 x 16 x 448
        float* ba1_sh = u + WBUF_FL;       // 448
        const unsigned wbuf_a = smem_u32(wbuf);
        for (int i = tid; i < WAP; i += 256) ba1_sh[i] = (i < 400) ? ba1[i] : 0.f;

        ull acc[8][7];
        #pragma unroll
        for (int p = 0; p < 8; p++)
            #pragma unroll
            for (int i = 0; i < 7; i++) acc[p][i] = 0ULL;

        // preload chunk 0
        {
            const float* src0 = Wa1;
            for (int q = tid; q < KC * 100; q += 256) {
                int row = q / 100, col = q % 100;
                CP16(wbuf_a + (unsigned)(row * WAP + col * 4) * 4,
                     src0 + row * 400 + col * 4);
            }
            CP_COMMIT();
        }

        for (int c = 0; c < NCH; c++) {
            if (c + 1 < NCH) {
                const float* src = Wa1 + (size_t)(c + 1) * KC * 400;
                unsigned dst0 = wbuf_a + (unsigned)(((c + 1) & 1) * KC * WAP) * 4;
                for (int q = tid; q < KC * 100; q += 256) {
                    int row = q / 100, col = q % 100;
                    CP16(dst0 + (unsigned)(row * WAP + col * 4) * 4,
                         src + row * 400 + col * 4);
                }
                CP_COMMIT();
                CP_WAIT1();
            } else {
                CP_WAIT0();
            }
            __syncthreads();

            const float* wb = wbuf + (c & 1) * KC * WAP;
            const int k0 = c * KC;
            #pragma unroll
            for (int kk = 0; kk < KC; kk++) {
                ull a[8];
                #pragma unroll
                for (int p = 0; p < 8; p++)
                    a[p] = packdup(h_sh[(ty * 8 + p) * HP + k0 + kk]);  // broadcast
                #pragma unroll
                for (int i = 0; i < 7; i++) {
                    ull b = *(const ull*)&wb[kk * WAP + tx * 2 + 64 * i];
                    #pragma unroll
                    for (int p = 0; p < 8; p++) FMA2(acc[p][i], a[p], b);
                }
            }
            __syncthreads();   // protect buf (c&1) before it is refilled
        }

        // relu + object-sum in registers, write straight to g_ip
        #pragma unroll
        for (int i = 0; i < 7; i++) {
            int j = tx * 2 + 64 * i;
            if (j < 400) {
                float b0 = ba1_sh[j], b1 = ba1_sh[j + 1];
                float s0 = 0.f, s1 = 0.f;
                #pragma unroll
                for (int p = 0; p < 8; p++) {
                    float lo, hi; unpack2(acc[p][i], lo, hi);
                    s0 += fmaxf(lo + b0, 0.f);
                    s1 += fmaxf(hi + b1, 0.f);
                }
                *(float2*)&g_ip[(size_t)(e0 + ty) * 400 + j] = make_float2(s0, s1);
            }
        }
    }
}

// ---------------------------------------------------------------------------
// Kernel 2: policy head  p0(relu) -> p1(relu) -> p2(tanh) -> out (B x 8)
// Block = 64 elements, 256 threads. ty (0..7) owns 8 element rows; tx (0..31)
// owns j = tx*2 + 64*i. cp.async double-buffered weight streaming.
// ---------------------------------------------------------------------------
__global__ __launch_bounds__(256, 1) void k_head(
    const float* __restrict__ Wp0, const float* __restrict__ bp0,
    const float* __restrict__ Wp1, const float* __restrict__ bp1,
    const float* __restrict__ Wp2, const float* __restrict__ bp2,
    float* __restrict__ out)
{
    extern __shared__ float sm[];
    float* a_sh = sm;                      // 64 x 400 = 25600 (ip tile, later q)
    float* p_sh = a_sh + EP * AP;          // 64 x 256 = 16384
    float* wbuf = p_sh + EP * PP;          // 2 x 16 x 256 = 8192
    float* w2   = wbuf + 2 * 16 * 256;     // 256 x 8  = 2048
    const unsigned wbuf_a = smem_u32(wbuf);

    const int tid = threadIdx.x;
    const int e0  = blockIdx.x * EP;
    for (int i = tid; i < EP * 400; i += 256) a_sh[i] = g_ip[(size_t)e0 * 400 + i];
    for (int i = tid; i < 2048; i += 256) w2[i] = Wp2[i];
    __syncthreads();

    const int tx = tid & 31;
    const int ty = tid >> 5;

    // GEMM1: p = relu(ip @ Wp0 + bp0), K=400, N=256, 25 chunks of 16
    {
        ull acc[8][4];
        #pragma unroll
        for (int p = 0; p < 8; p++)
            #pragma unroll
            for (int i = 0; i < 4; i++) acc[p][i] = 0ULL;

        for (int q = tid; q < 1024; q += 256) {   // preload chunk 0
            int row = q >> 6, col = q & 63;
            CP16(wbuf_a + (unsigned)(row * 256 + col * 4) * 4,
                 Wp0 + row * 256 + col * 4);
        }
        CP_COMMIT();

        for (int c = 0; c < 25; c++) {
            if (c + 1 < 25) {
                const float* src = Wp0 + (size_t)(c + 1) * 16 * 256;
                unsigned dst0 = wbuf_a + (unsigned)(((c + 1) & 1) * 4096) * 4;
                for (int q = tid; q < 1024; q += 256) {
                    int row = q >> 6, col = q & 63;
                    CP16(dst0 + (unsigned)(row * 256 + col * 4) * 4,
                         src + row * 256 + col * 4);
                }
                CP_COMMIT();
                CP_WAIT1();
            } else {
                CP_WAIT0();
            }
            __syncthreads();

            const float* wb = wbuf + (c & 1) * 4096;
            const int k0 = c * 16;
            #pragma unroll
            for (int kk = 0; kk < 16; kk++) {
                ull a[8];
                #pragma unroll
                for (int p = 0; p < 8; p++)
                    a[p] = packdup(a_sh[(ty * 8 + p) * AP + k0 + kk]);
                #pragma unroll
                for (int i = 0; i < 4; i++) {
                    ull b = *(const ull*)&wb[kk * 256 + tx * 2 + 64 * i];
                    #pragma unroll
                    for (int p = 0; p < 8; p++) FMA2(acc[p][i], a[p], b);
                }
            }
            __syncthreads();
        }
        #pragma unroll
        for (int i = 0; i < 4; i++) {
            int j = tx * 2 + 64 * i;
            float b0 = __ldg(bp0 + j), b1 = __ldg(bp0 + j + 1);
            #pragma unroll
            for (int p = 0; p < 8; p++) {
                float lo, hi; unpack2(acc[p][i], lo, hi);
                *(float2*)&p_sh[(ty * 8 + p) * PP + j] =
                    make_float2(fmaxf(lo + b0, 0.f), fmaxf(hi + b1, 0.f));
            }
        }
        // per-chunk sync at loop end already ordered wbuf; p_sh ordered by
        // the first sync inside GEMM2's pipeline below.
    }

    // GEMM2: q = relu(p @ Wp1 + bp1), K=256, N=256 (q overwrites a_sh, pitch PP)
    {
        ull acc[8][4];
        #pragma unroll
        for (int p = 0; p < 8; p++)
            #pragma unroll
            for (int i = 0; i < 4; i++) acc[p][i] = 0ULL;

        for (int q = tid; q < 1024; q += 256) {   // preload chunk 0
            int row = q >> 6, col = q & 63;
            CP16(wbuf_a + (unsigned)(row * 256 + col * 4) * 4,
                 Wp1 + row * 256 + col * 4);
        }
        CP_COMMIT();

        for (int c = 0; c < 16; c++) {
            if (c + 1 < 16) {
                const float* src = Wp1 + (size_t)(c + 1) * 16 * 256;
                unsigned dst0 = wbuf_a + (unsigned)(((c + 1) & 1) * 4096) * 4;
                for (int q = tid; q < 1024; q += 256) {
                    int row = q >> 6, col = q & 63;
                    CP16(dst0 + (unsigned)(row * 256 + col * 4) * 4,
                         src + row * 256 + col * 4);
                }
                CP_COMMIT();
                CP_WAIT1();
            } else {
                CP_WAIT0();
            }
            __syncthreads();

            const float* wb = wbuf + (c & 1) * 4096;
            const int k0 = c * 16;
            #pragma unroll
            for (int kk = 0; kk < 16; kk++) {
                ull a[8];
                #pragma unroll
                for (int p = 0; p < 8; p++)
                    a[p] = packdup(p_sh[(ty * 8 + p) * PP + k0 + kk]);
                #pragma unroll
                for (int i = 0; i < 4; i++) {
                    ull b = *(const ull*)&wb[kk * 256 + tx * 2 + 64 * i];
                    #pragma unroll
                    for (int p = 0; p < 8; p++) FMA2(acc[p][i], a[p], b);
                }
            }
            __syncthreads();
        }
        #pragma unroll
        for (int i = 0; i < 4; i++) {
            int j = tx * 2 + 64 * i;
            float b0 = __ldg(bp1 + j), b1 = __ldg(bp1 + j + 1);
            #pragma unroll
            for (int p = 0; p < 8; p++) {
                float lo, hi; unpack2(acc[p][i], lo, hi);
                *(float2*)&a_sh[(ty * 8 + p) * PP + j] =
                    make_float2(fmaxf(lo + b0, 0.f), fmaxf(hi + b1, 0.f));
            }
        }
        __syncthreads();
    }

    // GEMM3: out = tanh(q @ Wp2 + bp2), N=8
    for (int idx = tid; idx < EP * 8; idx += 256) {
        int e = idx >> 3, jo = idx & 7;
        float acc = __ldg(bp2 + jo);
        #pragma unroll 8
        for (int k = 0; k < 256; k++)
            acc = fmaf(a_sh[e * PP + k], w2[k * 8 + jo], acc);
        out[(size_t)(e0 + e) * 8 + jo] = tanhf(acc);
    }
}

// ---------------------------------------------------------------------------
extern "C" void kernel_launch(void* const* d_in, const int* in_sizes, int n_in,
                              void* d_out, int out_size)
{
    const float* o   = (const float*)d_in[0];
    const float* g   = (const float*)d_in[1];
    const float* Wc  = (const float*)d_in[2];
    const float* bc  = (const float*)d_in[3];
    const float* Wa0 = (const float*)d_in[4];
    const float* ba0 = (const float*)d_in[5];
    const float* Wa1 = (const float*)d_in[6];
    const float* ba1 = (const float*)d_in[7];
    const float* Wp0 = (const float*)d_in[8];
    const float* bp0 = (const float*)d_in[9];
    const float* Wp1 = (const float*)d_in[10];
    const float* bp1 = (const float*)d_in[11];
    const float* Wp2 = (const float*)d_in[12];
    const float* bp2 = (const float*)d_in[13];
    float* out = (float*)d_out;

    int B = in_sizes[0] / 260;

    size_t sm1 = (size_t)(PAIRS * XP + PAIRS * HP + U_FL) * sizeof(float);
    size_t sm3 = (size_t)(EP * AP + EP * PP + 2 * 16 * 256 + 2048) * sizeof(float);
    cudaFuncSetAttribute(k_main, cudaFuncAttributeMaxDynamicSharedMemorySize, (int)sm1);
    cudaFuncSetAttribute(k_head, cudaFuncAttributeMaxDynamicSharedMemorySize, (int)sm3);

    k_main<<<B / TB, 256, sm1>>>(o, g, Wc, bc, Wa0, ba0, Wa1, ba1);
    k_head<<<B / EP, 256, sm3>>>(Wp0, bp0, Wp1, bp1, Wp2, bp2, out);
}

// round 7
// speedup vs baseline: 1.3445x; 1.0046x over previous
#include <cuda_runtime.h>
#include <math.h>

#define NOBJ  8
#define TB    8            // elements per block in k_main
#define PAIRS 64           // TB * NOBJ
#define XP    53           // x_sh pitch
#define HP    258          // h_sh pitch (even for 8B-aligned stores)
#define WAP   448          // padded a1 N (400 -> 448)
#define KC    16           // K-chunk rows
#define NCH   16           // 256 / KC
#define NT    512          // threads per block

#define EP  64             // elements per block in k_head
#define AP  400            // ip tile pitch
#define PP  256            // p/q tile pitch

typedef unsigned long long ull;

// 104.9 MB scratch for input_pi (B x 400 fp32)
__device__ float g_ip[65536 * 400];

__device__ __forceinline__ ull packdup(float v) {
    ull r; asm("mov.b64 %0, {%1,%1};" : "=l"(r) : "f"(v)); return r;
}
__device__ __forceinline__ void unpack2(ull v, float& lo, float& hi) {
    asm("mov.b64 {%0,%1}, %2;" : "=f"(lo), "=f"(hi) : "l"(v));
}
#define FMA2(d, a, b) asm("fma.rn.f32x2 %0, %1, %2, %0;" : "+l"(d) : "l"(a), "l"(b))

__device__ __forceinline__ unsigned smem_u32(const void* p) {
    unsigned a;
    asm("{ .reg .u64 t; cvta.to.shared.u64 t, %1; cvt.u32.u64 %0, t; }"
        : "=r"(a) : "l"(p));
    return a;
}
#define CP16(dst_u32, src_ptr) \
    asm volatile("cp.async.cg.shared.global [%0], [%1], 16;" \
                 :: "r"(dst_u32), "l"(src_ptr))
#define CP_COMMIT() asm volatile("cp.async.commit_group;")
#define CP_WAIT1()  asm volatile("cp.async.wait_group 1;")
#define CP_WAIT0()  asm volatile("cp.async.wait_group 0;")

// ---------------------------------------------------------------------------
// Kernel 1: attention + gather + a0 + a1 + object-sum -> g_ip (B x 400)
// Block = 8 elements = 64 (elem,obj) pairs, 512 threads (16 warps).
// ty (0..15) owns 4 rows; tx (0..31) owns j = tx*2 + 64*i.
// Weights streamed via cp.async, 3 buffers, 1 barrier per chunk.
// ---------------------------------------------------------------------------
__global__ __launch_bounds__(NT, 1) void k_main(
    const float* __restrict__ o,   const float* __restrict__ g,
    const float* __restrict__ Wc,  const float* __restrict__ bc,
    const float* __restrict__ Wa0, const float* __restrict__ ba0,
    const float* __restrict__ Wa1, const float* __restrict__ ba1)
{
    extern __shared__ float sm[];
    float* x_sh = sm;                    // 64 x 53  = 3392
    float* h_sh = sm + PAIRS * XP;       // 64 x 258 = 16512
    float* u    = h_sh + PAIRS * HP;     // union: wbuf 3*16*448 + ba1 448 + part 8*448

    const int tid = threadIdx.x;
    const int e0  = blockIdx.x * TB;

    // ---------------- phase 0: attention + build scaled x ----------------
    {
        float* Wc_sh = u;            // 100 x 50 = 5000
        float* g_sh  = u + 5000;     // 8 x 100  = 800
        float* att   = u + 5800;     // 8 x 52   = 416
        for (int i = tid; i < 5000; i += NT) Wc_sh[i] = Wc[i];
        for (int i = tid; i < TB * 100; i += NT) g_sh[i] = g[(size_t)e0 * 100 + i];
        __syncthreads();

        for (int idx = tid; idx < TB * 50; idx += NT) {
            int e = idx / 50, j = idx % 50;
            float acc = bc[j];
            #pragma unroll 4
            for (int k = 0; k < 100; k++)
                acc = fmaf(g_sh[e * 100 + k], Wc_sh[k * 50 + j], acc);
            att[e * 52 + j] = 1.0f / (1.0f + expf(-acc));
        }
        __syncthreads();

        for (int idx = tid; idx < TB * NOBJ * 50; idx += NT) {
            int e = idx / 400, r = idx % 400, n = r / 50, d = r % 50;
            int gi;
            if (d < 10)       gi = d;
            else if (d < 20)  gi = 120 + d;                 // 130 + (d-10)
            else if (d < 35)  gi = 15 * n + d - 10;         // 10 + 15n + (d-20)
            else              gi = 15 * n + d + 105;        // 140 + 15n + (d-35)
            x_sh[(e * NOBJ + n) * XP + d] =
                o[(size_t)(e0 + e) * 260 + gi] * att[e * 52 + d];
        }
        __syncthreads();
    }

    const int tx = tid & 31;
    const int ty = tid >> 5;          // 0..15, rows ty*4 .. ty*4+3

    // ---------------- phase 1: h = relu(x @ Wa0 + ba0) ----------------
    {
        float* Wa0_sh = u;            // 50 x 256 = 12800
        float* ba0_sh = u + 12800;    // 256
        for (int i = tid; i < 12800; i += NT) Wa0_sh[i] = Wa0[i];
        for (int i = tid; i < 256; i += NT) ba0_sh[i] = ba0[i];
        __syncthreads();

        ull acc[4][4];
        #pragma unroll
        for (int p = 0; p < 4; p++)
            #pragma unroll
            for (int i = 0; i < 4; i++) acc[p][i] = 0ULL;

        for (int k = 0; k < 50; k++) {
            ull a[4];
            #pragma unroll
            for (int p = 0; p < 4; p++)
                a[p] = packdup(x_sh[(ty * 4 + p) * XP + k]);   // broadcast
            #pragma unroll
            for (int i = 0; i < 4; i++) {
                ull b = *(const ull*)&Wa0_sh[k * 256 + tx * 2 + 64 * i];
                #pragma unroll
                for (int p = 0; p < 4; p++) FMA2(acc[p][i], a[p], b);
            }
        }
        #pragma unroll
        for (int p = 0; p < 4; p++)
            #pragma unroll
            for (int i = 0; i < 4; i++) {
                int j = tx * 2 + 64 * i;
                float lo, hi; unpack2(acc[p][i], lo, hi);
                *(float2*)&h_sh[(ty * 4 + p) * HP + j] =
                    make_float2(fmaxf(lo + ba0_sh[j],     0.f),
                                fmaxf(hi + ba0_sh[j + 1], 0.f));
            }
        __syncthreads();
    }

    // ------- phase 2: input_pi = sum_n relu(h @ Wa1 + ba1) -> g_ip -------
    {
        float* wbuf   = u;                         // 3 x 16 x 448 = 21504
        float* ba1_sh = u + 3 * KC * WAP;          // 448
        float* part   = ba1_sh + WAP;              // 8 x 448 = 3584
        const unsigned wbuf_a = smem_u32(wbuf);
        for (int i = tid; i < WAP; i += NT) ba1_sh[i] = (i < 400) ? ba1[i] : 0.f;

        ull acc[4][7];
        #pragma unroll
        for (int p = 0; p < 4; p++)
            #pragma unroll
            for (int i = 0; i < 7; i++) acc[p][i] = 0ULL;

        // preload chunks 0 and 1
        #pragma unroll
        for (int pc = 0; pc < 2; pc++) {
            const float* src = Wa1 + (size_t)pc * KC * 400;
            unsigned dst0 = wbuf_a + (unsigned)(pc * KC * WAP) * 4;
            for (int q = tid; q < KC * 100; q += NT) {
                int row = q / 100, col = q % 100;
                CP16(dst0 + (unsigned)(row * WAP + col * 4) * 4,
                     src + row * 400 + col * 4);
            }
            CP_COMMIT();
        }

        for (int c = 0; c < NCH; c++) {
            if (c + 1 < NCH) CP_WAIT1(); else CP_WAIT0();
            __syncthreads();   // chunk c visible; compute(c-1) done everywhere
            if (c + 2 < NCH) { // refill buffer (c+2)%3 (last read at iter c-1)
                const float* src = Wa1 + (size_t)(c + 2) * KC * 400;
                unsigned dst0 = wbuf_a + (unsigned)(((c + 2) % 3) * KC * WAP) * 4;
                for (int q = tid; q < KC * 100; q += NT) {
                    int row = q / 100, col = q % 100;
                    CP16(dst0 + (unsigned)(row * WAP + col * 4) * 4,
                         src + row * 400 + col * 4);
                }
                CP_COMMIT();
            }
            const float* wb = wbuf + (c % 3) * KC * WAP;
            const int k0 = c * KC;
            #pragma unroll
            for (int kk = 0; kk < KC; kk++) {
                ull a[4];
                #pragma unroll
                for (int p = 0; p < 4; p++)
                    a[p] = packdup(h_sh[(ty * 4 + p) * HP + k0 + kk]);
                #pragma unroll
                for (int i = 0; i < 7; i++) {
                    ull b = *(const ull*)&wb[kk * WAP + tx * 2 + 64 * i];
                    #pragma unroll
                    for (int p = 0; p < 4; p++) FMA2(acc[p][i], a[p], b);
                }
            }
        }

        // relu + partial sum over this thread's 4 rows; 2 threads per element
        const int e = ty >> 1;
        if (ty & 1) {
            #pragma unroll
            for (int i = 0; i < 7; i++) {
                int j = tx * 2 + 64 * i;
                if (j < 400) {
                    float b0 = ba1_sh[j], b1 = ba1_sh[j + 1];
                    float s0 = 0.f, s1 = 0.f;
                    #pragma unroll
                    for (int p = 0; p < 4; p++) {
                        float lo, hi; unpack2(acc[p][i], lo, hi);
                        s0 += fmaxf(lo + b0, 0.f);
                        s1 += fmaxf(hi + b1, 0.f);
                    }
                    *(float2*)&part[e * WAP + j] = make_float2(s0, s1);
                }
            }
        }
        __syncthreads();
        if (!(ty & 1)) {
            #pragma unroll
            for (int i = 0; i < 7; i++) {
                int j = tx * 2 + 64 * i;
                if (j < 400) {
                    float b0 = ba1_sh[j], b1 = ba1_sh[j + 1];
                    float2 pr = *(const float2*)&part[e * WAP + j];
                    float s0 = pr.x, s1 = pr.y;
                    #pragma unroll
                    for (int p = 0; p < 4; p++) {
                        float lo, hi; unpack2(acc[p][i], lo, hi);
                        s0 += fmaxf(lo + b0, 0.f);
                        s1 += fmaxf(hi + b1, 0.f);
                    }
                    *(float2*)&g_ip[(size_t)(e0 + e) * 400 + j] = make_float2(s0, s1);
                }
            }
        }
    }
}

// ---------------------------------------------------------------------------
// Kernel 2: policy head. Block = 64 elements, 512 threads (16 warps).
// ty (0..15) owns rows ty*4..+3; tx owns j = tx*2 + 64*i, i<4.
// ---------------------------------------------------------------------------
__global__ __launch_bounds__(NT, 1) void k_head(
    const float* __restrict__ Wp0, const float* __restrict__ bp0,
    const float* __restrict__ Wp1, const float* __restrict__ bp1,
    const float* __restrict__ Wp2, const float* __restrict__ bp2,
    float* __restrict__ out)
{
    extern __shared__ float sm[];
    float* a_sh = sm;                      // 64 x 400 = 25600 (ip tile, later q)
    float* p_sh = a_sh + EP * AP;          // 64 x 256 = 16384
    float* wbuf = p_sh + EP * PP;          // 3 x 16 x 256 = 12288
    float* w2   = wbuf + 3 * 16 * 256;     // 256 x 8  = 2048
    const unsigned wbuf_a = smem_u32(wbuf);

    const int tid = threadIdx.x;
    const int e0  = blockIdx.x * EP;
    for (int i = tid; i < EP * 400; i += NT) a_sh[i] = g_ip[(size_t)e0 * 400 + i];
    for (int i = tid; i < 2048; i += NT) w2[i] = Wp2[i];

    const int tx = tid & 31;
    const int ty = tid >> 5;

    // GEMM1: p = relu(ip @ Wp0 + bp0), K=400, 25 chunks of 16
    {
        ull acc[4][4];
        #pragma unroll
        for (int p = 0; p < 4; p++)
            #pragma unroll
            for (int i = 0; i < 4; i++) acc[p][i] = 0ULL;

        __syncthreads();   // a_sh ready (also fences initial smem state)
        #pragma unroll
        for (int pc = 0; pc < 2; pc++) {
            const float* src = Wp0 + (size_t)pc * 16 * 256;
            unsigned dst0 = wbuf_a + (unsigned)(pc * 4096) * 4;
            for (int q = tid; q < 1024; q += NT) {
                int row = q >> 6, col = q & 63;
                CP16(dst0 + (unsigned)(row * 256 + col * 4) * 4,
                     src + row * 256 + col * 4);
            }
            CP_COMMIT();
        }

        for (int c = 0; c < 25; c++) {
            if (c + 1 < 25) CP_WAIT1(); else CP_WAIT0();
            __syncthreads();
            if (c + 2 < 25) {
                const float* src = Wp0 + (size_t)(c + 2) * 16 * 256;
                unsigned dst0 = wbuf_a + (unsigned)(((c + 2) % 3) * 4096) * 4;
                for (int q = tid; q < 1024; q += NT) {
                    int row = q >> 6, col = q & 63;
                    CP16(dst0 + (unsigned)(row * 256 + col * 4) * 4,
                         src + row * 256 + col * 4);
                }
                CP_COMMIT();
            }
            const float* wb = wbuf + (c % 3) * 4096;
            const int k0 = c * 16;
            #pragma unroll
            for (int kk = 0; kk < 16; kk++) {
                ull a[4];
                #pragma unroll
                for (int p = 0; p < 4; p++)
                    a[p] = packdup(a_sh[(ty * 4 + p) * AP + k0 + kk]);
                #pragma unroll
                for (int i = 0; i < 4; i++) {
                    ull b = *(const ull*)&wb[kk * 256 + tx * 2 + 64 * i];
                    #pragma unroll
                    for (int p = 0; p < 4; p++) FMA2(acc[p][i], a[p], b);
                }
            }
        }
        #pragma unroll
        for (int i = 0; i < 4; i++) {
            int j = tx * 2 + 64 * i;
            float b0 = __ldg(bp0 + j), b1 = __ldg(bp0 + j + 1);
            #pragma unroll
            for (int p = 0; p < 4; p++) {
                float lo, hi; unpack2(acc[p][i], lo, hi);
                *(float2*)&p_sh[(ty * 4 + p) * PP + j] =
                    make_float2(fmaxf(lo + b0, 0.f), fmaxf(hi + b1, 0.f));
            }
        }
        __syncthreads();   // p_sh ready; GEMM1's last wbuf reads done
    }

    // GEMM2: q = relu(p @ Wp1 + bp1), K=256 (q overwrites a_sh, pitch PP)
    {
        ull acc[4][4];
        #pragma unroll
        for (int p = 0; p < 4; p++)
            #pragma unroll
            for (int i = 0; i < 4; i++) acc[p][i] = 0ULL;

        #pragma unroll
        for (int pc = 0; pc < 2; pc++) {
            const float* src = Wp1 + (size_t)pc * 16 * 256;
            unsigned dst0 = wbuf_a + (unsigned)(pc * 4096) * 4;
            for (int q = tid; q < 1024; q += NT) {
                int row = q >> 6, col = q & 63;
                CP16(dst0 + (unsigned)(row * 256 + col * 4) * 4,
                     src + row * 256 + col * 4);
            }
            CP_COMMIT();
        }

        for (int c = 0; c < 16; c++) {
            if (c + 1 < 16) CP_WAIT1(); else CP_WAIT0();
            __syncthreads();
            if (c + 2 < 16) {
                const float* src = Wp1 + (size_t)(c + 2) * 16 * 256;
                unsigned dst0 = wbuf_a + (unsigned)(((c + 2) % 3) * 4096) * 4;
                for (int q = tid; q < 1024; q += NT) {
                    int row = q >> 6, col = q & 63;
                    CP16(dst0 + (unsigned)(row * 256 + col * 4) * 4,
                         src + row * 256 + col * 4);
                }
                CP_COMMIT();
            }
            const float* wb = wbuf + (c % 3) * 4096;
            const int k0 = c * 16;
            #pragma unroll
            for (int kk = 0; kk < 16; kk++) {
                ull a[4];
                #pragma unroll
                for (int p = 0; p < 4; p++)
                    a[p] = packdup(p_sh[(ty * 4 + p) * PP + k0 + kk]);
                #pragma unroll
                for (int i = 0; i < 4; i++) {
                    ull b = *(const ull*)&wb[kk * 256 + tx * 2 + 64 * i];
                    #pragma unroll
                    for (int p = 0; p < 4; p++) FMA2(acc[p][i], a[p], b);
                }
            }
        }
        #pragma unroll
        for (int i = 0; i < 4; i++) {
            int j = tx * 2 + 64 * i;
            float b0 = __ldg(bp1 + j), b1 = __ldg(bp1 + j + 1);
            #pragma unroll
            for (int p = 0; p < 4; p++) {
                float lo, hi; unpack2(acc[p][i], lo, hi);
                *(float2*)&a_sh[(ty * 4 + p) * PP + j] =
                    make_float2(fmaxf(lo + b0, 0.f), fmaxf(hi + b1, 0.f));
            }
        }
        __syncthreads();
    }

    // GEMM3: out = tanh(q @ Wp2 + bp2), N=8; one output per thread
    {
        int e = tid >> 3, jo = tid & 7;
        float acc = __ldg(bp2 + jo);
        #pragma unroll 8
        for (int k = 0; k < 256; k++)
            acc = fmaf(a_sh[e * PP + k], w2[k * 8 + jo], acc);
        out[(size_t)(e0 + e) * 8 + jo] = tanhf(acc);
    }
}

// ---------------------------------------------------------------------------
extern "C" void kernel_launch(void* const* d_in, const int* in_sizes, int n_in,
                              void* d_out, int out_size)
{
    const float* o   = (const float*)d_in[0];
    const float* g   = (const float*)d_in[1];
    const float* Wc  = (const float*)d_in[2];
    const float* bc  = (const float*)d_in[3];
    const float* Wa0 = (const float*)d_in[4];
    const float* ba0 = (const float*)d_in[5];
    const float* Wa1 = (const float*)d_in[6];
    const float* ba1 = (const float*)d_in[7];
    const float* Wp0 = (const float*)d_in[8];
    const float* bp0 = (const float*)d_in[9];
    const float* Wp1 = (const float*)d_in[10];
    const float* bp1 = (const float*)d_in[11];
    const float* Wp2 = (const float*)d_in[12];
    const float* bp2 = (const float*)d_in[13];
    float* out = (float*)d_out;

    int B = in_sizes[0] / 260;

    // k_main union: wbuf 3*KC*WAP + ba1 WAP + part 8*WAP = 21504+448+3584
    size_t u_fl = 3 * KC * WAP + WAP + 8 * WAP;
    size_t sm1 = (size_t)(PAIRS * XP + PAIRS * HP + u_fl) * sizeof(float);
    size_t sm3 = (size_t)(EP * AP + EP * PP + 3 * 16 * 256 + 2048) * sizeof(float);
    cudaFuncSetAttribute(k_main, cudaFuncAttributeMaxDynamicSharedMemorySize, (int)sm1);
    cudaFuncSetAttribute(k_head, cudaFuncAttributeMaxDynamicSharedMemorySize, (int)sm3);

    k_main<<<B / TB, NT, sm1>>>(o, g, Wc, bc, Wa0, ba0, Wa1, ba1);
    k_head<<<B / EP, NT, sm3>>>(Wp0, bp0, Wp1, bp1, Wp2, bp2, out);
}

// round 8
// speedup vs baseline: 1.4485x; 1.0774x over previous
#include <cuda_runtime.h>
#include <math.h>

#define NOBJ  8
#define TB    8            // elements per block in k_main
#define PAIRS 64           // TB * NOBJ
#define XP    54           // x_sh pitch (even: 8B-aligned vec2 loads)
#define HP    260          // h_sh pitch (mult of 4: 16B-aligned stores)
#define WAP   448          // padded a1 N (400 -> 448)
#define KC    16           // K-chunk rows
#define NCH   16           // 256 / KC
#define NT    512          // threads per block

#define EP  64             // elements per block in k_head
#define AP  400            // ip tile pitch
#define PP  256            // p/q tile pitch

typedef unsigned long long ull;

// 104.9 MB scratch for input_pi (B x 400 fp32)
__device__ float g_ip[65536 * 400];

__device__ __forceinline__ ull packdup(float v) {
    ull r; asm("mov.b64 %0, {%1,%1};" : "=l"(r) : "f"(v)); return r;
}
__device__ __forceinline__ void unpack2(ull v, float& lo, float& hi) {
    asm("mov.b64 {%0,%1}, %2;" : "=f"(lo), "=f"(hi) : "l"(v));
}
#define FMA2(d, a, b) asm("fma.rn.f32x2 %0, %1, %2, %0;" : "+l"(d) : "l"(a), "l"(b))

__device__ __forceinline__ unsigned smem_u32(const void* p) {
    unsigned a;
    asm("{ .reg .u64 t; cvta.to.shared.u64 t, %1; cvt.u32.u64 %0, t; }"
        : "=r"(a) : "l"(p));
    return a;
}
#define CP16(dst_u32, src_ptr) \
    asm volatile("cp.async.cg.shared.global [%0], [%1], 16;" \
                 :: "r"(dst_u32), "l"(src_ptr))
#define CP_COMMIT() asm volatile("cp.async.commit_group;")
#define CP_WAIT1()  asm volatile("cp.async.wait_group 1;")
#define CP_WAIT0()  asm volatile("cp.async.wait_group 0;")

// ---------------------------------------------------------------------------
// Core register-tiled MMA chunk: 16 k-steps, thread tile 8 rows x NC ull-cols.
// a: broadcast vec2 loads (8B, 2 k-steps); b: lane-consecutive LDS.64.
// wf/FMA2 = (8 + 2*2*NC) / (2*8*NC) = 1/(2NC) + 1/4  -> 0.375 @ NC=2..4.
// ---------------------------------------------------------------------------
template<int NC, int APITCH, int WPITCH>
__device__ __forceinline__ void mma_chunk(
    const float* __restrict__ wb,      // weight chunk base (16 x WPITCH)
    const float* __restrict__ abase,   // activation base: row0 of 8, at k0
    int jb, ull (&acc)[8][4])
{
    #pragma unroll
    for (int kk2 = 0; kk2 < 8; kk2++) {
        ull a2[8];
        #pragma unroll
        for (int p = 0; p < 8; p++)
            a2[p] = *(const ull*)(abase + p * APITCH + 2 * kk2);
        #pragma unroll
        for (int dk = 0; dk < 2; dk++) {
            ull ap[8];
            #pragma unroll
            for (int p = 0; p < 8; p++) {
                float lo, hi; unpack2(a2[p], lo, hi);
                ap[p] = packdup(dk ? hi : lo);
            }
            #pragma unroll
            for (int i = 0; i < NC; i++) {
                ull b = *(const ull*)(wb + (2 * kk2 + dk) * WPITCH + jb + 64 * i);
                #pragma unroll
                for (int p = 0; p < 8; p++) FMA2(acc[p][i], ap[p], b);
            }
        }
    }
}

// ---------------------------------------------------------------------------
// Kernel 1: attention + gather + a0 + a1 + object-sum -> g_ip (B x 400)
// Block = 8 elements = 64 (elem,obj) pairs, 512 threads (16 warps).
// Warp layout: r = (wid&7) -> rows r*8..r*8+7 (= all 8 objects of element r);
// cz = wid>>3 -> column half. Thread tile 8 rows x (4 or 3) ull cols.
// ---------------------------------------------------------------------------
__global__ __launch_bounds__(NT, 1) void k_main(
    const float* __restrict__ o,   const float* __restrict__ g,
    const float* __restrict__ Wc,  const float* __restrict__ bc,
    const float* __restrict__ Wa0, const float* __restrict__ ba0,
    const float* __restrict__ Wa1, const float* __restrict__ ba1)
{
    extern __shared__ float sm[];
    float* x_sh = sm;                    // 64 x 54  = 3456
    float* h_sh = sm + PAIRS * XP;       // 64 x 260 = 16640
    float* u    = h_sh + PAIRS * HP;     // union: wbuf 3*16*448 + ba1 448

    const int tid = threadIdx.x;
    const int e0  = blockIdx.x * TB;

    // ---------------- phase 0: attention + build scaled x ----------------
    {
        float* Wc_sh = u;            // 100 x 50 = 5000
        float* g_sh  = u + 5000;     // 8 x 100  = 800
        float* att   = u + 5800;     // 8 x 52   = 416
        for (int i = tid; i < 5000; i += NT) Wc_sh[i] = Wc[i];
        for (int i = tid; i < TB * 100; i += NT) g_sh[i] = g[(size_t)e0 * 100 + i];
        __syncthreads();

        for (int idx = tid; idx < TB * 50; idx += NT) {
            int e = idx / 50, j = idx % 50;
            float acc = bc[j];
            #pragma unroll 4
            for (int k = 0; k < 100; k++)
                acc = fmaf(g_sh[e * 100 + k], Wc_sh[k * 50 + j], acc);
            att[e * 52 + j] = 1.0f / (1.0f + expf(-acc));
        }
        __syncthreads();

        for (int idx = tid; idx < TB * NOBJ * 50; idx += NT) {
            int e = idx / 400, r = idx % 400, n = r / 50, d = r % 50;
            int gi;
            if (d < 10)       gi = d;
            else if (d < 20)  gi = 120 + d;                 // 130 + (d-10)
            else if (d < 35)  gi = 15 * n + d - 10;         // 10 + 15n + (d-20)
            else              gi = 15 * n + d + 105;        // 140 + 15n + (d-35)
            x_sh[(e * NOBJ + n) * XP + d] =
                o[(size_t)(e0 + e) * 260 + gi] * att[e * 52 + d];
        }
        __syncthreads();
    }

    const int tx = tid & 31;
    const int r  = (tid >> 5) & 7;     // row group / element
    const int cz = tid >> 8;           // column half

    // ---------------- phase 1: h = relu(x @ Wa0 + ba0) ----------------
    // Thread tile: 8 rows x 4 cols (float4 b) at j = cz*128 + tx*4.
    {
        float* Wa0_sh = u;            // 50 x 256 = 12800
        float* ba0_sh = u + 12800;    // 256
        for (int i = tid; i < 12800; i += NT) Wa0_sh[i] = Wa0[i];
        for (int i = tid; i < 256; i += NT) ba0_sh[i] = ba0[i];
        __syncthreads();

        const int jb1 = cz * 128 + tx * 4;
        const float* xb = x_sh + r * 8 * XP;
        ull acc1[8][2];
        #pragma unroll
        for (int p = 0; p < 8; p++) { acc1[p][0] = 0ULL; acc1[p][1] = 0ULL; }

        #pragma unroll 5
        for (int k = 0; k < 50; k += 2) {
            ull a2[8];
            #pragma unroll
            for (int p = 0; p < 8; p++)
                a2[p] = *(const ull*)(xb + p * XP + k);
            #pragma unroll
            for (int dk = 0; dk < 2; dk++) {
                float4 bv = *(const float4*)&Wa0_sh[(k + dk) * 256 + jb1];
                ull b0 = ((const ull*)&bv)[0], b1 = ((const ull*)&bv)[1];
                #pragma unroll
                for (int p = 0; p < 8; p++) {
                    float lo, hi; unpack2(a2[p], lo, hi);
                    ull ap = packdup(dk ? hi : lo);
                    FMA2(acc1[p][0], ap, b0);
                    FMA2(acc1[p][1], ap, b1);
                }
            }
        }
        float4 bb = *(const float4*)&ba0_sh[jb1];
        #pragma unroll
        for (int p = 0; p < 8; p++) {
            float l0, h0, l1, h1;
            unpack2(acc1[p][0], l0, h0);
            unpack2(acc1[p][1], l1, h1);
            float4 v = make_float4(fmaxf(l0 + bb.x, 0.f), fmaxf(h0 + bb.y, 0.f),
                                   fmaxf(l1 + bb.z, 0.f), fmaxf(h1 + bb.w, 0.f));
            *(float4*)&h_sh[(r * 8 + p) * HP + jb1] = v;
        }
        __syncthreads();
    }

    // ------- phase 2: input_pi = sum_n relu(h @ Wa1 + ba1) -> g_ip -------
    // cz=0: cols j = tx*2 + 64i, i<4 (0..255); cz=1: j = 256 + tx*2 + 64i, i<3.
    {
        float* wbuf   = u;                         // 3 x 16 x 448 = 21504
        float* ba1_sh = u + 3 * KC * WAP;          // 448
        const unsigned wbuf_a = smem_u32(wbuf);
        for (int i = tid; i < WAP; i += NT) ba1_sh[i] = (i < 400) ? ba1[i] : 0.f;

        const int jb2 = tx * 2 + 256 * cz;
        ull acc[8][4];
        #pragma unroll
        for (int p = 0; p < 8; p++)
            #pragma unroll
            for (int i = 0; i < 4; i++) acc[p][i] = 0ULL;

        #pragma unroll
        for (int pc = 0; pc < 2; pc++) {           // preload chunks 0,1
            const float* src = Wa1 + (size_t)pc * KC * 400;
            unsigned dst0 = wbuf_a + (unsigned)(pc * KC * WAP) * 4;
            for (int q = tid; q < KC * 100; q += NT) {
                int row = q / 100, col = q % 100;
                CP16(dst0 + (unsigned)(row * WAP + col * 4) * 4,
                     src + row * 400 + col * 4);
            }
            CP_COMMIT();
        }

        for (int c = 0; c < NCH; c++) {
            if (c + 1 < NCH) CP_WAIT1(); else CP_WAIT0();
            __syncthreads();
            if (c + 2 < NCH) {
                const float* src = Wa1 + (size_t)(c + 2) * KC * 400;
                unsigned dst0 = wbuf_a + (unsigned)(((c + 2) % 3) * KC * WAP) * 4;
                for (int q = tid; q < KC * 100; q += NT) {
                    int row = q / 100, col = q % 100;
                    CP16(dst0 + (unsigned)(row * WAP + col * 4) * 4,
                         src + row * 400 + col * 4);
                }
                CP_COMMIT();
            }
            const float* wb = wbuf + (c % 3) * KC * WAP;
            const float* ab = h_sh + r * 8 * HP + c * KC;
            if (cz == 0) mma_chunk<4, HP, WAP>(wb, ab, jb2, acc);
            else         mma_chunk<3, HP, WAP>(wb, ab, jb2, acc);
        }

        // relu + full object-sum in registers -> g_ip (rows r*8..r*8+7 are
        // exactly the 8 objects of element r)
        const int nc = 4 - cz;
        #pragma unroll
        for (int i = 0; i < 4; i++) {
            int j = jb2 + 64 * i;
            if (i < nc && j < 400) {
                float b0 = ba1_sh[j], b1 = ba1_sh[j + 1];
                float s0 = 0.f, s1 = 0.f;
                #pragma unroll
                for (int p = 0; p < 8; p++) {
                    float lo, hi; unpack2(acc[p][i], lo, hi);
                    s0 += fmaxf(lo + b0, 0.f);
                    s1 += fmaxf(hi + b1, 0.f);
                }
                *(float2*)&g_ip[(size_t)(e0 + r) * 400 + j] = make_float2(s0, s1);
            }
        }
    }
}

// ---------------------------------------------------------------------------
// Kernel 2: policy head. Block = 64 elements, 512 threads (16 warps).
// r = wid&7 -> rows r*8..+7; cz = wid>>3 -> cols j = tx*2 + 128*cz + 64*i, i<2.
// ---------------------------------------------------------------------------
__global__ __launch_bounds__(NT, 1) void k_head(
    const float* __restrict__ Wp0, const float* __restrict__ bp0,
    const float* __restrict__ Wp1, const float* __restrict__ bp1,
    const float* __restrict__ Wp2, const float* __restrict__ bp2,
    float* __restrict__ out)
{
    extern __shared__ float sm[];
    float* a_sh = sm;                      // 64 x 400 = 25600 (ip tile, later q)
    float* p_sh = a_sh + EP * AP;          // 64 x 256 = 16384
    float* wbuf = p_sh + EP * PP;          // 3 x 16 x 256 = 12288
    float* w2   = wbuf + 3 * 16 * 256;     // 256 x 8  = 2048
    const unsigned wbuf_a = smem_u32(wbuf);

    const int tid = threadIdx.x;
    const int e0  = blockIdx.x * EP;
    for (int i = tid; i < EP * 400; i += NT) a_sh[i] = g_ip[(size_t)e0 * 400 + i];
    for (int i = tid; i < 2048; i += NT) w2[i] = Wp2[i];

    const int tx = tid & 31;
    const int r  = (tid >> 5) & 7;
    const int cz = tid >> 8;
    const int jb = tx * 2 + 128 * cz;

    // GEMM1: p = relu(ip @ Wp0 + bp0), K=400, 25 chunks of 16
    {
        ull acc[8][4];
        #pragma unroll
        for (int p = 0; p < 8; p++)
            #pragma unroll
            for (int i = 0; i < 4; i++) acc[p][i] = 0ULL;

        __syncthreads();   // a_sh / w2 ready
        #pragma unroll
        for (int pc = 0; pc < 2; pc++) {
            const float* src = Wp0 + (size_t)pc * 16 * 256;
            unsigned dst0 = wbuf_a + (unsigned)(pc * 4096) * 4;
            for (int q = tid; q < 1024; q += NT) {
                int row = q >> 6, col = q & 63;
                CP16(dst0 + (unsigned)(row * 256 + col * 4) * 4,
                     src + row * 256 + col * 4);
            }
            CP_COMMIT();
        }

        for (int c = 0; c < 25; c++) {
            if (c + 1 < 25) CP_WAIT1(); else CP_WAIT0();
            __syncthreads();
            if (c + 2 < 25) {
                const float* src = Wp0 + (size_t)(c + 2) * 16 * 256;
                unsigned dst0 = wbuf_a + (unsigned)(((c + 2) % 3) * 4096) * 4;
                for (int q = tid; q < 1024; q += NT) {
                    int row = q >> 6, col = q & 63;
                    CP16(dst0 + (unsigned)(row * 256 + col * 4) * 4,
                         src + row * 256 + col * 4);
                }
                CP_COMMIT();
            }
            mma_chunk<2, AP, PP>(wbuf + (c % 3) * 4096,
                                 a_sh + r * 8 * AP + c * 16, jb, acc);
        }
        #pragma unroll
        for (int i = 0; i < 2; i++) {
            int j = jb + 64 * i;
            float b0 = __ldg(bp0 + j), b1 = __ldg(bp0 + j + 1);
            #pragma unroll
            for (int p = 0; p < 8; p++) {
                float lo, hi; unpack2(acc[p][i], lo, hi);
                *(float2*)&p_sh[(r * 8 + p) * PP + j] =
                    make_float2(fmaxf(lo + b0, 0.f), fmaxf(hi + b1, 0.f));
            }
        }
        __syncthreads();   // p_sh ready; GEMM1 wbuf reads done
    }

    // GEMM2: q = relu(p @ Wp1 + bp1), K=256 (q overwrites a_sh, pitch PP)
    {
        ull acc[8][4];
        #pragma unroll
        for (int p = 0; p < 8; p++)
            #pragma unroll
            for (int i = 0; i < 4; i++) acc[p][i] = 0ULL;

        #pragma unroll
        for (int pc = 0; pc < 2; pc++) {
            const float* src = Wp1 + (size_t)pc * 16 * 256;
            unsigned dst0 = wbuf_a + (unsigned)(pc * 4096) * 4;
            for (int q = tid; q < 1024; q += NT) {
                int row = q >> 6, col = q & 63;
                CP16(dst0 + (unsigned)(row * 256 + col * 4) * 4,
                     src + row * 256 + col * 4);
            }
            CP_COMMIT();
        }

        for (int c = 0; c < 16; c++) {
            if (c + 1 < 16) CP_WAIT1(); else CP_WAIT0();
            __syncthreads();
            if (c + 2 < 16) {
                const float* src = Wp1 + (size_t)(c + 2) * 16 * 256;
                unsigned dst0 = wbuf_a + (unsigned)(((c + 2) % 3) * 4096) * 4;
                for (int q = tid; q < 1024; q += NT) {
                    int row = q >> 6, col = q & 63;
                    CP16(dst0 + (unsigned)(row * 256 + col * 4) * 4,
                         src + row * 256 + col * 4);
                }
                CP_COMMIT();
            }
            mma_chunk<2, PP, PP>(wbuf + (c % 3) * 4096,
                                 p_sh + r * 8 * PP + c * 16, jb, acc);
        }
        #pragma unroll
        for (int i = 0; i < 2; i++) {
            int j = jb + 64 * i;
            float b0 = __ldg(bp1 + j), b1 = __ldg(bp1 + j + 1);
            #pragma unroll
            for (int p = 0; p < 8; p++) {
                float lo, hi; unpack2(acc[p][i], lo, hi);
                *(float2*)&a_sh[(r * 8 + p) * PP + j] =
                    make_float2(fmaxf(lo + b0, 0.f), fmaxf(hi + b1, 0.f));
            }
        }
        __syncthreads();
    }

    // GEMM3: out = tanh(q @ Wp2 + bp2); one output per thread
    {
        int e = tid >> 3, jo = tid & 7;
        float acc = __ldg(bp2 + jo);
        #pragma unroll 8
        for (int k = 0; k < 256; k++)
            acc = fmaf(a_sh[e * PP + k], w2[k * 8 + jo], acc);
        out[(size_t)(e0 + e) * 8 + jo] = tanhf(acc);
    }
}

// ---------------------------------------------------------------------------
extern "C" void kernel_launch(void* const* d_in, const int* in_sizes, int n_in,
                              void* d_out, int out_size)
{
    const float* o   = (const float*)d_in[0];
    const float* g   = (const float*)d_in[1];
    const float* Wc  = (const float*)d_in[2];
    const float* bc  = (const float*)d_in[3];
    const float* Wa0 = (const float*)d_in[4];
    const float* ba0 = (const float*)d_in[5];
    const float* Wa1 = (const float*)d_in[6];
    const float* ba1 = (const float*)d_in[7];
    const float* Wp0 = (const float*)d_in[8];
    const float* bp0 = (const float*)d_in[9];
    const float* Wp1 = (const float*)d_in[10];
    const float* bp1 = (const float*)d_in[11];
    const float* Wp2 = (const float*)d_in[12];
    const float* bp2 = (const float*)d_in[13];
    float* out = (float*)d_out;

    int B = in_sizes[0] / 260;

    size_t u_fl = 3 * KC * WAP + WAP;   // 21952 (phase2 max of union)
    size_t sm1 = (size_t)(PAIRS * XP + PAIRS * HP + u_fl) * sizeof(float);
    size_t sm3 = (size_t)(EP * AP + EP * PP + 3 * 16 * 256 + 2048) * sizeof(float);
    cudaFuncSetAttribute(k_main, cudaFuncAttributeMaxDynamicSharedMemorySize, (int)sm1);
    cudaFuncSetAttribute(k_head, cudaFuncAttributeMaxDynamicSharedMemorySize, (int)sm3);

    k_main<<<B / TB, NT, sm1>>>(o, g, Wc, bc, Wa0, ba0, Wa1, ba1);
    k_head<<<B / EP, NT, sm3>>>(Wp0, bp0, Wp1, bp1, Wp2, bp2, out);
}

// round 11
// speedup vs baseline: 2.3441x; 1.6183x over previous
#include <cuda_runtime.h>
#include <cuda_bf16.h>
#include <math.h>
#include <stdint.h>

typedef unsigned long long ull;

// ===========================================================================
// Helpers
// ===========================================================================
__device__ __forceinline__ unsigned smem_u32(const void* p) {
    unsigned a;
    asm("{ .reg .u64 t; cvta.to.shared.u64 t, %1; cvt.u32.u64 %0, t; }"
        : "=r"(a) : "l"(p));
    return a;
}
#define CP16(dst_u32, src_ptr) \
    asm volatile("cp.async.cg.shared.global [%0], [%1], 16;" \
                 :: "r"(dst_u32), "l"(src_ptr))
#define CP_COMMIT() asm volatile("cp.async.commit_group;")
#define CP_WAIT1()  asm volatile("cp.async.wait_group 1;")
#define CP_WAIT0()  asm volatile("cp.async.wait_group 0;")

__device__ __forceinline__ void ldsm_x4(unsigned addr, unsigned& r0, unsigned& r1,
                                        unsigned& r2, unsigned& r3) {
    asm volatile("ldmatrix.sync.aligned.m8n8.x4.shared.b16 {%0,%1,%2,%3}, [%4];"
                 : "=r"(r0), "=r"(r1), "=r"(r2), "=r"(r3) : "r"(addr));
}
__device__ __forceinline__ void ldsm_x2(unsigned addr, unsigned& r0, unsigned& r1) {
    asm volatile("ldmatrix.sync.aligned.m8n8.x2.shared.b16 {%0,%1}, [%2];"
                 : "=r"(r0), "=r"(r1) : "r"(addr));
}
__device__ __forceinline__ void mma16816(float* d, unsigned a0, unsigned a1,
                                         unsigned a2, unsigned a3,
                                         unsigned b0, unsigned b1) {
    asm volatile("mma.sync.aligned.m16n8k16.row.col.f32.bf16.bf16.f32 "
                 "{%0,%1,%2,%3}, {%4,%5,%6,%7}, {%8,%9}, {%0,%1,%2,%3};"
                 : "+f"(d[0]), "+f"(d[1]), "+f"(d[2]), "+f"(d[3])
                 : "r"(a0), "r"(a1), "r"(a2), "r"(a3), "r"(b0), "r"(b1));
}
__device__ __forceinline__ float redsum8(float v) {
    v += __shfl_xor_sync(0xffffffffu, v, 4);
    v += __shfl_xor_sync(0xffffffffu, v, 8);
    v += __shfl_xor_sync(0xffffffffu, v, 16);
    return v;
}
__device__ __forceinline__ void split2(float v0, float v1,
                                       __nv_bfloat162& h, __nv_bfloat162& l) {
    __nv_bfloat16 h0 = __float2bfloat16(v0), h1 = __float2bfloat16(v1);
    __nv_bfloat16 l0 = __float2bfloat16(v0 - __bfloat162float(h0));
    __nv_bfloat16 l1 = __float2bfloat16(v1 - __bfloat162float(h1));
    h = __halves2bfloat162(h0, h1);
    l = __halves2bfloat162(l0, l1);
}

// ===========================================================================
// Globals
// ===========================================================================
__device__ float g_ip[65536 * 400];                          // input_pi scratch
__device__ __align__(16) __nv_bfloat16 W0g[2][256 * 72];     // Wa0^T hi/lo, pitch 72
__device__ __align__(16) __nv_bfloat16 W1g[2][400 * 264];    // Wa1^T hi/lo, pitch 264

// ===========================================================================
// Prep: bf16 hi/lo weight images (n-major, k contiguous)
// ===========================================================================
__global__ void k_prep(const float* __restrict__ Wa0, const float* __restrict__ Wa1) {
    int idx = blockIdx.x * 256 + threadIdx.x;
    if (idx < 16384) {                         // 256 n x 64 k
        int n = idx >> 6, k = idx & 63;
        float v = (k < 50) ? Wa0[k * 256 + n] : 0.f;
        __nv_bfloat16 h = __float2bfloat16(v);
        __nv_bfloat16 l = __float2bfloat16(v - __bfloat162float(h));
        W0g[0][n * 72 + k] = h;
        W0g[1][n * 72 + k] = l;
    } else if (idx < 16384 + 102400) {         // 400 n x 256 k
        int t = idx - 16384;
        int k = t / 400, n = t % 400;
        float v = Wa1[k * 400 + n];
        __nv_bfloat16 h = __float2bfloat16(v);
        __nv_bfloat16 l = __float2bfloat16(v - __bfloat162float(h));
        W1g[0][n * 264 + k] = h;
        W1g[1][n * 264 + k] = l;
    }
}

// ===========================================================================
// Kernel 1: attention + gather + a0 + a1 + object-sum -> g_ip (B x 400)
// Block = 16 elements (M=128 rows), 256 threads / 8 warps, warp w owns m16
// strip rows [w*16, w*16+16) = elements 2w, 2w+1. Split-bf16 mma.sync.
// B operands are n-major/k-contiguous -> NON-trans ldmatrix gives the exact
// mma.m16n8k16 B fragment (lane L: B[k=2(L%4)+i][n=L/4]).
// ===========================================================================
#define OFF_A1H 0
#define OFF_A1L 67584
#define OFF_A0H 135168
#define OFF_A0L 153600
#define OFF_B0  172032
#define OFF_B1  135168
#define OFF_BA1 219648
#define OFF_BA0 221248
#define SMEM_MAIN 222464

__global__ __launch_bounds__(256, 1)
void k_main(const float* __restrict__ o,   const float* __restrict__ g,
            const float* __restrict__ Wc,  const float* __restrict__ bc,
            const float* __restrict__ ba0, const float* __restrict__ ba1)
{
    extern __shared__ __align__(1024) unsigned char smem[];
    const unsigned sbase = smem_u32(smem);
    const int tid = threadIdx.x, lane = tid & 31, warp = tid >> 5;
    const int e0 = blockIdx.x * 16;

    // ---- biases ----
    float* ba0_sh = (float*)(smem + OFF_BA0);
    float* ba1_sh = (float*)(smem + OFF_BA1);
    ba0_sh[tid] = ba0[tid];
    for (int i = tid; i < 400; i += 256) ba1_sh[i] = ba1[i];

    // ---- phase 0: staging + attention + scaled-x (A0 bf16 hi/lo) ----
    {
        float* o_sh  = (float*)(smem + 0);        // 16 x 260
        float* Wc_sh = (float*)(smem + 16640);    // 100 x 50
        float* g_sh  = (float*)(smem + 36640);    // 16 x 100
        float* att   = (float*)(smem + 43040);    // 16 x 52
        for (int i = tid; i < 16 * 260; i += 256) o_sh[i] = o[(size_t)e0 * 260 + i];
        for (int i = tid; i < 5000; i += 256) Wc_sh[i] = Wc[i];
        for (int i = tid; i < 1600; i += 256) g_sh[i] = g[(size_t)e0 * 100 + i];
        __syncthreads();

        for (int idx = tid; idx < 800; idx += 256) {
            int e = idx / 50, j = idx % 50;
            float acc = bc[j];
            #pragma unroll 4
            for (int k = 0; k < 100; k++)
                acc = fmaf(g_sh[e * 100 + k], Wc_sh[k * 50 + j], acc);
            att[e * 52 + j] = 1.0f / (1.0f + expf(-acc));
        }
        __syncthreads();

        // A0[row][k], row = e*8+n, k=d (0..63, zero-pad 50..63), pitch 72 bf16
        for (int idx = tid; idx < 4096; idx += 256) {
            int row = idx >> 5, kp = idx & 31;
            int e = row >> 3, n = row & 7;
            float v[2];
            #pragma unroll
            for (int t = 0; t < 2; t++) {
                int d = kp * 2 + t;
                float x = 0.f;
                if (d < 50) {
                    int gi;
                    if (d < 10)       gi = d;
                    else if (d < 20)  gi = 120 + d;
                    else if (d < 35)  gi = 15 * n + d - 10;
                    else              gi = 15 * n + d + 105;
                    x = o_sh[e * 260 + gi] * att[e * 52 + d];
                }
                v[t] = x;
            }
            __nv_bfloat162 h2, l2;
            split2(v[0], v[1], h2, l2);
            unsigned off = (unsigned)(row * 72 + kp * 2) * 2;
            *(__nv_bfloat162*)(smem + OFF_A0H + off) = h2;
            *(__nv_bfloat162*)(smem + OFF_A0L + off) = l2;
        }
    }

    // ---- preload B0 chunk 0 (n 0..63, both splits: 2x9216B) ----
    for (int q = tid; q < 1152; q += 256) {
        int sp = q >= 576, qq = q - sp * 576;
        CP16(sbase + OFF_B0 + sp * 9216 + qq * 16, (const char*)W0g[sp] + qq * 16);
    }
    CP_COMMIT();
    __syncthreads();   // A0 visible

    // per-lane ldmatrix address components
    const unsigned aoffA = (unsigned)(((warp * 16 + (lane & 15)) * 72 + ((lane & 16) >> 1)) * 2);
    const unsigned aoffA1 = (unsigned)(((warp * 16 + (lane & 15)) * 264 + ((lane & 16) >> 1)) * 2);
    const int bg = lane >> 3;
    // non-trans B: lane groups give (n-rows 0-7 k0-7), (n0-7 k8-15), (n8-15 k0-7), (n8-15 k8-15)
    const unsigned boff0 = (unsigned)((((bg >> 1) * 8 + (lane & 7)) * 72 + (bg & 1) * 8) * 2);
    const unsigned boff1 = (unsigned)((((bg >> 1) * 8 + (lane & 7)) * 264 + (bg & 1) * 8) * 2);
    const unsigned boffS = (unsigned)(((32 + (lane & 7)) * 264 + ((lane >> 3) & 1) * 8) * 2);

    // ================= GEMM1: h = relu(x @ Wa0 + ba0) -> A1 =================
    for (int c = 0; c < 4; c++) {
        if (c < 3) {
            for (int q = tid; q < 1152; q += 256) {
                int sp = q >= 576, qq = q - sp * 576;
                CP16(sbase + OFF_B0 + ((c + 1) & 1) * 18432 + sp * 9216 + qq * 16,
                     (const char*)W0g[sp] + (size_t)(c + 1) * 9216 + qq * 16);
            }
            CP_COMMIT();
            CP_WAIT1();
        } else {
            CP_WAIT0();
        }
        __syncthreads();

        const unsigned bufH = sbase + OFF_B0 + (c & 1) * 18432;
        const unsigned bufL = bufH + 9216;
        float d[8][4];
        #pragma unroll
        for (int t = 0; t < 8; t++)
            #pragma unroll
            for (int i = 0; i < 4; i++) d[t][i] = 0.f;

        #pragma unroll
        for (int s = 0; s < 4; s++) {
            unsigned aH[4], aL[4];
            ldsm_x4(sbase + OFF_A0H + aoffA + s * 32, aH[0], aH[1], aH[2], aH[3]);
            ldsm_x4(sbase + OFF_A0L + aoffA + s * 32, aL[0], aL[1], aL[2], aL[3]);
            #pragma unroll
            for (int pr = 0; pr < 4; pr++) {
                unsigned bh[4], bl[4];
                unsigned bo = pr * (16 * 144) + boff0 + s * 32;
                ldsm_x4(bufH + bo, bh[0], bh[1], bh[2], bh[3]);
                ldsm_x4(bufL + bo, bl[0], bl[1], bl[2], bl[3]);
                mma16816(d[2 * pr],     aH[0], aH[1], aH[2], aH[3], bh[0], bh[1]);
                mma16816(d[2 * pr],     aH[0], aH[1], aH[2], aH[3], bl[0], bl[1]);
                mma16816(d[2 * pr],     aL[0], aL[1], aL[2], aL[3], bh[0], bh[1]);
                mma16816(d[2 * pr + 1], aH[0], aH[1], aH[2], aH[3], bh[2], bh[3]);
                mma16816(d[2 * pr + 1], aH[0], aH[1], aH[2], aH[3], bl[2], bl[3]);
                mma16816(d[2 * pr + 1], aL[0], aL[1], aL[2], aL[3], bh[2], bh[3]);
            }
        }

        // epilogue: bias + relu + split -> A1 (pitch 264)
        const int r0 = warp * 16 + (lane >> 2);
        #pragma unroll
        for (int t = 0; t < 8; t++) {
            int c0 = c * 64 + t * 8 + (lane & 3) * 2;
            float b0 = ba0_sh[c0], b1 = ba0_sh[c0 + 1];
            __nv_bfloat162 h2, l2;
            split2(fmaxf(d[t][0] + b0, 0.f), fmaxf(d[t][1] + b1, 0.f), h2, l2);
            unsigned offA = (unsigned)(r0 * 264 + c0) * 2;
            *(__nv_bfloat162*)(smem + OFF_A1H + offA) = h2;
            *(__nv_bfloat162*)(smem + OFF_A1L + offA) = l2;
            split2(fmaxf(d[t][2] + b0, 0.f), fmaxf(d[t][3] + b1, 0.f), h2, l2);
            unsigned offB = (unsigned)((r0 + 8) * 264 + c0) * 2;
            *(__nv_bfloat162*)(smem + OFF_A1H + offB) = h2;
            *(__nv_bfloat162*)(smem + OFF_A1L + offB) = l2;
        }
        __syncthreads();
    }

    // ============ GEMM2: input_pi = sum_obj relu(h @ Wa1 + ba1) ============
    // 10 n-chunks of 40; B1 chunk = 2 splits x (40 x 264 bf16) = 42240 B
    for (int q = tid; q < 2640; q += 256) {   // preload chunk 0
        int sp = q >= 1320, qq = q - sp * 1320;
        CP16(sbase + OFF_B1 + sp * 21120 + qq * 16, (const char*)W1g[sp] + qq * 16);
    }
    CP_COMMIT();

    for (int c = 0; c < 10; c++) {
        if (c < 9) {
            for (int q = tid; q < 2640; q += 256) {
                int sp = q >= 1320, qq = q - sp * 1320;
                CP16(sbase + OFF_B1 + ((c + 1) & 1) * 42240 + sp * 21120 + qq * 16,
                     (const char*)W1g[sp] + (size_t)(c + 1) * 21120 + qq * 16);
            }
            CP_COMMIT();
            CP_WAIT1();
        } else {
            CP_WAIT0();
        }
        __syncthreads();

        const unsigned bufH = sbase + OFF_B1 + (c & 1) * 42240;
        const unsigned bufL = bufH + 21120;
        float d[5][4];
        #pragma unroll
        for (int t = 0; t < 5; t++)
            #pragma unroll
            for (int i = 0; i < 4; i++) d[t][i] = 0.f;

        #pragma unroll 4
        for (int s = 0; s < 16; s++) {
            unsigned aH[4], aL[4];
            ldsm_x4(sbase + OFF_A1H + aoffA1 + s * 32, aH[0], aH[1], aH[2], aH[3]);
            ldsm_x4(sbase + OFF_A1L + aoffA1 + s * 32, aL[0], aL[1], aL[2], aL[3]);
            #pragma unroll
            for (int pr = 0; pr < 2; pr++) {
                unsigned bh[4], bl[4];
                unsigned bo = pr * (16 * 528) + boff1 + s * 32;
                ldsm_x4(bufH + bo, bh[0], bh[1], bh[2], bh[3]);
                ldsm_x4(bufL + bo, bl[0], bl[1], bl[2], bl[3]);
                mma16816(d[2 * pr],     aH[0], aH[1], aH[2], aH[3], bh[0], bh[1]);
                mma16816(d[2 * pr],     aH[0], aH[1], aH[2], aH[3], bl[0], bl[1]);
                mma16816(d[2 * pr],     aL[0], aL[1], aL[2], aL[3], bh[0], bh[1]);
                mma16816(d[2 * pr + 1], aH[0], aH[1], aH[2], aH[3], bh[2], bh[3]);
                mma16816(d[2 * pr + 1], aH[0], aH[1], aH[2], aH[3], bl[2], bl[3]);
                mma16816(d[2 * pr + 1], aL[0], aL[1], aL[2], aL[3], bh[2], bh[3]);
            }
            {   // single tile (local n 32..39)
                unsigned bh[2], bl[2];
                unsigned bo = boffS + s * 32;
                ldsm_x2(bufH + bo, bh[0], bh[1]);
                ldsm_x2(bufL + bo, bl[0], bl[1]);
                mma16816(d[4], aH[0], aH[1], aH[2], aH[3], bh[0], bh[1]);
                mma16816(d[4], aH[0], aH[1], aH[2], aH[3], bl[0], bl[1]);
                mma16816(d[4], aL[0], aL[1], aL[2], aL[3], bh[0], bh[1]);
            }
        }

        // epilogue: bias + relu + 8-row object-sum -> g_ip
        #pragma unroll
        for (int t = 0; t < 5; t++) {
            int c0 = c * 40 + t * 8 + (lane & 3) * 2;
            float b0 = ba1_sh[c0], b1 = ba1_sh[c0 + 1];
            float s00 = redsum8(fmaxf(d[t][0] + b0, 0.f));
            float s01 = redsum8(fmaxf(d[t][1] + b1, 0.f));
            float s10 = redsum8(fmaxf(d[t][2] + b0, 0.f));
            float s11 = redsum8(fmaxf(d[t][3] + b1, 0.f));
            if (lane < 4)
                *(float2*)&g_ip[(size_t)(e0 + 2 * warp) * 400 + c0] = make_float2(s00, s01);
            else if (lane < 8)
                *(float2*)&g_ip[(size_t)(e0 + 2 * warp + 1) * 400 + c0] = make_float2(s10, s11);
        }
        __syncthreads();
    }
}

// ===========================================================================
// Kernel 2: policy head (round-8 SIMT FFMA2 version, unchanged)
// ===========================================================================
#define EP  64
#define AP  400
#define PP  256
#define NT  512

__device__ __forceinline__ ull packdup(float v) {
    ull r; asm("mov.b64 %0, {%1,%1};" : "=l"(r) : "f"(v)); return r;
}
__device__ __forceinline__ void unpack2(ull v, float& lo, float& hi) {
    asm("mov.b64 {%0,%1}, %2;" : "=f"(lo), "=f"(hi) : "l"(v));
}
#define FMA2(d, a, b) asm("fma.rn.f32x2 %0, %1, %2, %0;" : "+l"(d) : "l"(a), "l"(b))

template<int NC, int APITCH, int WPITCH>
__device__ __forceinline__ void mma_chunk(
    const float* __restrict__ wb, const float* __restrict__ abase,
    int jb, ull (&acc)[8][4])
{
    #pragma unroll
    for (int kk2 = 0; kk2 < 8; kk2++) {
        ull a2[8];
        #pragma unroll
        for (int p = 0; p < 8; p++)
            a2[p] = *(const ull*)(abase + p * APITCH + 2 * kk2);
        #pragma unroll
        for (int dk = 0; dk < 2; dk++) {
            ull ap[8];
            #pragma unroll
            for (int p = 0; p < 8; p++) {
                float lo, hi; unpack2(a2[p], lo, hi);
                ap[p] = packdup(dk ? hi : lo);
            }
            #pragma unroll
            for (int i = 0; i < NC; i++) {
                ull b = *(const ull*)(wb + (2 * kk2 + dk) * WPITCH + jb + 64 * i);
                #pragma unroll
                for (int p = 0; p < 8; p++) FMA2(acc[p][i], ap[p], b);
            }
        }
    }
}

__global__ __launch_bounds__(NT, 1) void k_head(
    const float* __restrict__ Wp0, const float* __restrict__ bp0,
    const float* __restrict__ Wp1, const float* __restrict__ bp1,
    const float* __restrict__ Wp2, const float* __restrict__ bp2,
    float* __restrict__ out)
{
    extern __shared__ float smf[];
    float* a_sh = smf;
    float* p_sh = a_sh + EP * AP;
    float* wbuf = p_sh + EP * PP;
    float* w2   = wbuf + 3 * 16 * 256;
    const unsigned wbuf_a = smem_u32(wbuf);

    const int tid = threadIdx.x;
    const int e0  = blockIdx.x * EP;
    for (int i = tid; i < EP * 400; i += NT) a_sh[i] = g_ip[(size_t)e0 * 400 + i];
    for (int i = tid; i < 2048; i += NT) w2[i] = Wp2[i];

    const int tx = tid & 31;
    const int r  = (tid >> 5) & 7;
    const int cz = tid >> 8;
    const int jb = tx * 2 + 128 * cz;

    {
        ull acc[8][4];
        #pragma unroll
        for (int p = 0; p < 8; p++)
            #pragma unroll
            for (int i = 0; i < 4; i++) acc[p][i] = 0ULL;

        __syncthreads();
        #pragma unroll
        for (int pc = 0; pc < 2; pc++) {
            const float* src = Wp0 + (size_t)pc * 16 * 256;
            unsigned dst0 = wbuf_a + (unsigned)(pc * 4096) * 4;
            for (int q = tid; q < 1024; q += NT) {
                int row = q >> 6, col = q & 63;
                CP16(dst0 + (unsigned)(row * 256 + col * 4) * 4,
                     src + row * 256 + col * 4);
            }
            CP_COMMIT();
        }
        for (int c = 0; c < 25; c++) {
            if (c + 1 < 25) CP_WAIT1(); else CP_WAIT0();
            __syncthreads();
            if (c + 2 < 25) {
                const float* src = Wp0 + (size_t)(c + 2) * 16 * 256;
                unsigned dst0 = wbuf_a + (unsigned)(((c + 2) % 3) * 4096) * 4;
                for (int q = tid; q < 1024; q += NT) {
                    int row = q >> 6, col = q & 63;
                    CP16(dst0 + (unsigned)(row * 256 + col * 4) * 4,
                         src + row * 256 + col * 4);
                }
                CP_COMMIT();
            }
            mma_chunk<2, AP, PP>(wbuf + (c % 3) * 4096,
                                 a_sh + r * 8 * AP + c * 16, jb, acc);
        }
        #pragma unroll
        for (int i = 0; i < 2; i++) {
            int j = jb + 64 * i;
            float b0 = __ldg(bp0 + j), b1 = __ldg(bp0 + j + 1);
            #pragma unroll
            for (int p = 0; p < 8; p++) {
                float lo, hi; unpack2(acc[p][i], lo, hi);
                *(float2*)&p_sh[(r * 8 + p) * PP + j] =
                    make_float2(fmaxf(lo + b0, 0.f), fmaxf(hi + b1, 0.f));
            }
        }
        __syncthreads();
    }

    {
        ull acc[8][4];
        #pragma unroll
        for (int p = 0; p < 8; p++)
            #pragma unroll
            for (int i = 0; i < 4; i++) acc[p][i] = 0ULL;

        #pragma unroll
        for (int pc = 0; pc < 2; pc++) {
            const float* src = Wp1 + (size_t)pc * 16 * 256;
            unsigned dst0 = wbuf_a + (unsigned)(pc * 4096) * 4;
            for (int q = tid; q < 1024; q += NT) {
                int row = q >> 6, col = q & 63;
                CP16(dst0 + (unsigned)(row * 256 + col * 4) * 4,
                     src + row * 256 + col * 4);
            }
            CP_COMMIT();
        }
        for (int c = 0; c < 16; c++) {
            if (c + 1 < 16) CP_WAIT1(); else CP_WAIT0();
            __syncthreads();
            if (c + 2 < 16) {
                const float* src = Wp1 + (size_t)(c + 2) * 16 * 256;
                unsigned dst0 = wbuf_a + (unsigned)(((c + 2) % 3) * 4096) * 4;
                for (int q = tid; q < 1024; q += NT) {
                    int row = q >> 6, col = q & 63;
                    CP16(dst0 + (unsigned)(row * 256 + col * 4) * 4,
                         src + row * 256 + col * 4);
                }
                CP_COMMIT();
            }
            mma_chunk<2, PP, PP>(wbuf + (c % 3) * 4096,
                                 p_sh + r * 8 * PP + c * 16, jb, acc);
        }
        #pragma unroll
        for (int i = 0; i < 2; i++) {
            int j = jb + 64 * i;
            float b0 = __ldg(bp1 + j), b1 = __ldg(bp1 + j + 1);
            #pragma unroll
            for (int p = 0; p < 8; p++) {
                float lo, hi; unpack2(acc[p][i], lo, hi);
                *(float2*)&a_sh[(r * 8 + p) * PP + j] =
                    make_float2(fmaxf(lo + b0, 0.f), fmaxf(hi + b1, 0.f));
            }
        }
        __syncthreads();
    }

    {
        int e = tid >> 3, jo = tid & 7;
        float acc = __ldg(bp2 + jo);
        #pragma unroll 8
        for (int k = 0; k < 256; k++)
            acc = fmaf(a_sh[e * PP + k], w2[k * 8 + jo], acc);
        out[(size_t)(e0 + e) * 8 + jo] = tanhf(acc);
    }
}

// ===========================================================================
extern "C" void kernel_launch(void* const* d_in, const int* in_sizes, int n_in,
                              void* d_out, int out_size)
{
    const float* o   = (const float*)d_in[0];
    const float* g   = (const float*)d_in[1];
    const float* Wc  = (const float*)d_in[2];
    const float* bc  = (const float*)d_in[3];
    const float* Wa0 = (const float*)d_in[4];
    const float* ba0 = (const float*)d_in[5];
    const float* Wa1 = (const float*)d_in[6];
    const float* ba1 = (const float*)d_in[7];
    const float* Wp0 = (const float*)d_in[8];
    const float* bp0 = (const float*)d_in[9];
    const float* Wp1 = (const float*)d_in[10];
    const float* bp1 = (const float*)d_in[11];
    const float* Wp2 = (const float*)d_in[12];
    const float* bp2 = (const float*)d_in[13];
    float* out = (float*)d_out;

    int B = in_sizes[0] / 260;

    size_t sm3 = (size_t)(EP * AP + EP * PP + 3 * 16 * 256 + 2048) * sizeof(float);
    cudaFuncSetAttribute(k_main, cudaFuncAttributeMaxDynamicSharedMemorySize, SMEM_MAIN);
    cudaFuncSetAttribute(k_head, cudaFuncAttributeMaxDynamicSharedMemorySize, (int)sm3);

    k_prep<<<464, 256>>>(Wa0, Wa1);
    k_main<<<B / 16, 256, SMEM_MAIN>>>(o, g, Wc, bc, ba0, ba1);
    k_head<<<B / EP, NT, sm3>>>(Wp0, bp0, Wp1, bp1, Wp2, bp2, out);
}

// round 12
// speedup vs baseline: 2.5139x; 1.0724x over previous
#include <cuda_runtime.h>
#include <cuda_bf16.h>
#include <math.h>
#include <stdint.h>

typedef unsigned long long ull;

// ===========================================================================
// Helpers
// ===========================================================================
__device__ __forceinline__ unsigned smem_u32(const void* p) {
    unsigned a;
    asm("{ .reg .u64 t; cvta.to.shared.u64 t, %1; cvt.u32.u64 %0, t; }"
        : "=r"(a) : "l"(p));
    return a;
}
#define CP16(dst_u32, src_ptr) \
    asm volatile("cp.async.cg.shared.global [%0], [%1], 16;" \
                 :: "r"(dst_u32), "l"(src_ptr))
#define CP_COMMIT() asm volatile("cp.async.commit_group;")
#define CP_WAIT1()  asm volatile("cp.async.wait_group 1;")
#define CP_WAIT0()  asm volatile("cp.async.wait_group 0;")

__device__ __forceinline__ void ldsm_x4(unsigned addr, unsigned& r0, unsigned& r1,
                                        unsigned& r2, unsigned& r3) {
    asm volatile("ldmatrix.sync.aligned.m8n8.x4.shared.b16 {%0,%1,%2,%3}, [%4];"
                 : "=r"(r0), "=r"(r1), "=r"(r2), "=r"(r3) : "r"(addr));
}
__device__ __forceinline__ void ldsm_x2(unsigned addr, unsigned& r0, unsigned& r1) {
    asm volatile("ldmatrix.sync.aligned.m8n8.x2.shared.b16 {%0,%1}, [%2];"
                 : "=r"(r0), "=r"(r1) : "r"(addr));
}
__device__ __forceinline__ void mma16816(float* d, unsigned a0, unsigned a1,
                                         unsigned a2, unsigned a3,
                                         unsigned b0, unsigned b1) {
    asm volatile("mma.sync.aligned.m16n8k16.row.col.f32.bf16.bf16.f32 "
                 "{%0,%1,%2,%3}, {%4,%5,%6,%7}, {%8,%9}, {%0,%1,%2,%3};"
                 : "+f"(d[0]), "+f"(d[1]), "+f"(d[2]), "+f"(d[3])
                 : "r"(a0), "r"(a1), "r"(a2), "r"(a3), "r"(b0), "r"(b1));
}
__device__ __forceinline__ float redsum8(float v) {
    v += __shfl_xor_sync(0xffffffffu, v, 4);
    v += __shfl_xor_sync(0xffffffffu, v, 8);
    v += __shfl_xor_sync(0xffffffffu, v, 16);
    return v;
}
__device__ __forceinline__ void split2(float v0, float v1,
                                       __nv_bfloat162& h, __nv_bfloat162& l) {
    __nv_bfloat16 h0 = __float2bfloat16(v0), h1 = __float2bfloat16(v1);
    __nv_bfloat16 l0 = __float2bfloat16(v0 - __bfloat162float(h0));
    __nv_bfloat16 l1 = __float2bfloat16(v1 - __bfloat162float(h1));
    h = __halves2bfloat162(h0, h1);
    l = __halves2bfloat162(l0, l1);
}
// split + relu + bias -> packed regs (for GEMM1->GEMM2 register fusion)
__device__ __forceinline__ void split2u(float v0, float v1,
                                        unsigned& h, unsigned& l) {
    __nv_bfloat162 h2, l2;
    split2(v0, v1, h2, l2);
    h = *(unsigned*)&h2;
    l = *(unsigned*)&l2;
}

// ===========================================================================
// Globals
// ===========================================================================
__device__ float g_ip[65536 * 400];                          // input_pi scratch
__device__ __align__(16) __nv_bfloat16 W0g[2][256 * 72];     // Wa0^T hi/lo, pitch 72
__device__ __align__(16) __nv_bfloat16 W1g[2][400 * 264];    // Wa1^T hi/lo, pitch 264

// ===========================================================================
// Prep: bf16 hi/lo weight images (n-major, k contiguous)
// ===========================================================================
__global__ void k_prep(const float* __restrict__ Wa0, const float* __restrict__ Wa1) {
    int idx = blockIdx.x * 256 + threadIdx.x;
    if (idx < 16384) {                         // 256 n x 64 k
        int n = idx >> 6, k = idx & 63;
        float v = (k < 50) ? Wa0[k * 256 + n] : 0.f;
        __nv_bfloat16 h = __float2bfloat16(v);
        __nv_bfloat16 l = __float2bfloat16(v - __bfloat162float(h));
        W0g[0][n * 72 + k] = h;
        W0g[1][n * 72 + k] = l;
    } else if (idx < 16384 + 102400) {         // 400 n x 256 k
        int t = idx - 16384;
        int k = t / 400, n = t % 400;
        float v = Wa1[k * 400 + n];
        __nv_bfloat16 h = __float2bfloat16(v);
        __nv_bfloat16 l = __float2bfloat16(v - __bfloat162float(h));
        W1g[0][n * 264 + k] = h;
        W1g[1][n * 264 + k] = l;
    }
}

// ===========================================================================
// Kernel 1: attention + gather + a0 + a1 + object-sum -> g_ip (B x 400)
// Block = 16 elements (M=128), 256 threads / 8 warps, warp w owns rows
// [16w,16w+16) = elements 2w,2w+1. GEMM1 output fragments are re-used
// directly as GEMM2 A fragments (D-frag layout == A-frag layout), so the
// intermediate h never touches smem.
// ===========================================================================
#define OFF_B1  0              // B1 double buffer: 2 x 42240
#define OFF_B0  84480          // B0 resident: H 36864 + L 36864
#define OFF_A0H 158208         // A0 hi: 128 x 144B
#define OFF_A0L 176640         // A0 lo
#define OFF_BA1 195072         // 400 f
#define OFF_BA0 196672         // 256 f
#define SMEM_MAIN 197696

__global__ __launch_bounds__(256, 1)
void k_main(const float* __restrict__ o,   const float* __restrict__ g,
            const float* __restrict__ Wc,  const float* __restrict__ bc,
            const float* __restrict__ ba0, const float* __restrict__ ba1)
{
    extern __shared__ __align__(1024) unsigned char smem[];
    const unsigned sbase = smem_u32(smem);
    const int tid = threadIdx.x, lane = tid & 31, warp = tid >> 5;
    const int e0 = blockIdx.x * 16;

    // ---- issue B0 load immediately (region disjoint from staging) : G1 ----
    for (int q = tid; q < 4608; q += 256)
        CP16(sbase + OFF_B0 + q * 16, (const char*)W0g[0] + q * 16);  // W0g[0],[1] contiguous
    CP_COMMIT();

    // ---- biases ----
    float* ba0_sh = (float*)(smem + OFF_BA0);
    float* ba1_sh = (float*)(smem + OFF_BA1);
    ba0_sh[tid] = ba0[tid];
    for (int i = tid; i < 400; i += 256) ba1_sh[i] = ba1[i];

    // ---- phase 0: staging + attention + scaled-x (A0 bf16 hi/lo) ----
    {
        float* o_sh  = (float*)(smem + 0);        // 16 x 260
        float* Wc_sh = (float*)(smem + 16640);    // 100 x 50
        float* g_sh  = (float*)(smem + 36640);    // 16 x 100
        float* att   = (float*)(smem + 43040);    // 16 x 52
        for (int i = tid; i < 16 * 260; i += 256) o_sh[i] = o[(size_t)e0 * 260 + i];
        for (int i = tid; i < 5000; i += 256) Wc_sh[i] = Wc[i];
        for (int i = tid; i < 1600; i += 256) g_sh[i] = g[(size_t)e0 * 100 + i];
        __syncthreads();

        for (int idx = tid; idx < 800; idx += 256) {
            int e = idx / 50, j = idx % 50;
            float acc = bc[j];
            #pragma unroll 4
            for (int k = 0; k < 100; k++)
                acc = fmaf(g_sh[e * 100 + k], Wc_sh[k * 50 + j], acc);
            att[e * 52 + j] = 1.0f / (1.0f + expf(-acc));
        }
        __syncthreads();

        // A0[row][k], row = e*8+n, k=d (0..63, zero-pad 50..63), pitch 72 bf16
        for (int idx = tid; idx < 4096; idx += 256) {
            int row = idx >> 5, kp = idx & 31;
            int e = row >> 3, n = row & 7;
            float v[2];
            #pragma unroll
            for (int t = 0; t < 2; t++) {
                int d = kp * 2 + t;
                float x = 0.f;
                if (d < 50) {
                    int gi;
                    if (d < 10)       gi = d;
                    else if (d < 20)  gi = 120 + d;
                    else if (d < 35)  gi = 15 * n + d - 10;
                    else              gi = 15 * n + d + 105;
                    x = o_sh[e * 260 + gi] * att[e * 52 + d];
                }
                v[t] = x;
            }
            __nv_bfloat162 h2, l2;
            split2(v[0], v[1], h2, l2);
            unsigned off = (unsigned)(row * 72 + kp * 2) * 2;
            *(__nv_bfloat162*)(smem + OFF_A0H + off) = h2;
            *(__nv_bfloat162*)(smem + OFF_A0L + off) = l2;
        }
    }
    __syncthreads();   // A0 + staging done -> B1 region reusable

    // ---- issue B1 chunk 0 : G2 ----
    for (int q = tid; q < 2640; q += 256) {
        int sp = q >= 1320, qq = q - sp * 1320;
        CP16(sbase + OFF_B1 + sp * 21120 + qq * 16, (const char*)W1g[sp] + qq * 16);
    }
    CP_COMMIT();

    CP_WAIT1();        // B0 (G1) done; G2 in flight
    __syncthreads();   // B0 visible to all

    // per-lane ldmatrix address components
    const unsigned aoffA = (unsigned)(((warp * 16 + (lane & 15)) * 72 + ((lane & 16) >> 1)) * 2);
    const int bg = lane >> 3;
    const unsigned brow0 = (unsigned)((bg >> 1) * 8 + (lane & 7));   // n-row within 16-group
    const unsigned bk0   = (unsigned)((bg & 1) * 16);                // k-half byte offset
    const unsigned boff1 = (unsigned)(brow0 * 528 + bk0);
    const unsigned boffS = (unsigned)((32 + (lane & 7)) * 528 + ((lane >> 3) & 1) * 16);

    // GEMM2 A fragments, produced by GEMM1 (register fusion)
    unsigned aH1[16][4], aL1[16][4];

    // ================= GEMM1: h = relu(x @ Wa0 + ba0) -> regs =================
    // B0 fully resident, no barriers inside.
    {
        const unsigned b0H = sbase + OFF_B0;
        const unsigned b0L = b0H + 36864;
        #pragma unroll
        for (int c = 0; c < 4; c++) {           // n-chunks of 64
            float d[8][4];
            #pragma unroll
            for (int t = 0; t < 8; t++)
                #pragma unroll
                for (int i = 0; i < 4; i++) d[t][i] = 0.f;

            #pragma unroll
            for (int s = 0; s < 4; s++) {
                unsigned aH[4], aL[4];
                ldsm_x4(sbase + OFF_A0H + aoffA + s * 32, aH[0], aH[1], aH[2], aH[3]);
                ldsm_x4(sbase + OFF_A0L + aoffA + s * 32, aL[0], aL[1], aL[2], aL[3]);
                unsigned bh[4][4], bl[4][4];
                #pragma unroll
                for (int pr = 0; pr < 4; pr++) {
                    unsigned bo = (unsigned)((c * 64 + pr * 16 + brow0) * 144) + bk0 + s * 32;
                    ldsm_x4(b0H + bo, bh[pr][0], bh[pr][1], bh[pr][2], bh[pr][3]);
                    ldsm_x4(b0L + bo, bl[pr][0], bl[pr][1], bl[pr][2], bl[pr][3]);
                }
                // term-major: same accumulator touched every 8 MMAs
                #pragma unroll
                for (int pr = 0; pr < 4; pr++) {
                    mma16816(d[2 * pr],     aH[0], aH[1], aH[2], aH[3], bh[pr][0], bh[pr][1]);
                    mma16816(d[2 * pr + 1], aH[0], aH[1], aH[2], aH[3], bh[pr][2], bh[pr][3]);
                }
                #pragma unroll
                for (int pr = 0; pr < 4; pr++) {
                    mma16816(d[2 * pr],     aH[0], aH[1], aH[2], aH[3], bl[pr][0], bl[pr][1]);
                    mma16816(d[2 * pr + 1], aH[0], aH[1], aH[2], aH[3], bl[pr][2], bl[pr][3]);
                }
                #pragma unroll
                for (int pr = 0; pr < 4; pr++) {
                    mma16816(d[2 * pr],     aL[0], aL[1], aL[2], aL[3], bh[pr][0], bh[pr][1]);
                    mma16816(d[2 * pr + 1], aL[0], aL[1], aL[2], aL[3], bh[pr][2], bh[pr][3]);
                }
            }

            // epilogue: bias + relu + split -> GEMM2 A fragments (slices 4c+u)
            #pragma unroll
            for (int u = 0; u < 4; u++) {
                const int s = 4 * c + u;
                int j0 = 64 * c + 16 * u + 2 * (lane & 3);   // cols of d[2u][0,1]
                int j1 = j0 + 8;                              // cols of d[2u+1][0,1]
                float b00 = ba0_sh[j0], b01 = ba0_sh[j0 + 1];
                float b10 = ba0_sh[j1], b11 = ba0_sh[j1 + 1];
                split2u(fmaxf(d[2*u][0] + b00, 0.f), fmaxf(d[2*u][1] + b01, 0.f),
                        aH1[s][0], aL1[s][0]);
                split2u(fmaxf(d[2*u][2] + b00, 0.f), fmaxf(d[2*u][3] + b01, 0.f),
                        aH1[s][1], aL1[s][1]);
                split2u(fmaxf(d[2*u+1][0] + b10, 0.f), fmaxf(d[2*u+1][1] + b11, 0.f),
                        aH1[s][2], aL1[s][2]);
                split2u(fmaxf(d[2*u+1][2] + b10, 0.f), fmaxf(d[2*u+1][3] + b11, 0.f),
                        aH1[s][3], aL1[s][3]);
            }
        }
    }

    // ---- issue B1 chunk 1 : G3 ----
    for (int q = tid; q < 2640; q += 256) {
        int sp = q >= 1320, qq = q - sp * 1320;
        CP16(sbase + OFF_B1 + 42240 + sp * 21120 + qq * 16,
             (const char*)W1g[sp] + 21120 + qq * 16);
    }
    CP_COMMIT();

    // ============ GEMM2: input_pi = sum_obj relu(h @ Wa1 + ba1) ============
    // 10 n-chunks of 40; A entirely in registers.
    for (int c = 0; c < 10; c++) {
        if (c < 9) CP_WAIT1(); else CP_WAIT0();
        __syncthreads();                         // chunk c visible everywhere

        const unsigned bufH = sbase + OFF_B1 + (c & 1) * 42240;
        const unsigned bufL = bufH + 21120;
        float d[5][4];
        #pragma unroll
        for (int t = 0; t < 5; t++)
            #pragma unroll
            for (int i = 0; i < 4; i++) d[t][i] = 0.f;

        #pragma unroll
        for (int s = 0; s < 16; s++) {
            unsigned bh0[4], bl0[4], bh1[4], bl1[4], bhS[2], blS[2];
            ldsm_x4(bufH + boff1 + s * 32, bh0[0], bh0[1], bh0[2], bh0[3]);
            ldsm_x4(bufL + boff1 + s * 32, bl0[0], bl0[1], bl0[2], bl0[3]);
            ldsm_x4(bufH + 16 * 528 + boff1 + s * 32, bh1[0], bh1[1], bh1[2], bh1[3]);
            ldsm_x4(bufL + 16 * 528 + boff1 + s * 32, bl1[0], bl1[1], bl1[2], bl1[3]);
            ldsm_x2(bufH + boffS + s * 32, bhS[0], bhS[1]);
            ldsm_x2(bufL + boffS + s * 32, blS[0], blS[1]);
            // HH terms (5 independent accumulators)
            mma16816(d[0], aH1[s][0], aH1[s][1], aH1[s][2], aH1[s][3], bh0[0], bh0[1]);
            mma16816(d[1], aH1[s][0], aH1[s][1], aH1[s][2], aH1[s][3], bh0[2], bh0[3]);
            mma16816(d[2], aH1[s][0], aH1[s][1], aH1[s][2], aH1[s][3], bh1[0], bh1[1]);
            mma16816(d[3], aH1[s][0], aH1[s][1], aH1[s][2], aH1[s][3], bh1[2], bh1[3]);
            mma16816(d[4], aH1[s][0], aH1[s][1], aH1[s][2], aH1[s][3], bhS[0], bhS[1]);
            // HL terms
            mma16816(d[0], aH1[s][0], aH1[s][1], aH1[s][2], aH1[s][3], bl0[0], bl0[1]);
            mma16816(d[1], aH1[s][0], aH1[s][1], aH1[s][2], aH1[s][3], bl0[2], bl0[3]);
            mma16816(d[2], aH1[s][0], aH1[s][1], aH1[s][2], aH1[s][3], bl1[0], bl1[1]);
            mma16816(d[3], aH1[s][0], aH1[s][1], aH1[s][2], aH1[s][3], bl1[2], bl1[3]);
            mma16816(d[4], aH1[s][0], aH1[s][1], aH1[s][2], aH1[s][3], blS[0], blS[1]);
            // LH terms
            mma16816(d[0], aL1[s][0], aL1[s][1], aL1[s][2], aL1[s][3], bh0[0], bh0[1]);
            mma16816(d[1], aL1[s][0], aL1[s][1], aL1[s][2], aL1[s][3], bh0[2], bh0[3]);
            mma16816(d[2], aL1[s][0], aL1[s][1], aL1[s][2], aL1[s][3], bh1[0], bh1[1]);
            mma16816(d[3], aL1[s][0], aL1[s][1], aL1[s][2], aL1[s][3], bh1[2], bh1[3]);
            mma16816(d[4], aL1[s][0], aL1[s][1], aL1[s][2], aL1[s][3], bhS[0], bhS[1]);
        }

        // epilogue: bias + relu + 8-row object-sum -> g_ip
        #pragma unroll
        for (int t = 0; t < 5; t++) {
            int c0 = c * 40 + t * 8 + (lane & 3) * 2;
            float b0 = ba1_sh[c0], b1 = ba1_sh[c0 + 1];
            float s00 = redsum8(fmaxf(d[t][0] + b0, 0.f));
            float s01 = redsum8(fmaxf(d[t][1] + b1, 0.f));
            float s10 = redsum8(fmaxf(d[t][2] + b0, 0.f));
            float s11 = redsum8(fmaxf(d[t][3] + b1, 0.f));
            if (lane < 4)
                *(float2*)&g_ip[(size_t)(e0 + 2 * warp) * 400 + c0] = make_float2(s00, s01);
            else if (lane < 8)
                *(float2*)&g_ip[(size_t)(e0 + 2 * warp + 1) * 400 + c0] = make_float2(s10, s11);
        }

        __syncthreads();                         // all reads of buf (c&1) done
        if (c + 2 < 10) {                        // refill just-freed buffer
            for (int q = tid; q < 2640; q += 256) {
                int sp = q >= 1320, qq = q - sp * 1320;
                CP16(sbase + OFF_B1 + (c & 1) * 42240 + sp * 21120 + qq * 16,
                     (const char*)W1g[sp] + (size_t)(c + 2) * 21120 + qq * 16);
            }
            CP_COMMIT();
        }
    }
}

// ===========================================================================
// Kernel 2: policy head (round-8 SIMT FFMA2 version, unchanged)
// ===========================================================================
#define EP  64
#define AP  400
#define PP  256
#define NT  512

__device__ __forceinline__ ull packdup(float v) {
    ull r; asm("mov.b64 %0, {%1,%1};" : "=l"(r) : "f"(v)); return r;
}
__device__ __forceinline__ void unpack2(ull v, float& lo, float& hi) {
    asm("mov.b64 {%0,%1}, %2;" : "=f"(lo), "=f"(hi) : "l"(v));
}
#define FMA2(d, a, b) asm("fma.rn.f32x2 %0, %1, %2, %0;" : "+l"(d) : "l"(a), "l"(b))

template<int NC, int APITCH, int WPITCH>
__device__ __forceinline__ void mma_chunk(
    const float* __restrict__ wb, const float* __restrict__ abase,
    int jb, ull (&acc)[8][4])
{
    #pragma unroll
    for (int kk2 = 0; kk2 < 8; kk2++) {
        ull a2[8];
        #pragma unroll
        for (int p = 0; p < 8; p++)
            a2[p] = *(const ull*)(abase + p * APITCH + 2 * kk2);
        #pragma unroll
        for (int dk = 0; dk < 2; dk++) {
            ull ap[8];
            #pragma unroll
            for (int p = 0; p < 8; p++) {
                float lo, hi; unpack2(a2[p], lo, hi);
                ap[p] = packdup(dk ? hi : lo);
            }
            #pragma unroll
            for (int i = 0; i < NC; i++) {
                ull b = *(const ull*)(wb + (2 * kk2 + dk) * WPITCH + jb + 64 * i);
                #pragma unroll
                for (int p = 0; p < 8; p++) FMA2(acc[p][i], ap[p], b);
            }
        }
    }
}

__global__ __launch_bounds__(NT, 1) void k_head(
    const float* __restrict__ Wp0, const float* __restrict__ bp0,
    const float* __restrict__ Wp1, const float* __restrict__ bp1,
    const float* __restrict__ Wp2, const float* __restrict__ bp2,
    float* __restrict__ out)
{
    extern __shared__ float smf[];
    float* a_sh = smf;
    float* p_sh = a_sh + EP * AP;
    float* wbuf = p_sh + EP * PP;
    float* w2   = wbuf + 3 * 16 * 256;
    const unsigned wbuf_a = smem_u32(wbuf);

    const int tid = threadIdx.x;
    const int e0  = blockIdx.x * EP;
    for (int i = tid; i < EP * 400; i += NT) a_sh[i] = g_ip[(size_t)e0 * 400 + i];
    for (int i = tid; i < 2048; i += NT) w2[i] = Wp2[i];

    const int tx = tid & 31;
    const int r  = (tid >> 5) & 7;
    const int cz = tid >> 8;
    const int jb = tx * 2 + 128 * cz;

    {
        ull acc[8][4];
        #pragma unroll
        for (int p = 0; p < 8; p++)
            #pragma unroll
            for (int i = 0; i < 4; i++) acc[p][i] = 0ULL;

        __syncthreads();
        #pragma unroll
        for (int pc = 0; pc < 2; pc++) {
            const float* src = Wp0 + (size_t)pc * 16 * 256;
            unsigned dst0 = wbuf_a + (unsigned)(pc * 4096) * 4;
            for (int q = tid; q < 1024; q += NT) {
                int row = q >> 6, col = q & 63;
                CP16(dst0 + (unsigned)(row * 256 + col * 4) * 4,
                     src + row * 256 + col * 4);
            }
            CP_COMMIT();
        }
        for (int c = 0; c < 25; c++) {
            if (c + 1 < 25) CP_WAIT1(); else CP_WAIT0();
            __syncthreads();
            if (c + 2 < 25) {
                const float* src = Wp0 + (size_t)(c + 2) * 16 * 256;
                unsigned dst0 = wbuf_a + (unsigned)(((c + 2) % 3) * 4096) * 4;
                for (int q = tid; q < 1024; q += NT) {
                    int row = q >> 6, col = q & 63;
                    CP16(dst0 + (unsigned)(row * 256 + col * 4) * 4,
                         src + row * 256 + col * 4);
                }
                CP_COMMIT();
            }
            mma_chunk<2, AP, PP>(wbuf + (c % 3) * 4096,
                                 a_sh + r * 8 * AP + c * 16, jb, acc);
        }
        #pragma unroll
        for (int i = 0; i < 2; i++) {
            int j = jb + 64 * i;
            float b0 = __ldg(bp0 + j), b1 = __ldg(bp0 + j + 1);
            #pragma unroll
            for (int p = 0; p < 8; p++) {
                float lo, hi; unpack2(acc[p][i], lo, hi);
                *(float2*)&p_sh[(r * 8 + p) * PP + j] =
                    make_float2(fmaxf(lo + b0, 0.f), fmaxf(hi + b1, 0.f));
            }
        }
        __syncthreads();
    }

    {
        ull acc[8][4];
        #pragma unroll
        for (int p = 0; p < 8; p++)
            #pragma unroll
            for (int i = 0; i < 4; i++) acc[p][i] = 0ULL;

        #pragma unroll
        for (int pc = 0; pc < 2; pc++) {
            const float* src = Wp1 + (size_t)pc * 16 * 256;
            unsigned dst0 = wbuf_a + (unsigned)(pc * 4096) * 4;
            for (int q = tid; q < 1024; q += NT) {
                int row = q >> 6, col = q & 63;
                CP16(dst0 + (unsigned)(row * 256 + col * 4) * 4,
                     src + row * 256 + col * 4);
            }
            CP_COMMIT();
        }
        for (int c = 0; c < 16; c++) {
            if (c + 1 < 16) CP_WAIT1(); else CP_WAIT0();
            __syncthreads();
            if (c + 2 < 16) {
                const float* src = Wp1 + (size_t)(c + 2) * 16 * 256;
                unsigned dst0 = wbuf_a + (unsigned)(((c + 2) % 3) * 4096) * 4;
                for (int q = tid; q < 1024; q += NT) {
                    int row = q >> 6, col = q & 63;
                    CP16(dst0 + (unsigned)(row * 256 + col * 4) * 4,
                         src + row * 256 + col * 4);
                }
                CP_COMMIT();
            }
            mma_chunk<2, PP, PP>(wbuf + (c % 3) * 4096,
                                 p_sh + r * 8 * PP + c * 16, jb, acc);
        }
        #pragma unroll
        for (int i = 0; i < 2; i++) {
            int j = jb + 64 * i;
            float b0 = __ldg(bp1 + j), b1 = __ldg(bp1 + j + 1);
            #pragma unroll
            for (int p = 0; p < 8; p++) {
                float lo, hi; unpack2(acc[p][i], lo, hi);
                *(float2*)&a_sh[(r * 8 + p) * PP + j] =
                    make_float2(fmaxf(lo + b0, 0.f), fmaxf(hi + b1, 0.f));
            }
        }
        __syncthreads();
    }

    {
        int e = tid >> 3, jo = tid & 7;
        float acc = __ldg(bp2 + jo);
        #pragma unroll 8
        for (int k = 0; k < 256; k++)
            acc = fmaf(a_sh[e * PP + k], w2[k * 8 + jo], acc);
        out[(size_t)(e0 + e) * 8 + jo] = tanhf(acc);
    }
}

// ===========================================================================
extern "C" void kernel_launch(void* const* d_in, const int* in_sizes, int n_in,
                              void* d_out, int out_size)
{
    const float* o   = (const float*)d_in[0];
    const float* g   = (const float*)d_in[1];
    const float* Wc  = (const float*)d_in[2];
    const float* bc  = (const float*)d_in[3];
    const float* Wa0 = (const float*)d_in[4];
    const float* ba0 = (const float*)d_in[5];
    const float* Wa1 = (const float*)d_in[6];
    const float* ba1 = (const float*)d_in[7];
    const float* Wp0 = (const float*)d_in[8];
    const float* bp0 = (const float*)d_in[9];
    const float* Wp1 = (const float*)d_in[10];
    const float* bp1 = (const float*)d_in[11];
    const float* Wp2 = (const float*)d_in[12];
    const float* bp2 = (const float*)d_in[13];
    float* out = (float*)d_out;

    int B = in_sizes[0] / 260;

    size_t sm3 = (size_t)(EP * AP + EP * PP + 3 * 16 * 256 + 2048) * sizeof(float);
    cudaFuncSetAttribute(k_main, cudaFuncAttributeMaxDynamicSharedMemorySize, SMEM_MAIN);
    cudaFuncSetAttribute(k_head, cudaFuncAttributeMaxDynamicSharedMemorySize, (int)sm3);

    k_prep<<<464, 256>>>(Wa0, Wa1);
    k_main<<<B / 16, 256, SMEM_MAIN>>>(o, g, Wc, bc, ba0, ba1);
    k_head<<<B / EP, NT, sm3>>>(Wp0, bp0, Wp1, bp1, Wp2, bp2, out);
}

// round 13
// speedup vs baseline: 3.8268x; 1.5223x over previous
#include <cuda_runtime.h>
#include <cuda_fp16.h>
#include <math.h>
#include <stdint.h>

typedef unsigned long long ull;

// ===========================================================================
// Helpers
// ===========================================================================
__device__ __forceinline__ unsigned smem_u32(const void* p) {
    unsigned a;
    asm("{ .reg .u64 t; cvta.to.shared.u64 t, %1; cvt.u32.u64 %0, t; }"
        : "=r"(a) : "l"(p));
    return a;
}
#define CP16(dst_u32, src_ptr) \
    asm volatile("cp.async.cg.shared.global [%0], [%1], 16;" \
                 :: "r"(dst_u32), "l"(src_ptr))
#define CP_COMMIT() asm volatile("cp.async.commit_group;")
#define CP_WAIT1()  asm volatile("cp.async.wait_group 1;")
#define CP_WAIT0()  asm volatile("cp.async.wait_group 0;")

__device__ __forceinline__ void ldsm_x4(unsigned addr, unsigned& r0, unsigned& r1,
                                        unsigned& r2, unsigned& r3) {
    asm volatile("ldmatrix.sync.aligned.m8n8.x4.shared.b16 {%0,%1,%2,%3}, [%4];"
                 : "=r"(r0), "=r"(r1), "=r"(r2), "=r"(r3) : "r"(addr));
}
__device__ __forceinline__ void ldsm_x2(unsigned addr, unsigned& r0, unsigned& r1) {
    asm volatile("ldmatrix.sync.aligned.m8n8.x2.shared.b16 {%0,%1}, [%2];"
                 : "=r"(r0), "=r"(r1) : "r"(addr));
}
// fp16 MMA, fp32 accumulate
__device__ __forceinline__ void mma16816(float* d, unsigned a0, unsigned a1,
                                         unsigned a2, unsigned a3,
                                         unsigned b0, unsigned b1) {
    asm volatile("mma.sync.aligned.m16n8k16.row.col.f32.f16.f16.f32 "
                 "{%0,%1,%2,%3}, {%4,%5,%6,%7}, {%8,%9}, {%0,%1,%2,%3};"
                 : "+f"(d[0]), "+f"(d[1]), "+f"(d[2]), "+f"(d[3])
                 : "r"(a0), "r"(a1), "r"(a2), "r"(a3), "r"(b0), "r"(b1));
}
__device__ __forceinline__ float redsum8(float v) {
    v += __shfl_xor_sync(0xffffffffu, v, 4);
    v += __shfl_xor_sync(0xffffffffu, v, 8);
    v += __shfl_xor_sync(0xffffffffu, v, 16);
    return v;
}
__device__ __forceinline__ unsigned pack_h2(float v0, float v1) {
    __half2 h = __floats2half2_rn(v0, v1);
    return *(unsigned*)&h;
}

// ===========================================================================
// Globals
// ===========================================================================
__device__ float g_ip[65536 * 400];                    // input_pi scratch
__device__ __align__(16) __half W0g[256 * 72];         // Wa0^T fp16, pitch 72
__device__ __align__(16) __half W1g[400 * 264];        // Wa1^T fp16, pitch 264

// ===========================================================================
// Prep: fp16 weight images (n-major, k contiguous)
// ===========================================================================
__global__ void k_prep(const float* __restrict__ Wa0, const float* __restrict__ Wa1) {
    int idx = blockIdx.x * 256 + threadIdx.x;
    if (idx < 16384) {                         // 256 n x 64 k
        int n = idx >> 6, k = idx & 63;
        float v = (k < 50) ? Wa0[k * 256 + n] : 0.f;
        W0g[n * 72 + k] = __float2half(v);
    } else if (idx < 16384 + 102400) {         // 400 n x 256 k
        int t = idx - 16384;
        int k = t / 400, n = t % 400;
        W1g[n * 264 + k] = __float2half(Wa1[k * 400 + n]);
    }
}

// ===========================================================================
// Kernel 1: attention + gather + a0 + a1 + object-sum -> g_ip (B x 400)
// Block = 16 elements (M=128), 256 threads / 8 warps, warp w owns rows
// [16w,16w+16) = elements 2w,2w+1. Single-pass fp16 HMMA; GEMM1 outputs
// re-used directly as GEMM2 A fragments (register fusion). 2 blocks/SM.
// ===========================================================================
#define OFF_B1  0          // B1 double buffer: 2 x 21120
#define OFF_A0  42240      // A0: 128 x 144B
#define OFF_BA1 60672      // 400 f
#define OFF_BA0 62272      // 256 f
#define OFF_B0  63296      // B0 resident: 256 x 144B
#define SMEM_MAIN 100160

__global__ __launch_bounds__(256, 2)
void k_main(const float* __restrict__ o,   const float* __restrict__ g,
            const float* __restrict__ Wc,  const float* __restrict__ bc,
            const float* __restrict__ ba0, const float* __restrict__ ba1)
{
    extern __shared__ __align__(1024) unsigned char smem[];
    const unsigned sbase = smem_u32(smem);
    const int tid = threadIdx.x, lane = tid & 31, warp = tid >> 5;
    const int e0 = blockIdx.x * 16;

    // ---- issue B0 load immediately (region disjoint from staging) : G1 ----
    for (int q = tid; q < 2304; q += 256)
        CP16(sbase + OFF_B0 + q * 16, (const char*)W0g + q * 16);
    CP_COMMIT();

    // ---- biases ----
    float* ba0_sh = (float*)(smem + OFF_BA0);
    float* ba1_sh = (float*)(smem + OFF_BA1);
    ba0_sh[tid] = ba0[tid];
    for (int i = tid; i < 400; i += 256) ba1_sh[i] = ba1[i];

    // ---- phase 0: staging + attention + scaled-x (A0 fp16) ----
    {
        float* o_sh = (float*)(smem + 0);         // 16 x 260 = 16640B
        float* g_sh = (float*)(smem + 16640);     // 16 x 100 = 6400B
        float* att  = (float*)(smem + 23040);     // 16 x 52  = 3328B
        for (int i = tid; i < 16 * 260; i += 256) o_sh[i] = o[(size_t)e0 * 260 + i];
        for (int i = tid; i < 1600; i += 256) g_sh[i] = g[(size_t)e0 * 100 + i];
        __syncthreads();

        // attention: 16 x 50 sigmoid (Wc via L2, no smem copy)
        for (int idx = tid; idx < 800; idx += 256) {
            int e = idx / 50, j = idx % 50;
            float acc = bc[j];
            #pragma unroll 4
            for (int k = 0; k < 100; k++)
                acc = fmaf(g_sh[e * 100 + k], __ldg(Wc + k * 50 + j), acc);
            att[e * 52 + j] = 1.0f / (1.0f + expf(-acc));
        }
        __syncthreads();

        // A0[row][k], row = e*8+n, k=d (0..63, zero-pad 50..63), pitch 72 fp16
        for (int idx = tid; idx < 4096; idx += 256) {
            int row = idx >> 5, kp = idx & 31;
            int e = row >> 3, n = row & 7;
            float v[2];
            #pragma unroll
            for (int t = 0; t < 2; t++) {
                int d = kp * 2 + t;
                float x = 0.f;
                if (d < 50) {
                    int gi;
                    if (d < 10)       gi = d;
                    else if (d < 20)  gi = 120 + d;
                    else if (d < 35)  gi = 15 * n + d - 10;
                    else              gi = 15 * n + d + 105;
                    x = o_sh[e * 260 + gi] * att[e * 52 + d];
                }
                v[t] = x;
            }
            *(unsigned*)(smem + OFF_A0 + (unsigned)(row * 72 + kp * 2) * 2) =
                pack_h2(v[0], v[1]);
        }
    }
    __syncthreads();   // A0 + staging done -> B1 region reusable

    // ---- issue B1 chunk 0 : G2 ----
    for (int q = tid; q < 1320; q += 256)
        CP16(sbase + OFF_B1 + q * 16, (const char*)W1g + q * 16);
    CP_COMMIT();

    CP_WAIT1();        // B0 (G1) done; G2 in flight
    __syncthreads();   // B0 visible to all

    // per-lane ldmatrix address components
    const unsigned aoffA = (unsigned)(((warp * 16 + (lane & 15)) * 72 + ((lane & 16) >> 1)) * 2);
    const int bg = lane >> 3;
    const unsigned brow0 = (unsigned)((bg >> 1) * 8 + (lane & 7));
    const unsigned bk0   = (unsigned)((bg & 1) * 16);
    const unsigned boff1 = (unsigned)(brow0 * 528 + bk0);
    const unsigned boffS = (unsigned)((32 + (lane & 7)) * 528 + ((lane >> 3) & 1) * 16);

    // GEMM2 A fragments, produced by GEMM1 (register fusion)
    unsigned aH1[16][4];

    // ================= GEMM1: h = relu(x @ Wa0 + ba0) -> regs =================
    {
        const unsigned b0H = sbase + OFF_B0;
        #pragma unroll
        for (int c = 0; c < 4; c++) {           // n-chunks of 64
            float d[8][4];
            #pragma unroll
            for (int t = 0; t < 8; t++)
                #pragma unroll
                for (int i = 0; i < 4; i++) d[t][i] = 0.f;

            #pragma unroll
            for (int s = 0; s < 4; s++) {
                unsigned a[4];
                ldsm_x4(sbase + OFF_A0 + aoffA + s * 32, a[0], a[1], a[2], a[3]);
                unsigned bh[4][4];
                #pragma unroll
                for (int pr = 0; pr < 4; pr++) {
                    unsigned bo = (unsigned)((c * 64 + pr * 16 + brow0) * 144) + bk0 + s * 32;
                    ldsm_x4(b0H + bo, bh[pr][0], bh[pr][1], bh[pr][2], bh[pr][3]);
                }
                #pragma unroll
                for (int pr = 0; pr < 4; pr++) {
                    mma16816(d[2 * pr],     a[0], a[1], a[2], a[3], bh[pr][0], bh[pr][1]);
                    mma16816(d[2 * pr + 1], a[0], a[1], a[2], a[3], bh[pr][2], bh[pr][3]);
                }
            }

            // epilogue: bias + relu + fp16 pack -> GEMM2 A fragments
            #pragma unroll
            for (int u = 0; u < 4; u++) {
                const int s = 4 * c + u;
                int j0 = 64 * c + 16 * u + 2 * (lane & 3);
                int j1 = j0 + 8;
                float b00 = ba0_sh[j0], b01 = ba0_sh[j0 + 1];
                float b10 = ba0_sh[j1], b11 = ba0_sh[j1 + 1];
                aH1[s][0] = pack_h2(fmaxf(d[2*u][0] + b00, 0.f), fmaxf(d[2*u][1] + b01, 0.f));
                aH1[s][1] = pack_h2(fmaxf(d[2*u][2] + b00, 0.f), fmaxf(d[2*u][3] + b01, 0.f));
                aH1[s][2] = pack_h2(fmaxf(d[2*u+1][0] + b10, 0.f), fmaxf(d[2*u+1][1] + b11, 0.f));
                aH1[s][3] = pack_h2(fmaxf(d[2*u+1][2] + b10, 0.f), fmaxf(d[2*u+1][3] + b11, 0.f));
            }
        }
    }

    // ---- issue B1 chunk 1 : G3 ----
    for (int q = tid; q < 1320; q += 256)
        CP16(sbase + OFF_B1 + 21120 + q * 16, (const char*)W1g + 21120 + q * 16);
    CP_COMMIT();

    // ============ GEMM2: input_pi = sum_obj relu(h @ Wa1 + ba1) ============
    // 10 n-chunks of 40; A entirely in registers.
    for (int c = 0; c < 10; c++) {
        if (c < 9) CP_WAIT1(); else CP_WAIT0();
        __syncthreads();                         // chunk c visible everywhere

        const unsigned bufH = sbase + OFF_B1 + (c & 1) * 21120;
        float d[5][4];
        #pragma unroll
        for (int t = 0; t < 5; t++)
            #pragma unroll
            for (int i = 0; i < 4; i++) d[t][i] = 0.f;

        #pragma unroll
        for (int s = 0; s < 16; s++) {
            unsigned bh0[4], bh1[4], bhS[2];
            ldsm_x4(bufH + boff1 + s * 32, bh0[0], bh0[1], bh0[2], bh0[3]);
            ldsm_x4(bufH + 16 * 528 + boff1 + s * 32, bh1[0], bh1[1], bh1[2], bh1[3]);
            ldsm_x2(bufH + boffS + s * 32, bhS[0], bhS[1]);
            mma16816(d[0], aH1[s][0], aH1[s][1], aH1[s][2], aH1[s][3], bh0[0], bh0[1]);
            mma16816(d[1], aH1[s][0], aH1[s][1], aH1[s][2], aH1[s][3], bh0[2], bh0[3]);
            mma16816(d[2], aH1[s][0], aH1[s][1], aH1[s][2], aH1[s][3], bh1[0], bh1[1]);
            mma16816(d[3], aH1[s][0], aH1[s][1], aH1[s][2], aH1[s][3], bh1[2], bh1[3]);
            mma16816(d[4], aH1[s][0], aH1[s][1], aH1[s][2], aH1[s][3], bhS[0], bhS[1]);
        }

        // epilogue: bias + relu + 8-row object-sum -> g_ip
        #pragma unroll
        for (int t = 0; t < 5; t++) {
            int c0 = c * 40 + t * 8 + (lane & 3) * 2;
            float b0 = ba1_sh[c0], b1 = ba1_sh[c0 + 1];
            float s00 = redsum8(fmaxf(d[t][0] + b0, 0.f));
            float s01 = redsum8(fmaxf(d[t][1] + b1, 0.f));
            float s10 = redsum8(fmaxf(d[t][2] + b0, 0.f));
            float s11 = redsum8(fmaxf(d[t][3] + b1, 0.f));
            if (lane < 4)
                *(float2*)&g_ip[(size_t)(e0 + 2 * warp) * 400 + c0] = make_float2(s00, s01);
            else if (lane < 8)
                *(float2*)&g_ip[(size_t)(e0 + 2 * warp + 1) * 400 + c0] = make_float2(s10, s11);
        }

        __syncthreads();                         // all reads of buf (c&1) done
        if (c + 2 < 10) {                        // refill just-freed buffer
            for (int q = tid; q < 1320; q += 256)
                CP16(sbase + OFF_B1 + (c & 1) * 21120 + q * 16,
                     (const char*)W1g + (size_t)(c + 2) * 21120 + q * 16);
            CP_COMMIT();
        }
    }
}

// ===========================================================================
// Kernel 2: policy head (round-8 SIMT FFMA2 version, unchanged)
// ===========================================================================
#define EP  64
#define AP  400
#define PP  256
#define NT  512

__device__ __forceinline__ ull packdup(float v) {
    ull r; asm("mov.b64 %0, {%1,%1};" : "=l"(r) : "f"(v)); return r;
}
__device__ __forceinline__ void unpack2(ull v, float& lo, float& hi) {
    asm("mov.b64 {%0,%1}, %2;" : "=f"(lo), "=f"(hi) : "l"(v));
}
#define FMA2(d, a, b) asm("fma.rn.f32x2 %0, %1, %2, %0;" : "+l"(d) : "l"(a), "l"(b))

template<int NC, int APITCH, int WPITCH>
__device__ __forceinline__ void mma_chunk(
    const float* __restrict__ wb, const float* __restrict__ abase,
    int jb, ull (&acc)[8][4])
{
    #pragma unroll
    for (int kk2 = 0; kk2 < 8; kk2++) {
        ull a2[8];
        #pragma unroll
        for (int p = 0; p < 8; p++)
            a2[p] = *(const ull*)(abase + p * APITCH + 2 * kk2);
        #pragma unroll
        for (int dk = 0; dk < 2; dk++) {
            ull ap[8];
            #pragma unroll
            for (int p = 0; p < 8; p++) {
                float lo, hi; unpack2(a2[p], lo, hi);
                ap[p] = packdup(dk ? hi : lo);
            }
            #pragma unroll
            for (int i = 0; i < NC; i++) {
                ull b = *(const ull*)(wb + (2 * kk2 + dk) * WPITCH + jb + 64 * i);
                #pragma unroll
                for (int p = 0; p < 8; p++) FMA2(acc[p][i], ap[p], b);
            }
        }
    }
}

__global__ __launch_bounds__(NT, 1) void k_head(
    const float* __restrict__ Wp0, const float* __restrict__ bp0,
    const float* __restrict__ Wp1, const float* __restrict__ bp1,
    const float* __restrict__ Wp2, const float* __restrict__ bp2,
    float* __restrict__ out)
{
    extern __shared__ float smf[];
    float* a_sh = smf;
    float* p_sh = a_sh + EP * AP;
    float* wbuf = p_sh + EP * PP;
    float* w2   = wbuf + 3 * 16 * 256;
    const unsigned wbuf_a = smem_u32(wbuf);

    const int tid = threadIdx.x;
    const int e0  = blockIdx.x * EP;
    for (int i = tid; i < EP * 400; i += NT) a_sh[i] = g_ip[(size_t)e0 * 400 + i];
    for (int i = tid; i < 2048; i += NT) w2[i] = Wp2[i];

    const int tx = tid & 31;
    const int r  = (tid >> 5) & 7;
    const int cz = tid >> 8;
    const int jb = tx * 2 + 128 * cz;

    {
        ull acc[8][4];
        #pragma unroll
        for (int p = 0; p < 8; p++)
            #pragma unroll
            for (int i = 0; i < 4; i++) acc[p][i] = 0ULL;

        __syncthreads();
        #pragma unroll
        for (int pc = 0; pc < 2; pc++) {
            const float* src = Wp0 + (size_t)pc * 16 * 256;
            unsigned dst0 = wbuf_a + (unsigned)(pc * 4096) * 4;
            for (int q = tid; q < 1024; q += NT) {
                int row = q >> 6, col = q & 63;
                CP16(dst0 + (unsigned)(row * 256 + col * 4) * 4,
                     src + row * 256 + col * 4);
            }
            CP_COMMIT();
        }
        for (int c = 0; c < 25; c++) {
            if (c + 1 < 25) CP_WAIT1(); else CP_WAIT0();
            __syncthreads();
            if (c + 2 < 25) {
                const float* src = Wp0 + (size_t)(c + 2) * 16 * 256;
                unsigned dst0 = wbuf_a + (unsigned)(((c + 2) % 3) * 4096) * 4;
                for (int q = tid; q < 1024; q += NT) {
                    int row = q >> 6, col = q & 63;
                    CP16(dst0 + (unsigned)(row * 256 + col * 4) * 4,
                         src + row * 256 + col * 4);
                }
                CP_COMMIT();
            }
            mma_chunk<2, AP, PP>(wbuf + (c % 3) * 4096,
                                 a_sh + r * 8 * AP + c * 16, jb, acc);
        }
        #pragma unroll
        for (int i = 0; i < 2; i++) {
            int j = jb + 64 * i;
            float b0 = __ldg(bp0 + j), b1 = __ldg(bp0 + j + 1);
            #pragma unroll
            for (int p = 0; p < 8; p++) {
                float lo, hi; unpack2(acc[p][i], lo, hi);
                *(float2*)&p_sh[(r * 8 + p) * PP + j] =
                    make_float2(fmaxf(lo + b0, 0.f), fmaxf(hi + b1, 0.f));
            }
        }
        __syncthreads();
    }

    {
        ull acc[8][4];
        #pragma unroll
        for (int p = 0; p < 8; p++)
            #pragma unroll
            for (int i = 0; i < 4; i++) acc[p][i] = 0ULL;

        #pragma unroll
        for (int pc = 0; pc < 2; pc++) {
            const float* src = Wp1 + (size_t)pc * 16 * 256;
            unsigned dst0 = wbuf_a + (unsigned)(pc * 4096) * 4;
            for (int q = tid; q < 1024; q += NT) {
                int row = q >> 6, col = q & 63;
                CP16(dst0 + (unsigned)(row * 256 + col * 4) * 4,
                     src + row * 256 + col * 4);
            }
            CP_COMMIT();
        }
        for (int c = 0; c < 16; c++) {
            if (c + 1 < 16) CP_WAIT1(); else CP_WAIT0();
            __syncthreads();
            if (c + 2 < 16) {
                const float* src = Wp1 + (size_t)(c + 2) * 16 * 256;
                unsigned dst0 = wbuf_a + (unsigned)(((c + 2) % 3) * 4096) * 4;
                for (int q = tid; q < 1024; q += NT) {
                    int row = q >> 6, col = q & 63;
                    CP16(dst0 + (unsigned)(row * 256 + col * 4) * 4,
                         src + row * 256 + col * 4);
                }
                CP_COMMIT();
            }
            mma_chunk<2, PP, PP>(wbuf + (c % 3) * 4096,
                                 p_sh + r * 8 * PP + c * 16, jb, acc);
        }
        #pragma unroll
        for (int i = 0; i < 2; i++) {
            int j = jb + 64 * i;
            float b0 = __ldg(bp1 + j), b1 = __ldg(bp1 + j + 1);
            #pragma unroll
            for (int p = 0; p < 8; p++) {
                float lo, hi; unpack2(acc[p][i], lo, hi);
                *(float2*)&a_sh[(r * 8 + p) * PP + j] =
                    make_float2(fmaxf(lo + b0, 0.f), fmaxf(hi + b1, 0.f));
            }
        }
        __syncthreads();
    }

    {
        int e = tid >> 3, jo = tid & 7;
        float acc = __ldg(bp2 + jo);
        #pragma unroll 8
        for (int k = 0; k < 256; k++)
            acc = fmaf(a_sh[e * PP + k], w2[k * 8 + jo], acc);
        out[(size_t)(e0 + e) * 8 + jo] = tanhf(acc);
    }
}

// ===========================================================================
extern "C" void kernel_launch(void* const* d_in, const int* in_sizes, int n_in,
                              void* d_out, int out_size)
{
    const float* o   = (const float*)d_in[0];
    const float* g   = (const float*)d_in[1];
    const float* Wc  = (const float*)d_in[2];
    const float* bc  = (const float*)d_in[3];
    const float* Wa0 = (const float*)d_in[4];
    const float* ba0 = (const float*)d_in[5];
    const float* Wa1 = (const float*)d_in[6];
    const float* ba1 = (const float*)d_in[7];
    const float* Wp0 = (const float*)d_in[8];
    const float* bp0 = (const float*)d_in[9];
    const float* Wp1 = (const float*)d_in[10];
    const float* bp1 = (const float*)d_in[11];
    const float* Wp2 = (const float*)d_in[12];
    const float* bp2 = (const float*)d_in[13];
    float* out = (float*)d_out;

    int B = in_sizes[0] / 260;

    size_t sm3 = (size_t)(EP * AP + EP * PP + 3 * 16 * 256 + 2048) * sizeof(float);
    cudaFuncSetAttribute(k_main, cudaFuncAttributeMaxDynamicSharedMemorySize, SMEM_MAIN);
    cudaFuncSetAttribute(k_head, cudaFuncAttributeMaxDynamicSharedMemorySize, (int)sm3);

    k_prep<<<464, 256>>>(Wa0, Wa1);
    k_main<<<B / 16, 256, SMEM_MAIN>>>(o, g, Wc, bc, ba0, ba1);
    k_head<<<B / EP, NT, sm3>>>(Wp0, bp0, Wp1, bp1, Wp2, bp2, out);
}

// round 14
// speedup vs baseline: 5.8886x; 1.5388x over previous
#include <cuda_runtime.h>
#include <cuda_fp16.h>
#include <math.h>
#include <stdint.h>

// ===========================================================================
// Helpers
// ===========================================================================
__device__ __forceinline__ unsigned smem_u32(const void* p) {
    unsigned a;
    asm("{ .reg .u64 t; cvta.to.shared.u64 t, %1; cvt.u32.u64 %0, t; }"
        : "=r"(a) : "l"(p));
    return a;
}
#define CP16(dst_u32, src_ptr) \
    asm volatile("cp.async.cg.shared.global [%0], [%1], 16;" \
                 :: "r"(dst_u32), "l"(src_ptr))
#define CP_COMMIT() asm volatile("cp.async.commit_group;")
#define CP_WAIT1()  asm volatile("cp.async.wait_group 1;")
#define CP_WAIT0()  asm volatile("cp.async.wait_group 0;")

__device__ __forceinline__ void ldsm_x4(unsigned addr, unsigned& r0, unsigned& r1,
                                        unsigned& r2, unsigned& r3) {
    asm volatile("ldmatrix.sync.aligned.m8n8.x4.shared.b16 {%0,%1,%2,%3}, [%4];"
                 : "=r"(r0), "=r"(r1), "=r"(r2), "=r"(r3) : "r"(addr));
}
__device__ __forceinline__ void ldsm_x2(unsigned addr, unsigned& r0, unsigned& r1) {
    asm volatile("ldmatrix.sync.aligned.m8n8.x2.shared.b16 {%0,%1}, [%2];"
                 : "=r"(r0), "=r"(r1) : "r"(addr));
}
// fp16 MMA, fp32 accumulate
__device__ __forceinline__ void mma16816(float* d, unsigned a0, unsigned a1,
                                         unsigned a2, unsigned a3,
                                         unsigned b0, unsigned b1) {
    asm volatile("mma.sync.aligned.m16n8k16.row.col.f32.f16.f16.f32 "
                 "{%0,%1,%2,%3}, {%4,%5,%6,%7}, {%8,%9}, {%0,%1,%2,%3};"
                 : "+f"(d[0]), "+f"(d[1]), "+f"(d[2]), "+f"(d[3])
                 : "r"(a0), "r"(a1), "r"(a2), "r"(a3), "r"(b0), "r"(b1));
}
__device__ __forceinline__ float redsum8(float v) {
    v += __shfl_xor_sync(0xffffffffu, v, 4);
    v += __shfl_xor_sync(0xffffffffu, v, 8);
    v += __shfl_xor_sync(0xffffffffu, v, 16);
    return v;
}
__device__ __forceinline__ unsigned pack_h2(float v0, float v1) {
    __half2 h = __floats2half2_rn(v0, v1);
    return *(unsigned*)&h;
}

// ===========================================================================
// Globals
// ===========================================================================
__device__ __align__(16) __half g_iph[65536 * 400];     // input_pi (fp16)
__device__ __align__(16) __half W0g[256 * 72];          // Wa0^T fp16, pitch 72
__device__ __align__(16) __half W1g[400 * 264];         // Wa1^T fp16, pitch 264
__device__ __align__(16) __half Wp0g[256 * 408];        // Wp0^T fp16, pitch 408
__device__ __align__(16) __half Wp1g[256 * 264];        // Wp1^T fp16, pitch 264
__device__ __align__(16) __half Wp2g[8 * 264];          // Wp2^T fp16, pitch 264

// ===========================================================================
// Prep: fp16 weight images (n-major, k contiguous)
// ===========================================================================
__global__ void k_prep(const float* __restrict__ Wa0, const float* __restrict__ Wa1,
                       const float* __restrict__ Wp0, const float* __restrict__ Wp1,
                       const float* __restrict__ Wp2) {
    int idx = blockIdx.x * 256 + threadIdx.x;
    if (idx < 16384) {                                   // W0: 256n x 64k
        int n = idx >> 6, k = idx & 63;
        float v = (k < 50) ? Wa0[k * 256 + n] : 0.f;
        W0g[n * 72 + k] = __float2half(v);
    } else if (idx < 119184 - 400) {                     // W1: 400n x 256k
        int t = idx - 16384;                             // t < 102400
        int k = t / 400, n = t % 400;
        W1g[n * 264 + k] = __float2half(Wa1[k * 400 + n]);
    } else if (idx < 118784 + 102400) {                  // Wp0: 256n x 400k
        int t = idx - 118784;
        int n = t & 255, k = t >> 8;                     // k < 400
        Wp0g[n * 408 + k] = __float2half(Wp0[k * 256 + n]);
    } else if (idx < 221184 + 65536) {                   // Wp1: 256n x 256k
        int t = idx - 221184;
        int n = t & 255, k = t >> 8;
        Wp1g[n * 264 + k] = __float2half(Wp1[k * 256 + n]);
    } else if (idx < 286720 + 2048) {                    // Wp2: 8n x 256k
        int t = idx - 286720;
        int n = t & 7, k = t >> 3;
        Wp2g[n * 264 + k] = __float2half(Wp2[k * 8 + n]);
    }
}

// ===========================================================================
// Kernel 1: attention + gather + a0 + a1 + object-sum -> g_iph (B x 400 fp16)
// Block = 16 elements (M=128), 256 threads / 8 warps. fp16 HMMA; GEMM1
// outputs re-used directly as GEMM2 A fragments. 2 blocks/SM.
// ===========================================================================
#define OFF_B1  0          // B1 double buffer: 2 x 21120
#define OFF_A0  42240      // A0: 128 x 144B
#define OFF_BA1 60672      // 400 f
#define OFF_BA0 62272      // 256 f
#define OFF_B0  63296      // B0 resident: 256 x 144B
#define SMEM_MAIN 100160

__global__ __launch_bounds__(256, 2)
void k_main(const float* __restrict__ o,   const float* __restrict__ g,
            const float* __restrict__ Wc,  const float* __restrict__ bc,
            const float* __restrict__ ba0, const float* __restrict__ ba1)
{
    extern __shared__ __align__(1024) unsigned char smem[];
    const unsigned sbase = smem_u32(smem);
    const int tid = threadIdx.x, lane = tid & 31, warp = tid >> 5;
    const int e0 = blockIdx.x * 16;

    // ---- issue B0 load immediately : G1 ----
    for (int q = tid; q < 2304; q += 256)
        CP16(sbase + OFF_B0 + q * 16, (const char*)W0g + q * 16);
    CP_COMMIT();

    // ---- biases ----
    float* ba0_sh = (float*)(smem + OFF_BA0);
    float* ba1_sh = (float*)(smem + OFF_BA1);
    ba0_sh[tid] = ba0[tid];
    for (int i = tid; i < 400; i += 256) ba1_sh[i] = ba1[i];

    // ---- phase 0: staging + attention + scaled-x (A0 fp16) ----
    {
        float* o_sh = (float*)(smem + 0);         // 16 x 260
        float* g_sh = (float*)(smem + 16640);     // 16 x 100
        float* att  = (float*)(smem + 23040);     // 16 x 52
        for (int i = tid; i < 16 * 260; i += 256) o_sh[i] = o[(size_t)e0 * 260 + i];
        for (int i = tid; i < 1600; i += 256) g_sh[i] = g[(size_t)e0 * 100 + i];
        __syncthreads();

        for (int idx = tid; idx < 800; idx += 256) {
            int e = idx / 50, j = idx % 50;
            float acc = bc[j];
            #pragma unroll 4
            for (int k = 0; k < 100; k++)
                acc = fmaf(g_sh[e * 100 + k], __ldg(Wc + k * 50 + j), acc);
            att[e * 52 + j] = 1.0f / (1.0f + expf(-acc));
        }
        __syncthreads();

        for (int idx = tid; idx < 4096; idx += 256) {
            int row = idx >> 5, kp = idx & 31;
            int e = row >> 3, n = row & 7;
            float v[2];
            #pragma unroll
            for (int t = 0; t < 2; t++) {
                int d = kp * 2 + t;
                float x = 0.f;
                if (d < 50) {
                    int gi;
                    if (d < 10)       gi = d;
                    else if (d < 20)  gi = 120 + d;
                    else if (d < 35)  gi = 15 * n + d - 10;
                    else              gi = 15 * n + d + 105;
                    x = o_sh[e * 260 + gi] * att[e * 52 + d];
                }
                v[t] = x;
            }
            *(unsigned*)(smem + OFF_A0 + (unsigned)(row * 72 + kp * 2) * 2) =
                pack_h2(v[0], v[1]);
        }
    }
    __syncthreads();

    // ---- issue B1 chunk 0 : G2 ----
    for (int q = tid; q < 1320; q += 256)
        CP16(sbase + OFF_B1 + q * 16, (const char*)W1g + q * 16);
    CP_COMMIT();

    CP_WAIT1();
    __syncthreads();

    const unsigned aoffA = (unsigned)(((warp * 16 + (lane & 15)) * 72 + ((lane & 16) >> 1)) * 2);
    const int bg = lane >> 3;
    const unsigned brow0 = (unsigned)((bg >> 1) * 8 + (lane & 7));
    const unsigned bk0   = (unsigned)((bg & 1) * 16);
    const unsigned boff1 = (unsigned)(brow0 * 528 + bk0);
    const unsigned boffS = (unsigned)((32 + (lane & 7)) * 528 + ((lane >> 3) & 1) * 16);

    unsigned aH1[16][4];

    // ================= GEMM1: h = relu(x @ Wa0 + ba0) -> regs =================
    {
        const unsigned b0H = sbase + OFF_B0;
        #pragma unroll
        for (int c = 0; c < 4; c++) {
            float d[8][4];
            #pragma unroll
            for (int t = 0; t < 8; t++)
                #pragma unroll
                for (int i = 0; i < 4; i++) d[t][i] = 0.f;

            #pragma unroll
            for (int s = 0; s < 4; s++) {
                unsigned a[4];
                ldsm_x4(sbase + OFF_A0 + aoffA + s * 32, a[0], a[1], a[2], a[3]);
                unsigned bh[4][4];
                #pragma unroll
                for (int pr = 0; pr < 4; pr++) {
                    unsigned bo = (unsigned)((c * 64 + pr * 16 + brow0) * 144) + bk0 + s * 32;
                    ldsm_x4(b0H + bo, bh[pr][0], bh[pr][1], bh[pr][2], bh[pr][3]);
                }
                #pragma unroll
                for (int pr = 0; pr < 4; pr++) {
                    mma16816(d[2 * pr],     a[0], a[1], a[2], a[3], bh[pr][0], bh[pr][1]);
                    mma16816(d[2 * pr + 1], a[0], a[1], a[2], a[3], bh[pr][2], bh[pr][3]);
                }
            }

            #pragma unroll
            for (int u = 0; u < 4; u++) {
                const int s = 4 * c + u;
                int j0 = 64 * c + 16 * u + 2 * (lane & 3);
                int j1 = j0 + 8;
                float b00 = ba0_sh[j0], b01 = ba0_sh[j0 + 1];
                float b10 = ba0_sh[j1], b11 = ba0_sh[j1 + 1];
                aH1[s][0] = pack_h2(fmaxf(d[2*u][0] + b00, 0.f), fmaxf(d[2*u][1] + b01, 0.f));
                aH1[s][1] = pack_h2(fmaxf(d[2*u][2] + b00, 0.f), fmaxf(d[2*u][3] + b01, 0.f));
                aH1[s][2] = pack_h2(fmaxf(d[2*u+1][0] + b10, 0.f), fmaxf(d[2*u+1][1] + b11, 0.f));
                aH1[s][3] = pack_h2(fmaxf(d[2*u+1][2] + b10, 0.f), fmaxf(d[2*u+1][3] + b11, 0.f));
            }
        }
    }

    // ---- issue B1 chunk 1 : G3 ----
    for (int q = tid; q < 1320; q += 256)
        CP16(sbase + OFF_B1 + 21120 + q * 16, (const char*)W1g + 21120 + q * 16);
    CP_COMMIT();

    // ============ GEMM2: input_pi = sum_obj relu(h @ Wa1 + ba1) ============
    for (int c = 0; c < 10; c++) {
        if (c < 9) CP_WAIT1(); else CP_WAIT0();
        __syncthreads();

        const unsigned bufH = sbase + OFF_B1 + (c & 1) * 21120;
        float d[5][4];
        #pragma unroll
        for (int t = 0; t < 5; t++)
            #pragma unroll
            for (int i = 0; i < 4; i++) d[t][i] = 0.f;

        #pragma unroll
        for (int s = 0; s < 16; s++) {
            unsigned bh0[4], bh1[4], bhS[2];
            ldsm_x4(bufH + boff1 + s * 32, bh0[0], bh0[1], bh0[2], bh0[3]);
            ldsm_x4(bufH + 16 * 528 + boff1 + s * 32, bh1[0], bh1[1], bh1[2], bh1[3]);
            ldsm_x2(bufH + boffS + s * 32, bhS[0], bhS[1]);
            mma16816(d[0], aH1[s][0], aH1[s][1], aH1[s][2], aH1[s][3], bh0[0], bh0[1]);
            mma16816(d[1], aH1[s][0], aH1[s][1], aH1[s][2], aH1[s][3], bh0[2], bh0[3]);
            mma16816(d[2], aH1[s][0], aH1[s][1], aH1[s][2], aH1[s][3], bh1[0], bh1[1]);
            mma16816(d[3], aH1[s][0], aH1[s][1], aH1[s][2], aH1[s][3], bh1[2], bh1[3]);
            mma16816(d[4], aH1[s][0], aH1[s][1], aH1[s][2], aH1[s][3], bhS[0], bhS[1]);
        }

        // epilogue: bias + relu + object-sum -> g_iph (fp16)
        #pragma unroll
        for (int t = 0; t < 5; t++) {
            int c0 = c * 40 + t * 8 + (lane & 3) * 2;
            float b0 = ba1_sh[c0], b1 = ba1_sh[c0 + 1];
            float s00 = redsum8(fmaxf(d[t][0] + b0, 0.f));
            float s01 = redsum8(fmaxf(d[t][1] + b1, 0.f));
            float s10 = redsum8(fmaxf(d[t][2] + b0, 0.f));
            float s11 = redsum8(fmaxf(d[t][3] + b1, 0.f));
            if (lane < 4)
                *(unsigned*)&g_iph[(size_t)(e0 + 2 * warp) * 400 + c0] = pack_h2(s00, s01);
            else if (lane < 8)
                *(unsigned*)&g_iph[(size_t)(e0 + 2 * warp + 1) * 400 + c0] = pack_h2(s10, s11);
        }

        __syncthreads();
        if (c + 2 < 10) {
            for (int q = tid; q < 1320; q += 256)
                CP16(sbase + OFF_B1 + (c & 1) * 21120 + q * 16,
                     (const char*)W1g + (size_t)(c + 2) * 21120 + q * 16);
            CP_COMMIT();
        }
    }
}

// ===========================================================================
// Kernel 2: policy head (fp16 HMMA, register-fused p0->p1->p2)
// Block = 128 elements (M=128), 256 threads / 8 warps; warp w owns rows
// [16w,16w+16). p and q never touch smem (D-frag == A-frag identity).
// ===========================================================================
#define HOFF_A0  0          // ip tile: 128 x 816B (pitch 408 halves)
#define HOFF_W0  104448     // Wp0/Wp1 double buffer: 2 x 26112
#define HOFF_W2  156672     // Wp2 resident: 8 x 528B
#define HOFF_BP0 160896
#define HOFF_BP1 161920
#define HOFF_BP2 162944
#define SMEM_HEAD 162976

__global__ __launch_bounds__(256, 1)
void k_head(const float* __restrict__ bp0, const float* __restrict__ bp1,
            const float* __restrict__ bp2, float* __restrict__ out)
{
    extern __shared__ __align__(1024) unsigned char smem[];
    const unsigned sbase = smem_u32(smem);
    const int tid = threadIdx.x, lane = tid & 31, warp = tid >> 5;
    const int e0 = blockIdx.x * 128;

    // ---- G1: A0 (ip fp16, pitch 408) + Wp2 image ----
    for (int q = tid; q < 6400; q += 256) {
        int row = q / 50, col = q % 50;
        CP16(sbase + HOFF_A0 + (unsigned)(row * 816 + col * 16),
             (const char*)(g_iph + (size_t)(e0 + row) * 400) + col * 16);
    }
    for (int q = tid; q < 264; q += 256)
        CP16(sbase + HOFF_W2 + q * 16, (const char*)Wp2g + q * 16);
    CP_COMMIT();

    // ---- biases ----
    float* bp0_sh = (float*)(smem + HOFF_BP0);
    float* bp1_sh = (float*)(smem + HOFF_BP1);
    float* bp2_sh = (float*)(smem + HOFF_BP2);
    bp0_sh[tid] = bp0[tid];
    bp1_sh[tid] = bp1[tid];
    if (tid < 8) bp2_sh[tid] = bp2[tid];

    // ---- G2/G3: Wp0 chunks 0,1 (32 n-rows each, pitch 816B) ----
    #pragma unroll
    for (int pc = 0; pc < 2; pc++) {
        for (int q = tid; q < 1600; q += 256) {
            int row = q / 50, col = q % 50;
            CP16(sbase + HOFF_W0 + (unsigned)(pc * 26112 + row * 816 + col * 16),
                 (const char*)Wp0g + (size_t)(pc * 32 + row) * 816 + col * 16);
        }
        CP_COMMIT();
    }

    // per-lane ldmatrix address components
    const unsigned aoffH = (unsigned)((warp * 16 + (lane & 15)) * 816 + ((lane & 16) >> 1) * 2);
    const int bg = lane >> 3;
    const unsigned brow0 = (unsigned)((bg >> 1) * 8 + (lane & 7));
    const unsigned bk0   = (unsigned)((bg & 1) * 16);
    const unsigned boffW = brow0 * 816 + bk0;      // Wp0 (pitch 816B)
    const unsigned boffP = brow0 * 528 + bk0;      // Wp1 (pitch 528B)
    const unsigned boffS = (unsigned)((lane & 7) * 528 + ((lane >> 3) & 1) * 16);  // Wp2

    unsigned aP1[16][4];    // p fragments (A of GEMM p1)
    unsigned aP2[16][4];    // q fragments (A of GEMM p2)

    // ================= p0: p = relu(ip @ Wp0 + bp0) -> regs =================
    for (int c = 0; c < 8; c++) {               // n-chunks of 32
        if (c < 7) CP_WAIT1(); else CP_WAIT0();
        __syncthreads();

        const unsigned bufW = sbase + HOFF_W0 + (c & 1) * 26112;
        float d[4][4];
        #pragma unroll
        for (int t = 0; t < 4; t++)
            #pragma unroll
            for (int i = 0; i < 4; i++) d[t][i] = 0.f;

        #pragma unroll
        for (int s = 0; s < 25; s++) {
            unsigned a[4], b0[4], b1[4];
            ldsm_x4(sbase + HOFF_A0 + aoffH + s * 32, a[0], a[1], a[2], a[3]);
            ldsm_x4(bufW + boffW + s * 32, b0[0], b0[1], b0[2], b0[3]);
            ldsm_x4(bufW + 16 * 816 + boffW + s * 32, b1[0], b1[1], b1[2], b1[3]);
            mma16816(d[0], a[0], a[1], a[2], a[3], b0[0], b0[1]);
            mma16816(d[1], a[0], a[1], a[2], a[3], b0[2], b0[3]);
            mma16816(d[2], a[0], a[1], a[2], a[3], b1[0], b1[1]);
            mma16816(d[3], a[0], a[1], a[2], a[3], b1[2], b1[3]);
        }

        // epilogue: bias + relu + pack -> p1 A fragments (slices 2c, 2c+1)
        #pragma unroll
        for (int pr = 0; pr < 2; pr++) {
            const int s = 2 * c + pr;
            int j0 = 32 * c + 16 * pr + 2 * (lane & 3);
            int j1 = j0 + 8;
            float b00 = bp0_sh[j0], b01 = bp0_sh[j0 + 1];
            float b10 = bp0_sh[j1], b11 = bp0_sh[j1 + 1];
            aP1[s][0] = pack_h2(fmaxf(d[2*pr][0] + b00, 0.f), fmaxf(d[2*pr][1] + b01, 0.f));
            aP1[s][1] = pack_h2(fmaxf(d[2*pr][2] + b00, 0.f), fmaxf(d[2*pr][3] + b01, 0.f));
            aP1[s][2] = pack_h2(fmaxf(d[2*pr+1][0] + b10, 0.f), fmaxf(d[2*pr+1][1] + b11, 0.f));
            aP1[s][3] = pack_h2(fmaxf(d[2*pr+1][2] + b10, 0.f), fmaxf(d[2*pr+1][3] + b11, 0.f));
        }

        __syncthreads();
        if (c + 2 < 8) {                         // refill (c&1) with chunk c+2
            for (int q = tid; q < 1600; q += 256) {
                int row = q / 50, col = q % 50;
                CP16(sbase + HOFF_W0 + (unsigned)((c & 1) * 26112 + row * 816 + col * 16),
                     (const char*)Wp0g + (size_t)((c + 2) * 32 + row) * 816 + col * 16);
            }
            CP_COMMIT();
        }
    }

    // ---- preload Wp1 chunks 0,1 (32 n-rows each, pitch 528B) ----
    #pragma unroll
    for (int pc = 0; pc < 2; pc++) {
        for (int q = tid; q < 1024; q += 256) {
            int row = q >> 5, col = q & 31;
            CP16(sbase + HOFF_W0 + (unsigned)(pc * 26112 + row * 528 + col * 16),
                 (const char*)Wp1g + (size_t)(pc * 32 + row) * 528 + col * 16);
        }
        CP_COMMIT();
    }

    // ================= p1: q = relu(p @ Wp1 + bp1) -> regs =================
    for (int c = 0; c < 8; c++) {
        if (c < 7) CP_WAIT1(); else CP_WAIT0();
        __syncthreads();

        const unsigned bufW = sbase + HOFF_W0 + (c & 1) * 26112;
        float d[4][4];
        #pragma unroll
        for (int t = 0; t < 4; t++)
            #pragma unroll
            for (int i = 0; i < 4; i++) d[t][i] = 0.f;

        #pragma unroll
        for (int s = 0; s < 16; s++) {
            unsigned b0[4], b1[4];
            ldsm_x4(bufW + boffP + s * 32, b0[0], b0[1], b0[2], b0[3]);
            ldsm_x4(bufW + 16 * 528 + boffP + s * 32, b1[0], b1[1], b1[2], b1[3]);
            mma16816(d[0], aP1[s][0], aP1[s][1], aP1[s][2], aP1[s][3], b0[0], b0[1]);
            mma16816(d[1], aP1[s][0], aP1[s][1], aP1[s][2], aP1[s][3], b0[2], b0[3]);
            mma16816(d[2], aP1[s][0], aP1[s][1], aP1[s][2], aP1[s][3], b1[0], b1[1]);
            mma16816(d[3], aP1[s][0], aP1[s][1], aP1[s][2], aP1[s][3], b1[2], b1[3]);
        }

        #pragma unroll
        for (int pr = 0; pr < 2; pr++) {
            const int s = 2 * c + pr;
            int j0 = 32 * c + 16 * pr + 2 * (lane & 3);
            int j1 = j0 + 8;
            float b00 = bp1_sh[j0], b01 = bp1_sh[j0 + 1];
            float b10 = bp1_sh[j1], b11 = bp1_sh[j1 + 1];
            aP2[s][0] = pack_h2(fmaxf(d[2*pr][0] + b00, 0.f), fmaxf(d[2*pr][1] + b01, 0.f));
            aP2[s][1] = pack_h2(fmaxf(d[2*pr][2] + b00, 0.f), fmaxf(d[2*pr][3] + b01, 0.f));
            aP2[s][2] = pack_h2(fmaxf(d[2*pr+1][0] + b10, 0.f), fmaxf(d[2*pr+1][1] + b11, 0.f));
            aP2[s][3] = pack_h2(fmaxf(d[2*pr+1][2] + b10, 0.f), fmaxf(d[2*pr+1][3] + b11, 0.f));
        }

        __syncthreads();
        if (c + 2 < 8) {
            for (int q = tid; q < 1024; q += 256) {
                int row = q >> 5, col = q & 31;
                CP16(sbase + HOFF_W0 + (unsigned)((c & 1) * 26112 + row * 528 + col * 16),
                     (const char*)Wp1g + (size_t)((c + 2) * 32 + row) * 528 + col * 16);
            }
            CP_COMMIT();
        }
    }

    // ================= p2: out = tanh(q @ Wp2 + bp2) =================
    {
        const unsigned w2 = sbase + HOFF_W2;
        float d[4] = {0.f, 0.f, 0.f, 0.f};
        #pragma unroll
        for (int s = 0; s < 16; s++) {
            unsigned b0, b1;
            ldsm_x2(w2 + boffS + s * 32, b0, b1);
            mma16816(d, aP2[s][0], aP2[s][1], aP2[s][2], aP2[s][3], b0, b1);
        }
        int row = lane >> 2, col = 2 * (lane & 3);
        float bb0 = bp2_sh[col], bb1 = bp2_sh[col + 1];
        int elo = e0 + warp * 16 + row;
        *(float2*)&out[(size_t)elo * 8 + col] =
            make_float2(tanhf(d[0] + bb0), tanhf(d[1] + bb1));
        *(float2*)&out[(size_t)(elo + 8) * 8 + col] =
            make_float2(tanhf(d[2] + bb0), tanhf(d[3] + bb1));
    }
}

// ===========================================================================
extern "C" void kernel_launch(void* const* d_in, const int* in_sizes, int n_in,
                              void* d_out, int out_size)
{
    const float* o   = (const float*)d_in[0];
    const float* g   = (const float*)d_in[1];
    const float* Wc  = (const float*)d_in[2];
    const float* bc  = (const float*)d_in[3];
    const float* Wa0 = (const float*)d_in[4];
    const float* ba0 = (const float*)d_in[5];
    const float* Wa1 = (const float*)d_in[6];
    const float* ba1 = (const float*)d_in[7];
    const float* Wp0 = (const float*)d_in[8];
    const float* bp0 = (const float*)d_in[9];
    const float* Wp1 = (const float*)d_in[10];
    const float* bp1 = (const float*)d_in[11];
    const float* Wp2 = (const float*)d_in[12];
    const float* bp2 = (const float*)d_in[13];
    float* out = (float*)d_out;

    int B = in_sizes[0] / 260;

    cudaFuncSetAttribute(k_main, cudaFuncAttributeMaxDynamicSharedMemorySize, SMEM_MAIN);
    cudaFuncSetAttribute(k_head, cudaFuncAttributeMaxDynamicSharedMemorySize, SMEM_HEAD);

    k_prep<<<1128, 256>>>(Wa0, Wa1, Wp0, Wp1, Wp2);
    k_main<<<B / 16, 256, SMEM_MAIN>>>(o, g, Wc, bc, ba0, ba1);
    k_head<<<B / 128, 256, SMEM_HEAD>>>(bp0, bp1, bp2, out);
}

// round 15
// speedup vs baseline: 6.6240x; 1.1249x over previous
#include <cuda_runtime.h>
#include <cuda_fp16.h>
#include <math.h>
#include <stdint.h>

// ===========================================================================
// Helpers
// ===========================================================================
__device__ __forceinline__ unsigned smem_u32(const void* p) {
    unsigned a;
    asm("{ .reg .u64 t; cvta.to.shared.u64 t, %1; cvt.u32.u64 %0, t; }"
        : "=r"(a) : "l"(p));
    return a;
}
#define CP16(dst_u32, src_ptr) \
    asm volatile("cp.async.cg.shared.global [%0], [%1], 16;" \
                 :: "r"(dst_u32), "l"(src_ptr))
#define CP_COMMIT() asm volatile("cp.async.commit_group;")
#define CP_WAIT2()  asm volatile("cp.async.wait_group 2;")
#define CP_WAIT1()  asm volatile("cp.async.wait_group 1;")
#define CP_WAIT0()  asm volatile("cp.async.wait_group 0;")

__device__ __forceinline__ void ldsm_x4(unsigned addr, unsigned& r0, unsigned& r1,
                                        unsigned& r2, unsigned& r3) {
    asm volatile("ldmatrix.sync.aligned.m8n8.x4.shared.b16 {%0,%1,%2,%3}, [%4];"
                 : "=r"(r0), "=r"(r1), "=r"(r2), "=r"(r3) : "r"(addr));
}
__device__ __forceinline__ void ldsm_x2(unsigned addr, unsigned& r0, unsigned& r1) {
    asm volatile("ldmatrix.sync.aligned.m8n8.x2.shared.b16 {%0,%1}, [%2];"
                 : "=r"(r0), "=r"(r1) : "r"(addr));
}
// fp16 MMA, fp32 accumulate
__device__ __forceinline__ void mma16816(float* d, unsigned a0, unsigned a1,
                                         unsigned a2, unsigned a3,
                                         unsigned b0, unsigned b1) {
    asm volatile("mma.sync.aligned.m16n8k16.row.col.f32.f16.f16.f32 "
                 "{%0,%1,%2,%3}, {%4,%5,%6,%7}, {%8,%9}, {%0,%1,%2,%3};"
                 : "+f"(d[0]), "+f"(d[1]), "+f"(d[2]), "+f"(d[3])
                 : "r"(a0), "r"(a1), "r"(a2), "r"(a3), "r"(b0), "r"(b1));
}
__device__ __forceinline__ float redsum8(float v) {
    v += __shfl_xor_sync(0xffffffffu, v, 4);
    v += __shfl_xor_sync(0xffffffffu, v, 8);
    v += __shfl_xor_sync(0xffffffffu, v, 16);
    return v;
}
__device__ __forceinline__ unsigned pack_h2(float v0, float v1) {
    __half2 h = __floats2half2_rn(v0, v1);
    return *(unsigned*)&h;
}

// ===========================================================================
// Globals
// ===========================================================================
__device__ __align__(16) __half g_iph[65536 * 400];     // input_pi (fp16)
__device__ __align__(16) __half W0g[256 * 72];          // Wa0^T fp16, pitch 72
__device__ __align__(16) __half W1g[400 * 264];         // Wa1^T fp16, pitch 264
__device__ __align__(16) __half Wp0g[256 * 408];        // Wp0^T fp16, pitch 408
__device__ __align__(16) __half Wp1g[256 * 264];        // Wp1^T fp16, pitch 264
__device__ __align__(16) __half Wp2g[8 * 264];          // Wp2^T fp16, pitch 264

// ===========================================================================
// Prep: fp16 weight images (n-major, k contiguous)
// ===========================================================================
__global__ void k_prep(const float* __restrict__ Wa0, const float* __restrict__ Wa1,
                       const float* __restrict__ Wp0, const float* __restrict__ Wp1,
                       const float* __restrict__ Wp2) {
    int idx = blockIdx.x * 256 + threadIdx.x;
    if (idx < 16384) {                                   // W0: 256n x 64k
        int n = idx >> 6, k = idx & 63;
        float v = (k < 50) ? Wa0[k * 256 + n] : 0.f;
        W0g[n * 72 + k] = __float2half(v);
    } else if (idx < 118784) {                           // W1: 400n x 256k
        int t = idx - 16384;
        int k = t / 400, n = t % 400;
        W1g[n * 264 + k] = __float2half(Wa1[k * 400 + n]);
    } else if (idx < 118784 + 102400) {                  // Wp0: 256n x 400k
        int t = idx - 118784;
        int n = t & 255, k = t >> 8;
        Wp0g[n * 408 + k] = __float2half(Wp0[k * 256 + n]);
    } else if (idx < 221184 + 65536) {                   // Wp1: 256n x 256k
        int t = idx - 221184;
        int n = t & 255, k = t >> 8;
        Wp1g[n * 264 + k] = __float2half(Wp1[k * 256 + n]);
    } else if (idx < 286720 + 2048) {                    // Wp2: 8n x 256k
        int t = idx - 286720;
        int n = t & 7, k = t >> 3;
        Wp2g[n * 264 + k] = __float2half(Wp2[k * 8 + n]);
    }
}

// ===========================================================================
// Kernel 1: attention + gather + a0 + a1 + object-sum -> g_iph (B x 400 fp16)
// Block = 16 elements (M=128), 256 threads / 8 warps, 2 blocks/SM.
// ALL weights stream through one 3-slot ring -> 1 barrier per chunk.
// ===========================================================================
#define RS      21120          // ring slot bytes
#define OFF_R   0              // 3 slots: 0, 21120, 42240 (end 63360)
#define OFF_A0  63360          // A0: 128 x 144B = 18432
#define OFF_BA1 81792          // 400 f
#define OFF_BA0 83392          // 256 f
#define SMEM_MAIN 84416

__global__ __launch_bounds__(256, 2)
void k_main(const float* __restrict__ o,   const float* __restrict__ g,
            const float* __restrict__ Wc,  const float* __restrict__ bc,
            const float* __restrict__ ba0, const float* __restrict__ ba1)
{
    extern __shared__ __align__(1024) unsigned char smem[];
    const unsigned sbase = smem_u32(smem);
    const int tid = threadIdx.x, lane = tid & 31, warp = tid >> 5;
    const int e0 = blockIdx.x * 16;

    // ---- G_A: B0 pair0 (n 0..127, 18432B) -> slot 2 (free during staging) ----
    for (int q = tid; q < 1152; q += 256)
        CP16(sbase + OFF_R + 2 * RS + q * 16, (const char*)W0g + q * 16);
    CP_COMMIT();

    // ---- biases ----
    float* ba0_sh = (float*)(smem + OFF_BA0);
    float* ba1_sh = (float*)(smem + OFF_BA1);
    ba0_sh[tid] = ba0[tid];
    for (int i = tid; i < 400; i += 256) ba1_sh[i] = ba1[i];

    // ---- phase 0: staging (slots 0-1 region) + attention + A0 fp16 ----
    {
        float* o_sh = (float*)(smem + 0);         // 16 x 260
        float* g_sh = (float*)(smem + 16640);     // 16 x 100
        float* att  = (float*)(smem + 23040);     // 16 x 52   (end 26368 < 42240)
        for (int i = tid; i < 16 * 260; i += 256) o_sh[i] = o[(size_t)e0 * 260 + i];
        for (int i = tid; i < 1600; i += 256) g_sh[i] = g[(size_t)e0 * 100 + i];
        __syncthreads();

        for (int idx = tid; idx < 800; idx += 256) {
            int e = idx / 50, j = idx % 50;
            float acc = bc[j];
            #pragma unroll 4
            for (int k = 0; k < 100; k++)
                acc = fmaf(g_sh[e * 100 + k], __ldg(Wc + k * 50 + j), acc);
            att[e * 52 + j] = 1.0f / (1.0f + expf(-acc));
        }
        __syncthreads();

        for (int idx = tid; idx < 4096; idx += 256) {
            int row = idx >> 5, kp = idx & 31;
            int e = row >> 3, n = row & 7;
            float v[2];
            #pragma unroll
            for (int t = 0; t < 2; t++) {
                int d = kp * 2 + t;
                float x = 0.f;
                if (d < 50) {
                    int gi;
                    if (d < 10)       gi = d;
                    else if (d < 20)  gi = 120 + d;
                    else if (d < 35)  gi = 15 * n + d - 10;
                    else              gi = 15 * n + d + 105;
                    x = o_sh[e * 260 + gi] * att[e * 52 + d];
                }
                v[t] = x;
            }
            *(unsigned*)(smem + OFF_A0 + (unsigned)(row * 72 + kp * 2) * 2) =
                pack_h2(v[0], v[1]);
        }
    }
    __syncthreads();   // staging reads + A0 writes done -> slots 0,1 free

    // ---- G_B: B0 pair1 -> slot 0;  G_C: B1 chunk0 -> slot 1 ----
    for (int q = tid; q < 1152; q += 256)
        CP16(sbase + OFF_R + q * 16, (const char*)W0g + 18432 + q * 16);
    CP_COMMIT();
    for (int q = tid; q < 1320; q += 256)
        CP16(sbase + OFF_R + RS + q * 16, (const char*)W1g + q * 16);
    CP_COMMIT();

    // per-lane ldmatrix address components
    const unsigned aoffA = (unsigned)(((warp * 16 + (lane & 15)) * 72 + ((lane & 16) >> 1)) * 2);
    const int bg = lane >> 3;
    const unsigned brow0 = (unsigned)((bg >> 1) * 8 + (lane & 7));
    const unsigned bk0   = (unsigned)((bg & 1) * 16);
    const unsigned boff1 = (unsigned)(brow0 * 528 + bk0);
    const unsigned boffS = (unsigned)((32 + (lane & 7)) * 528 + ((lane >> 3) & 1) * 16);

    // hoist A0 fragments (A0 ready since the staging barrier)
    unsigned aA0[4][4];
    #pragma unroll
    for (int s = 0; s < 4; s++)
        ldsm_x4(sbase + OFF_A0 + aoffA + s * 32,
                aA0[s][0], aA0[s][1], aA0[s][2], aA0[s][3]);

    unsigned aH1[16][4];   // GEMM2 A fragments (register fusion)

    // ================= GEMM1: h = relu(x @ Wa0 + ba0) -> regs =================
    #pragma unroll
    for (int p = 0; p < 2; p++) {
        if (p == 0) CP_WAIT2(); else CP_WAIT1();
        __syncthreads();
        if (p == 1) {   // G_D: B1 chunk1 -> slot 2 (pair0 reads done by barrier)
            for (int q = tid; q < 1320; q += 256)
                CP16(sbase + OFF_R + 2 * RS + q * 16, (const char*)W1g + 21120 + q * 16);
            CP_COMMIT();
        }
        const unsigned base = sbase + OFF_R + (p == 0 ? 2 * RS : 0);
        #pragma unroll
        for (int cc = 0; cc < 2; cc++) {
            const int c = p * 2 + cc;   // n-chunk 0..3
            float d[8][4];
            #pragma unroll
            for (int t = 0; t < 8; t++)
                #pragma unroll
                for (int i = 0; i < 4; i++) d[t][i] = 0.f;

            #pragma unroll
            for (int s = 0; s < 4; s++) {
                unsigned bh[4][4];
                #pragma unroll
                for (int pr = 0; pr < 4; pr++) {
                    unsigned bo = (unsigned)((cc * 64 + pr * 16 + brow0) * 144) + bk0 + s * 32;
                    ldsm_x4(base + bo, bh[pr][0], bh[pr][1], bh[pr][2], bh[pr][3]);
                }
                #pragma unroll
                for (int pr = 0; pr < 4; pr++) {
                    mma16816(d[2 * pr],     aA0[s][0], aA0[s][1], aA0[s][2], aA0[s][3],
                             bh[pr][0], bh[pr][1]);
                    mma16816(d[2 * pr + 1], aA0[s][0], aA0[s][1], aA0[s][2], aA0[s][3],
                             bh[pr][2], bh[pr][3]);
                }
            }

            // epilogue: bias + relu + fp16 pack -> GEMM2 A fragments
            #pragma unroll
            for (int u = 0; u < 4; u++) {
                const int s = 4 * c + u;
                int j0 = 64 * c + 16 * u + 2 * (lane & 3);
                int j1 = j0 + 8;
                float b00 = ba0_sh[j0], b01 = ba0_sh[j0 + 1];
                float b10 = ba0_sh[j1], b11 = ba0_sh[j1 + 1];
                aH1[s][0] = pack_h2(fmaxf(d[2*u][0] + b00, 0.f), fmaxf(d[2*u][1] + b01, 0.f));
                aH1[s][1] = pack_h2(fmaxf(d[2*u][2] + b00, 0.f), fmaxf(d[2*u][3] + b01, 0.f));
                aH1[s][2] = pack_h2(fmaxf(d[2*u+1][0] + b10, 0.f), fmaxf(d[2*u+1][1] + b11, 0.f));
                aH1[s][3] = pack_h2(fmaxf(d[2*u+1][2] + b10, 0.f), fmaxf(d[2*u+1][3] + b11, 0.f));
            }
        }
    }

    // ============ GEMM2: input_pi = sum_obj relu(h @ Wa1 + ba1) ============
    // chunk c lives in slot (c+1)%3; one barrier per chunk.
    for (int c = 0; c < 10; c++) {
        if (c < 9) CP_WAIT1(); else CP_WAIT0();
        __syncthreads();   // chunk c visible; chunk c-1 reads done everywhere
        if (c + 2 < 10) {  // refill slot c%3 (read at iter c-1)
            for (int q = tid; q < 1320; q += 256)
                CP16(sbase + OFF_R + (unsigned)(c % 3) * RS + q * 16,
                     (const char*)W1g + (size_t)(c + 2) * 21120 + q * 16);
            CP_COMMIT();
        }

        const unsigned bufH = sbase + OFF_R + (unsigned)((c + 1) % 3) * RS;
        float d[5][4];
        #pragma unroll
        for (int t = 0; t < 5; t++)
            #pragma unroll
            for (int i = 0; i < 4; i++) d[t][i] = 0.f;

        #pragma unroll
        for (int s = 0; s < 16; s++) {
            unsigned bh0[4], bh1[4], bhS[2];
            ldsm_x4(bufH + boff1 + s * 32, bh0[0], bh0[1], bh0[2], bh0[3]);
            ldsm_x4(bufH + 16 * 528 + boff1 + s * 32, bh1[0], bh1[1], bh1[2], bh1[3]);
            ldsm_x2(bufH + boffS + s * 32, bhS[0], bhS[1]);
            mma16816(d[0], aH1[s][0], aH1[s][1], aH1[s][2], aH1[s][3], bh0[0], bh0[1]);
            mma16816(d[1], aH1[s][0], aH1[s][1], aH1[s][2], aH1[s][3], bh0[2], bh0[3]);
            mma16816(d[2], aH1[s][0], aH1[s][1], aH1[s][2], aH1[s][3], bh1[0], bh1[1]);
            mma16816(d[3], aH1[s][0], aH1[s][1], aH1[s][2], aH1[s][3], bh1[2], bh1[3]);
            mma16816(d[4], aH1[s][0], aH1[s][1], aH1[s][2], aH1[s][3], bhS[0], bhS[1]);
        }

        // epilogue: bias + relu + object-sum -> g_iph (fp16)
        #pragma unroll
        for (int t = 0; t < 5; t++) {
            int c0 = c * 40 + t * 8 + (lane & 3) * 2;
            float b0 = ba1_sh[c0], b1 = ba1_sh[c0 + 1];
            float s00 = redsum8(fmaxf(d[t][0] + b0, 0.f));
            float s01 = redsum8(fmaxf(d[t][1] + b1, 0.f));
            float s10 = redsum8(fmaxf(d[t][2] + b0, 0.f));
            float s11 = redsum8(fmaxf(d[t][3] + b1, 0.f));
            if (lane < 4)
                *(unsigned*)&g_iph[(size_t)(e0 + 2 * warp) * 400 + c0] = pack_h2(s00, s01);
            else if (lane < 8)
                *(unsigned*)&g_iph[(size_t)(e0 + 2 * warp + 1) * 400 + c0] = pack_h2(s10, s11);
        }
    }
}

// ===========================================================================
// Kernel 2: policy head (fp16 HMMA, register-fused p0->p1->p2)
// Block = 128 elements (M=128), 256 threads / 8 warps. A fragments hoisted
// to registers once; weights via 3-slot ring, 1 barrier per chunk.
// ===========================================================================
#define HRS      26112          // ring slot bytes (p0 chunk 26112, p1 16896)
#define HOFF_A0  0              // ip tile: 128 x 816B
#define HOFF_W   104448         // 3 slots -> 182784
#define HOFF_W2  182784         // 8 x 528B
#define HOFF_BP0 187008
#define HOFF_BP1 188032
#define HOFF_BP2 189056
#define SMEM_HEAD 189088

__global__ __launch_bounds__(256, 1)
void k_head(const float* __restrict__ bp0, const float* __restrict__ bp1,
            const float* __restrict__ bp2, float* __restrict__ out)
{
    extern __shared__ __align__(1024) unsigned char smem[];
    const unsigned sbase = smem_u32(smem);
    const int tid = threadIdx.x, lane = tid & 31, warp = tid >> 5;
    const int e0 = blockIdx.x * 128;

    // ---- G1: A0 (ip fp16, pitch 408) + Wp2 image ----
    for (int q = tid; q < 6400; q += 256) {
        int row = q / 50, col = q % 50;
        CP16(sbase + HOFF_A0 + (unsigned)(row * 816 + col * 16),
             (const char*)(g_iph + (size_t)(e0 + row) * 400) + col * 16);
    }
    for (int q = tid; q < 264; q += 256)
        CP16(sbase + HOFF_W2 + q * 16, (const char*)Wp2g + q * 16);
    CP_COMMIT();

    // ---- biases ----
    float* bp0_sh = (float*)(smem + HOFF_BP0);
    float* bp1_sh = (float*)(smem + HOFF_BP1);
    float* bp2_sh = (float*)(smem + HOFF_BP2);
    bp0_sh[tid] = bp0[tid];
    bp1_sh[tid] = bp1[tid];
    if (tid < 8) bp2_sh[tid] = bp2[tid];

    // ---- G2/G3: Wp0 chunks 0,1 -> slots 0,1 ----
    #pragma unroll
    for (int pc = 0; pc < 2; pc++) {
        for (int q = tid; q < 1600; q += 256) {
            int row = q / 50, col = q % 50;
            CP16(sbase + HOFF_W + (unsigned)(pc * HRS + row * 816 + col * 16),
                 (const char*)Wp0g + (size_t)(pc * 32 + row) * 816 + col * 16);
        }
        CP_COMMIT();
    }

    // per-lane ldmatrix address components
    const unsigned aoffH = (unsigned)((warp * 16 + (lane & 15)) * 816 + ((lane & 16) >> 1) * 2);
    const int bg = lane >> 3;
    const unsigned brow0 = (unsigned)((bg >> 1) * 8 + (lane & 7));
    const unsigned bk0   = (unsigned)((bg & 1) * 16);
    const unsigned boffW = brow0 * 816 + bk0;      // Wp0 (pitch 816B)
    const unsigned boffP = brow0 * 528 + bk0;      // Wp1 (pitch 528B)
    const unsigned boffS = (unsigned)((lane & 7) * 528 + ((lane >> 3) & 1) * 16);  // Wp2

    // ---- wait for A0, hoist A fragments to registers (one-time) ----
    CP_WAIT2();        // G1 done (G2, G3 may be pending)
    __syncthreads();
    unsigned aA[25][4];
    #pragma unroll
    for (int s = 0; s < 25; s++)
        ldsm_x4(sbase + HOFF_A0 + aoffH + s * 32, aA[s][0], aA[s][1], aA[s][2], aA[s][3]);

    unsigned aP1[16][4];    // p fragments
    unsigned aP2[16][4];    // q fragments

    // ================= p0: p = relu(ip @ Wp0 + bp0) -> regs =================
    // p0 chunk c in slot c%3; p1 chunks 0,1 prefetched at c==6,7 into slots 2,0.
    for (int c = 0; c < 8; c++) {
        CP_WAIT1();
        __syncthreads();
        if (c + 2 < 8) {          // refill slot (c+2)%3 (read at iter c-1)
            for (int q = tid; q < 1600; q += 256) {
                int row = q / 50, col = q % 50;
                CP16(sbase + HOFF_W + (unsigned)(((c + 2) % 3) * HRS + row * 816 + col * 16),
                     (const char*)Wp0g + (size_t)((c + 2) * 32 + row) * 816 + col * 16);
            }
            CP_COMMIT();
        } else {                  // c==6 -> p1 chunk0 slot2; c==7 -> p1 chunk1 slot0
            const int pc = c - 6;
            const int slot = (8 + pc) % 3;
            for (int q = tid; q < 1024; q += 256) {
                int row = q >> 5, col = q & 31;
                CP16(sbase + HOFF_W + (unsigned)(slot * HRS + row * 528 + col * 16),
                     (const char*)Wp1g + (size_t)(pc * 32 + row) * 528 + col * 16);
            }
            CP_COMMIT();
        }

        const unsigned bufW = sbase + HOFF_W + (unsigned)(c % 3) * HRS;
        float d[4][4];
        #pragma unroll
        for (int t = 0; t < 4; t++)
            #pragma unroll
            for (int i = 0; i < 4; i++) d[t][i] = 0.f;

        #pragma unroll
        for (int s = 0; s < 25; s++) {
            unsigned b0[4], b1[4];
            ldsm_x4(bufW + boffW + s * 32, b0[0], b0[1], b0[2], b0[3]);
            ldsm_x4(bufW + 16 * 816 + boffW + s * 32, b1[0], b1[1], b1[2], b1[3]);
            mma16816(d[0], aA[s][0], aA[s][1], aA[s][2], aA[s][3], b0[0], b0[1]);
            mma16816(d[1], aA[s][0], aA[s][1], aA[s][2], aA[s][3], b0[2], b0[3]);
            mma16816(d[2], aA[s][0], aA[s][1], aA[s][2], aA[s][3], b1[0], b1[1]);
            mma16816(d[3], aA[s][0], aA[s][1], aA[s][2], aA[s][3], b1[2], b1[3]);
        }

        #pragma unroll
        for (int pr = 0; pr < 2; pr++) {
            const int s = 2 * c + pr;
            int j0 = 32 * c + 16 * pr + 2 * (lane & 3);
            int j1 = j0 + 8;
            float b00 = bp0_sh[j0], b01 = bp0_sh[j0 + 1];
            float b10 = bp0_sh[j1], b11 = bp0_sh[j1 + 1];
            aP1[s][0] = pack_h2(fmaxf(d[2*pr][0] + b00, 0.f), fmaxf(d[2*pr][1] + b01, 0.f));
            aP1[s][1] = pack_h2(fmaxf(d[2*pr][2] + b00, 0.f), fmaxf(d[2*pr][3] + b01, 0.f));
            aP1[s][2] = pack_h2(fmaxf(d[2*pr+1][0] + b10, 0.f), fmaxf(d[2*pr+1][1] + b11, 0.f));
            aP1[s][3] = pack_h2(fmaxf(d[2*pr+1][2] + b10, 0.f), fmaxf(d[2*pr+1][3] + b11, 0.f));
        }
    }

    // ================= p1: q = relu(p @ Wp1 + bp1) -> regs =================
    // p1 chunk c in slot (c+2)%3; refill chunk c+2 into slot (c+1)%3.
    for (int c = 0; c < 8; c++) {
        if (c < 7) CP_WAIT1(); else CP_WAIT0();
        __syncthreads();
        if (c + 2 < 8) {
            for (int q = tid; q < 1024; q += 256) {
                int row = q >> 5, col = q & 31;
                CP16(sbase + HOFF_W + (unsigned)(((c + 1) % 3) * HRS + row * 528 + col * 16),
                     (const char*)Wp1g + (size_t)((c + 2) * 32 + row) * 528 + col * 16);
            }
            CP_COMMIT();
        }

        const unsigned bufW = sbase + HOFF_W + (unsigned)((c + 2) % 3) * HRS;
        float d[4][4];
        #pragma unroll
        for (int t = 0; t < 4; t++)
            #pragma unroll
            for (int i = 0; i < 4; i++) d[t][i] = 0.f;

        #pragma unroll
        for (int s = 0; s < 16; s++) {
            unsigned b0[4], b1[4];
            ldsm_x4(bufW + boffP + s * 32, b0[0], b0[1], b0[2], b0[3]);
            ldsm_x4(bufW + 16 * 528 + boffP + s * 32, b1[0], b1[1], b1[2], b1[3]);
            mma16816(d[0], aP1[s][0], aP1[s][1], aP1[s][2], aP1[s][3], b0[0], b0[1]);
            mma16816(d[1], aP1[s][0], aP1[s][1], aP1[s][2], aP1[s][3], b0[2], b0[3]);
            mma16816(d[2], aP1[s][0], aP1[s][1], aP1[s][2], aP1[s][3], b1[0], b1[1]);
            mma16816(d[3], aP1[s][0], aP1[s][1], aP1[s][2], aP1[s][3], b1[2], b1[3]);
        }

        #pragma unroll
        for (int pr = 0; pr < 2; pr++) {
            const int s = 2 * c + pr;
            int j0 = 32 * c + 16 * pr + 2 * (lane & 3);
            int j1 = j0 + 8;
            float b00 = bp1_sh[j0], b01 = bp1_sh[j0 + 1];
            float b10 = bp1_sh[j1], b11 = bp1_sh[j1 + 1];
            aP2[s][0] = pack_h2(fmaxf(d[2*pr][0] + b00, 0.f), fmaxf(d[2*pr][1] + b01, 0.f));
            aP2[s][1] = pack_h2(fmaxf(d[2*pr][2] + b00, 0.f), fmaxf(d[2*pr][3] + b01, 0.f));
            aP2[s][2] = pack_h2(fmaxf(d[2*pr+1][0] + b10, 0.f), fmaxf(d[2*pr+1][1] + b11, 0.f));
            aP2[s][3] = pack_h2(fmaxf(d[2*pr+1][2] + b10, 0.f), fmaxf(d[2*pr+1][3] + b11, 0.f));
        }
    }

    // ================= p2: out = tanh(q @ Wp2 + bp2) =================
    {
        const unsigned w2 = sbase + HOFF_W2;
        float d[4] = {0.f, 0.f, 0.f, 0.f};
        #pragma unroll
        for (int s = 0; s < 16; s++) {
            unsigned b0, b1;
            ldsm_x2(w2 + boffS + s * 32, b0, b1);
            mma16816(d, aP2[s][0], aP2[s][1], aP2[s][2], aP2[s][3], b0, b1);
        }
        int row = lane >> 2, col = 2 * (lane & 3);
        float bb0 = bp2_sh[col], bb1 = bp2_sh[col + 1];
        int elo = e0 + warp * 16 + row;
        *(float2*)&out[(size_t)elo * 8 + col] =
            make_float2(tanhf(d[0] + bb0), tanhf(d[1] + bb1));
        *(float2*)&out[(size_t)(elo + 8) * 8 + col] =
            make_float2(tanhf(d[2] + bb0), tanhf(d[3] + bb1));
    }
}

// ===========================================================================
extern "C" void kernel_launch(void* const* d_in, const int* in_sizes, int n_in,
                              void* d_out, int out_size)
{
    const float* o   = (const float*)d_in[0];
    const float* g   = (const float*)d_in[1];
    const float* Wc  = (const float*)d_in[2];
    const float* bc  = (const float*)d_in[3];
    const float* Wa0 = (const float*)d_in[4];
    const float* ba0 = (const float*)d_in[5];
    const float* Wa1 = (const float*)d_in[6];
    const float* ba1 = (const float*)d_in[7];
    const float* Wp0 = (const float*)d_in[8];
    const float* bp0 = (const float*)d_in[9];
    const float* Wp1 = (const float*)d_in[10];
    const float* bp1 = (const float*)d_in[11];
    const float* Wp2 = (const float*)d_in[12];
    const float* bp2 = (const float*)d_in[13];
    float* out = (float*)d_out;

    int B = in_sizes[0] / 260;

    cudaFuncSetAttribute(k_main, cudaFuncAttributeMaxDynamicSharedMemorySize, SMEM_MAIN);
    cudaFuncSetAttribute(k_head, cudaFuncAttributeMaxDynamicSharedMemorySize, SMEM_HEAD);

    k_prep<<<1128, 256>>>(Wa0, Wa1, Wp0, Wp1, Wp2);
    k_main<<<B / 16, 256, SMEM_MAIN>>>(o, g, Wc, bc, ba0, ba1);
    k_head<<<B / 128, 256, SMEM_HEAD>>>(bp0, bp1, bp2, out);
}